// round 4
// baseline (speedup 1.0000x reference)
#include <cuda_runtime.h>
#include <cuda_bf16.h>
#include <mma.h>
#include <cstdint>

using namespace nvcuda;

#define NB   128
#define NS   12
#define NL   128
#define NE   512
#define NE2  1024
#define NH   512
#define NH3  1536
#define NKIN 2304

// ---------------- scratch ----------------
__device__ int   g_idx[NB];
__device__ int   g_gc[NB];
__device__ float g_mask_sum;
__device__ float g_h[NB * NH];
__device__ float g_xproj[NB * NS * NH3];
__device__ float g_outh[NB * NS * NH];
__device__ float g_hpart[NB * NS * NE];
__device__ float g_epart[NB * NL * NE];
__device__ float g_plan_partial[2048];
__device__ unsigned g_bg_arrive[4];
__device__ unsigned g_bg_gen[4];
// bf16 copies
__device__ __nv_bfloat16 g_enc_bf[NB * NL * NE2];
__device__ __nv_bfloat16 g_inps_bf[NB * NS * NE2];
__device__ __nv_bfloat16 g_outh_bf[NB * NS * NH];
__device__ __nv_bfloat16 g_hb[NB * NH];
__device__ __nv_bfloat16 g_wp1_bf[NE * NH3];
__device__ __nv_bfloat16 g_wih_bf[NH3 * NE2];
__device__ __nv_bfloat16 g_ginit_bf[NB * NKIN];
__device__ __nv_bfloat16 g_winit_bf[NH * NKIN];

// ---------------- helpers ----------------
__device__ __forceinline__ float fast_tanh(float x) {
    float y; asm("tanh.approx.f32 %0, %1;" : "=f"(y) : "f"(x)); return y;
}
__device__ __forceinline__ float sigmoidf(float x) { return 1.f / (1.f + __expf(-x)); }
__device__ __forceinline__ float softplusf(float x) { return (x > 15.f) ? x : log1pf(__expf(x)); }

__device__ __forceinline__ void cp16(void* sdst, const void* gsrc) {
    uint32_t s = (uint32_t)__cvta_generic_to_shared(sdst);
    asm volatile("cp.async.cg.shared.global [%0], [%1], 16;\n" :: "r"(s), "l"(gsrc));
}
#define CP_COMMIT() asm volatile("cp.async.commit_group;\n")
#define CP_WAIT1()  asm volatile("cp.async.wait_group 1;\n")
#define CP_WAIT0()  asm volatile("cp.async.wait_group 0;\n")

// ---------------- fp32 -> bf16 convert ----------------
__global__ void k_cvt(const float4* __restrict__ src, __nv_bfloat162* __restrict__ dst, int n4) {
    int i = blockIdx.x * 256 + threadIdx.x;
    if (i < n4) {
        float4 v = src[i];
        dst[2 * i]     = __nv_bfloat162{__float2bfloat16(v.x), __float2bfloat16(v.y)};
        dst[2 * i + 1] = __nv_bfloat162{__float2bfloat16(v.z), __float2bfloat16(v.w)};
    }
}

// ---------------- stable descending sort of group_count ----------------
__global__ void k_sort(const int* __restrict__ gc) {
    __shared__ int s_gc[NB];
    __shared__ int red[NB];
    int t = threadIdx.x;
    s_gc[t] = gc[t];
    __syncthreads();
    int my = s_gc[t];
    int rank = 0;
    #pragma unroll 8
    for (int j = 0; j < NB; j++) {
        int v = s_gc[j];
        rank += (v > my) || (v == my && j < t);
    }
    g_idx[rank] = t;
    g_gc[rank]  = my;
    red[t] = my;
    __syncthreads();
    for (int off = 64; off > 0; off >>= 1) {
        if (t < off) red[t] += red[t + off];
        __syncthreads();
    }
    if (t == 0) g_mask_sum = (float)red[0];
}

// ---------------- alpha + inps einsum; emits bf16 inps and bf16 enc ----------------
__global__ void k_inps(const float* __restrict__ enc, const int* __restrict__ segments) {
    __shared__ float s_a[NS][NL];
    __shared__ float s_inv[NS];
    int b = blockIdx.x, t = threadIdx.x;  // 256
    int p = g_idx[b];
    for (int i = t; i < NS * NL; i += 256) {
        int s = i >> 7, l = i & 127;
        float v = 0.f;
        if (s > 0) v = (float)segments[(p * NS + (s - 1)) * NL + l];
        s_a[s][l] = v;
    }
    __syncthreads();
    if (t < NS) {
        float sum = 0.f;
        for (int l = 0; l < NL; l++) sum += s_a[t][l];
        s_inv[t] = 1.f / (sum + 1.f);
    }
    __syncthreads();
    for (int i = t; i < NS * NL; i += 256) {
        int s = i >> 7;
        s_a[s][i & 127] *= s_inv[s];
    }
    __syncthreads();
    const float* encb = enc + (size_t)b * NL * NE2;
    #pragma unroll
    for (int eo = 0; eo < NE2 / 256; eo++) {
        int e = eo * 256 + t;
        float acc[NS];
        #pragma unroll
        for (int s = 0; s < NS; s++) acc[s] = 0.f;
        for (int l = 0; l < NL; l++) {
            float v = encb[l * NE2 + e];
            g_enc_bf[((size_t)b * NL + l) * NE2 + e] = __float2bfloat16(v);
            #pragma unroll
            for (int s = 0; s < NS; s++) acc[s] += s_a[s][l] * v;
        }
        #pragma unroll
        for (int s = 0; s < NS; s++)
            g_inps_bf[((size_t)b * NS + s) * NE2 + e] = __float2bfloat16(acc[s]);
    }
}

// ---------------- bf16 GEMM, 128x128 tile, cp.async double buffer ----------------
__global__ __launch_bounds__(256) void gemm_bf16(
    const __nv_bfloat16* __restrict__ A, int lda,
    const __nv_bfloat16* __restrict__ W, int ldw,
    float* __restrict__ C, int ldc, int K) {
    __shared__ __align__(16) __nv_bfloat16 As[2][128][40];
    __shared__ __align__(16) __nv_bfloat16 Ws[2][128][40];

    const int tid  = threadIdx.x;
    const int warp = tid >> 5;
    const int wm   = warp & 1;
    const int wn   = warp >> 1;
    const int m0   = blockIdx.y * 128;
    const int n0   = blockIdx.x * 128;
    const int nkt  = K >> 5;

    wmma::fragment<wmma::accumulator, 16, 16, 16, float> acc[4][2];
    #pragma unroll
    for (int i = 0; i < 4; i++)
        #pragma unroll
        for (int j = 0; j < 2; j++) wmma::fill_fragment(acc[i][j], 0.f);

    auto issue = [&](int kt, int st) {
        int k0 = kt << 5;
        #pragma unroll
        for (int q = 0; q < 2; q++) {
            int chunk = tid * 2 + q;          // 0..511
            int r  = chunk >> 2;              // 0..127
            int c8 = (chunk & 3) * 8;
            cp16(&As[st][r][c8], A + (size_t)(m0 + r) * lda + k0 + c8);
            cp16(&Ws[st][r][c8], W + (size_t)(n0 + r) * ldw + k0 + c8);
        }
        CP_COMMIT();
    };

    issue(0, 0);
    for (int kt = 0; kt < nkt; kt++) {
        int st = kt & 1;
        if (kt + 1 < nkt) { issue(kt + 1, st ^ 1); CP_WAIT1(); }
        else             { CP_WAIT0(); }
        __syncthreads();
        #pragma unroll
        for (int kk = 0; kk < 32; kk += 16) {
            wmma::fragment<wmma::matrix_a, 16, 16, 16, __nv_bfloat16, wmma::row_major> af[4];
            wmma::fragment<wmma::matrix_b, 16, 16, 16, __nv_bfloat16, wmma::col_major> bf[2];
            #pragma unroll
            for (int i = 0; i < 4; i++)
                wmma::load_matrix_sync(af[i], &As[st][wm * 64 + i * 16][kk], 40);
            #pragma unroll
            for (int j = 0; j < 2; j++)
                wmma::load_matrix_sync(bf[j], &Ws[st][wn * 32 + j * 16][kk], 40);
            #pragma unroll
            for (int i = 0; i < 4; i++)
                #pragma unroll
                for (int j = 0; j < 2; j++)
                    wmma::mma_sync(acc[i][j], af[i], bf[j], acc[i][j]);
        }
        __syncthreads();
    }
    #pragma unroll
    for (int i = 0; i < 4; i++)
        #pragma unroll
        for (int j = 0; j < 2; j++)
            wmma::store_matrix_sync(
                C + (size_t)(m0 + wm * 64 + i * 16) * ldc + n0 + wn * 32 + j * 16,
                acc[i][j], ldc, wmma::mem_row_major);
}

// ---------------- bf16 GEMM, 64x64 tile (h0) ----------------
__global__ __launch_bounds__(128) void gemm64_bf16(
    const __nv_bfloat16* __restrict__ A, int lda,
    const __nv_bfloat16* __restrict__ W, int ldw,
    float* __restrict__ C, int ldc, int K) {
    __shared__ __align__(16) __nv_bfloat16 As[2][64][40];
    __shared__ __align__(16) __nv_bfloat16 Ws[2][64][40];

    const int tid  = threadIdx.x;
    const int warp = tid >> 5;
    const int wm   = warp & 1;
    const int wn   = warp >> 1;
    const int m0   = blockIdx.y * 64;
    const int n0   = blockIdx.x * 64;
    const int nkt  = K >> 5;

    wmma::fragment<wmma::accumulator, 16, 16, 16, float> acc[2][2];
    #pragma unroll
    for (int i = 0; i < 2; i++)
        #pragma unroll
        for (int j = 0; j < 2; j++) wmma::fill_fragment(acc[i][j], 0.f);

    auto issue = [&](int kt, int st) {
        int k0 = kt << 5;
        #pragma unroll
        for (int q = 0; q < 2; q++) {
            int chunk = tid * 2 + q;
            int r  = chunk >> 2;
            int c8 = (chunk & 3) * 8;
            cp16(&As[st][r][c8], A + (size_t)(m0 + r) * lda + k0 + c8);
            cp16(&Ws[st][r][c8], W + (size_t)(n0 + r) * ldw + k0 + c8);
        }
        CP_COMMIT();
    };

    issue(0, 0);
    for (int kt = 0; kt < nkt; kt++) {
        int st = kt & 1;
        if (kt + 1 < nkt) { issue(kt + 1, st ^ 1); CP_WAIT1(); }
        else             { CP_WAIT0(); }
        __syncthreads();
        #pragma unroll
        for (int kk = 0; kk < 32; kk += 16) {
            wmma::fragment<wmma::matrix_a, 16, 16, 16, __nv_bfloat16, wmma::row_major> af[2];
            wmma::fragment<wmma::matrix_b, 16, 16, 16, __nv_bfloat16, wmma::col_major> bf[2];
            #pragma unroll
            for (int i = 0; i < 2; i++)
                wmma::load_matrix_sync(af[i], &As[st][wm * 32 + i * 16][kk], 40);
            #pragma unroll
            for (int j = 0; j < 2; j++)
                wmma::load_matrix_sync(bf[j], &Ws[st][wn * 32 + j * 16][kk], 40);
            #pragma unroll
            for (int i = 0; i < 2; i++)
                #pragma unroll
                for (int j = 0; j < 2; j++)
                    wmma::mma_sync(acc[i][j], af[i], bf[j], acc[i][j]);
        }
        __syncthreads();
    }
    #pragma unroll
    for (int i = 0; i < 2; i++)
        #pragma unroll
        for (int j = 0; j < 2; j++)
            wmma::store_matrix_sync(
                C + (size_t)(m0 + wm * 32 + i * 16) * ldc + n0 + wn * 32 + j * 16,
                acc[i][j], ldc, wmma::mem_row_major);
}

// ---------------- per-batch-group barrier (16 CTAs each) ----------------
__device__ __forceinline__ void bgsync(int bg) {
    __syncthreads();
    if (threadIdx.x == 0) {
        unsigned gen;
        asm volatile("ld.acquire.gpu.u32 %0, [%1];" : "=r"(gen) : "l"(&g_bg_gen[bg]) : "memory");
        __threadfence();
        unsigned old = atomicAdd(&g_bg_arrive[bg], 1u);
        if (old == 15) {
            g_bg_arrive[bg] = 0;
            __threadfence();
            atomicAdd(&g_bg_gen[bg], 1u);
        } else {
            unsigned cur;
            do {
                __nanosleep(32);
                asm volatile("ld.acquire.gpu.u32 %0, [%1];" : "=r"(cur) : "l"(&g_bg_gen[bg]) : "memory");
            } while (cur == gen);
        }
    }
    __syncthreads();
}

// ---------------- persistent GRU scan ----------------
// 64 CTAs: (colslice 0..15) x (batchgroup 0..3). Per-bg barrier; loop only to bg's smax.
__global__ __launch_bounds__(256) void k_gru_persist(
    const float* __restrict__ Whh, const float* __restrict__ bih,
    const float* __restrict__ bhh, const float* __restrict__ binit) {
    extern __shared__ __align__(16) char dyn[];
    __nv_bfloat16* sW  = (__nv_bfloat16*)dyn;          // [96][520]
    __nv_bfloat16* sH  = sW + 96 * 520;                // [32][520]
    float*         sGH = (float*)(sH + 32 * 520);      // [32][100]
    float*         sB  = sGH + 32 * 100;               // [192]

    const int tid  = threadIdx.x;
    const int warp = tid >> 5;
    const int cs   = blockIdx.x & 15;
    const int bg   = blockIdx.x >> 4;
    const int C0   = cs * 32;
    const int B0   = bg * 32;

    for (int i = tid; i < 96 * 128; i += 256) {
        int r = i >> 7, c4 = (i & 127) * 4;
        int p = r >> 5, j = r & 31;
        float4 v = *(const float4*)(Whh + (size_t)(p * NH + C0 + j) * NH + c4);
        __nv_bfloat16* d = sW + r * 520 + c4;
        d[0] = __float2bfloat16(v.x); d[1] = __float2bfloat16(v.y);
        d[2] = __float2bfloat16(v.z); d[3] = __float2bfloat16(v.w);
    }
    if (tid < 96) {
        int p = tid >> 5, j = tid & 31;
        sB[tid]      = bih[p * NH + C0 + j];
        sB[96 + tid] = bhh[p * NH + C0 + j];
    }
    for (int i = tid; i < 32 * 32; i += 256) {
        int bi = i >> 5, ci = i & 31;
        int b = B0 + bi, c = C0 + ci;
        float v = g_h[b * NH + c] + binit[c];
        g_h[b * NH + c]  = v;
        g_hb[b * NH + c] = __float2bfloat16(v);
    }
    const int smax = g_gc[B0];  // sorted desc -> max for this batch group
    bgsync(bg);

    for (int s = 0; s < smax; s++) {
        for (int i = tid; i < 32 * 64; i += 256) {
            int r = i >> 6, c8 = (i & 63) * 8;
            *(uint4*)(sH + r * 520 + c8) =
                *(const uint4*)(g_hb + (size_t)(B0 + r) * NH + c8);
        }
        __syncthreads();
        if (warp < 6) {
            wmma::fragment<wmma::accumulator, 16, 16, 16, float> acc[2];
            wmma::fill_fragment(acc[0], 0.f);
            wmma::fill_fragment(acc[1], 0.f);
            for (int kk = 0; kk < 512; kk += 16) {
                wmma::fragment<wmma::matrix_a, 16, 16, 16, __nv_bfloat16, wmma::row_major> af[2];
                wmma::fragment<wmma::matrix_b, 16, 16, 16, __nv_bfloat16, wmma::col_major> bf;
                wmma::load_matrix_sync(af[0], sH + kk, 520);
                wmma::load_matrix_sync(af[1], sH + 16 * 520 + kk, 520);
                wmma::load_matrix_sync(bf, sW + warp * 16 * 520 + kk, 520);
                wmma::mma_sync(acc[0], af[0], bf, acc[0]);
                wmma::mma_sync(acc[1], af[1], bf, acc[1]);
            }
            wmma::store_matrix_sync(sGH + warp * 16, acc[0], 100, wmma::mem_row_major);
            wmma::store_matrix_sync(sGH + 16 * 100 + warp * 16, acc[1], 100, wmma::mem_row_major);
        }
        __syncthreads();
        for (int i = tid; i < 32 * 32; i += 256) {
            int bi = i >> 5, ci = i & 31;
            int b = B0 + bi, c = C0 + ci;
            const float* x = g_xproj + ((size_t)b * NS + s) * NH3;
            float r = sigmoidf(x[c]           + sB[ci]      + sGH[bi * 100 + ci]      + sB[96 + ci]);
            float z = sigmoidf(x[NH + c]      + sB[32 + ci] + sGH[bi * 100 + 32 + ci] + sB[96 + 32 + ci]);
            float n = tanhf(x[2 * NH + c] + sB[64 + ci] +
                            r * (sGH[bi * 100 + 64 + ci] + sB[96 + 64 + ci]));
            float hp = g_h[b * NH + c];
            float hn = (1.f - z) * n + z * hp;
            g_h[b * NH + c]  = hn;
            g_hb[b * NH + c] = __float2bfloat16(hn);
            size_t oi = ((size_t)b * NS + s) * NH + c;
            g_outh[oi]    = hn;
            g_outh_bf[oi] = __float2bfloat16(hn);
        }
        bgsync(bg);
    }
}

// ---------------- fused plan logits + BCE ----------------
__global__ void k_plan(const int* __restrict__ segments,
                       const float* __restrict__ b_p1,
                       const float* __restrict__ W_p2,
                       const float* __restrict__ b_p2) {
    __shared__ float s_h[NS][NE];
    __shared__ float s_w2[NE];
    __shared__ float s_b1[NE];
    __shared__ float s_warp[8];
    int t = threadIdx.x;
    int b = blockIdx.y, ltile = blockIdx.x;  // (16, B)
    for (int i = t; i < NS * NE; i += 256) s_h[i >> 9][i & 511] = g_hpart[(size_t)b * NS * NE + i];
    for (int i = t; i < NE; i += 256) { s_w2[i] = W_p2[i]; s_b1[i] = b_p1[i]; }
    __syncthreads();

    int warp = t >> 5, lane = t & 31;
    int l = ltile * 8 + warp;
    const float* ep = g_epart + (size_t)(b * NL + l) * NE;
    float epr[16];
    #pragma unroll
    for (int j = 0; j < 16; j++) {
        int e = lane + 32 * j;
        epr[j] = ep[e] + s_b1[e];
    }

    int gcb = g_gc[b];
    int p   = g_idx[b];
    float bp2 = b_p2[0];
    float local = 0.f;
    for (int s = 0; s < gcb; s++) {
        float acc = 0.f;
        #pragma unroll
        for (int j = 0; j < 16; j++) {
            int e = lane + 32 * j;
            acc += fast_tanh(s_h[s][e] + epr[j]) * s_w2[e];
        }
        #pragma unroll
        for (int off = 16; off; off >>= 1) acc += __shfl_xor_sync(0xffffffffu, acc, off);
        if (lane == 0) {
            float pl  = acc + bp2;
            float tgt = (float)segments[(p * NS + s) * NL + l];
            local += softplusf(pl) - pl * tgt;
        }
    }
    if (lane == 0) s_warp[warp] = local;
    __syncthreads();
    if (t == 0) {
        float sum = 0.f;
        #pragma unroll
        for (int w = 0; w < 8; w++) sum += s_warp[w];
        g_plan_partial[b * 16 + ltile] = sum;
    }
}

// ---------------- stop loss + final reduction ----------------
__global__ void k_final(const float* __restrict__ W_stop,
                        const float* __restrict__ b_stop,
                        float* __restrict__ out) {
    __shared__ float s_w[NH];
    __shared__ float s_stop[32];
    __shared__ float s_red[1024];
    int t = threadIdx.x;  // 1024
    for (int i = t; i < NH; i += 1024) s_w[i] = W_stop[i];
    __syncthreads();

    int warp = t >> 5, lane = t & 31;
    float stop_local = 0.f;
    for (int bs = warp; bs < NB * NS; bs += 32) {
        int b = bs / NS, s = bs % NS;
        int gcb = g_gc[b];
        if (s < gcb) {
            const float* o = g_outh + (size_t)bs * NH;
            float a = 0.f;
            #pragma unroll
            for (int j = 0; j < 16; j++) a += o[lane + 32 * j] * s_w[lane + 32 * j];
            #pragma unroll
            for (int off = 16; off; off >>= 1) a += __shfl_xor_sync(0xffffffffu, a, off);
            if (lane == 0) {
                float logit = a + b_stop[0];
                float label = (s == gcb - 1) ? 1.f : 0.f;
                stop_local += softplusf(logit) - logit * label;
            }
        }
    }
    if (lane == 0) s_stop[warp] = stop_local;

    s_red[t] = g_plan_partial[t] + g_plan_partial[t + 1024];
    __syncthreads();
    for (int off = 512; off; off >>= 1) {
        if (t < off) s_red[t] += s_red[t + off];
        __syncthreads();
    }
    if (t == 0) {
        float stop_sum = 0.f;
        #pragma unroll
        for (int w = 0; w < 32; w++) stop_sum += s_stop[w];
        float ms = g_mask_sum;
        out[0] = stop_sum / ms;
        out[1] = s_red[0] / (ms * (float)NL);
    }
}

// ---------------- launch (fork/join two-stream graph) ----------------
extern "C" void kernel_launch(void* const* d_in, const int* in_sizes, int n_in,
                              void* d_out, int out_size) {
    const float* enc    = (const float*)d_in[0];
    const int*   segs   = (const int*)d_in[1];
    const int*   gcnt   = (const int*)d_in[2];
    const float* ginit  = (const float*)d_in[3];
    const float* W_init = (const float*)d_in[4];
    const float* b_init = (const float*)d_in[5];
    const float* W_ih   = (const float*)d_in[6];
    const float* b_ih   = (const float*)d_in[7];
    const float* W_hh   = (const float*)d_in[8];
    const float* b_hh   = (const float*)d_in[9];
    const float* W_p1   = (const float*)d_in[10];
    const float* b_p1   = (const float*)d_in[11];
    const float* W_p2   = (const float*)d_in[12];
    const float* b_p2   = (const float*)d_in[13];
    const float* W_stop = (const float*)d_in[14];
    const float* b_stop = (const float*)d_in[15];
    float* out = (float*)d_out;

    float *p_h, *p_xproj, *p_hpart, *p_epart;
    __nv_bfloat16 *p_inps_bf, *p_outh_bf, *p_enc_bf, *p_wp1_bf, *p_wih_bf, *p_ginit_bf, *p_winit_bf;
    cudaGetSymbolAddress((void**)&p_h,        g_h);
    cudaGetSymbolAddress((void**)&p_xproj,    g_xproj);
    cudaGetSymbolAddress((void**)&p_hpart,    g_hpart);
    cudaGetSymbolAddress((void**)&p_epart,    g_epart);
    cudaGetSymbolAddress((void**)&p_inps_bf,  g_inps_bf);
    cudaGetSymbolAddress((void**)&p_outh_bf,  g_outh_bf);
    cudaGetSymbolAddress((void**)&p_enc_bf,   g_enc_bf);
    cudaGetSymbolAddress((void**)&p_wp1_bf,   g_wp1_bf);
    cudaGetSymbolAddress((void**)&p_wih_bf,   g_wih_bf);
    cudaGetSymbolAddress((void**)&p_ginit_bf, g_ginit_bf);
    cudaGetSymbolAddress((void**)&p_winit_bf, g_winit_bf);

    static cudaStream_t s1 = nullptr;
    static cudaEvent_t e0 = nullptr, e1 = nullptr;
    if (!s1) {
        cudaStreamCreateWithFlags(&s1, cudaStreamNonBlocking);
        cudaEventCreateWithFlags(&e0, cudaEventDisableTiming);
        cudaEventCreateWithFlags(&e1, cudaEventDisableTiming);
        cudaFuncSetAttribute(k_gru_persist, cudaFuncAttributeMaxDynamicSharedMemorySize, 147456);
    }

    // ---- main stream: epart branch (epart = global launch index 3, ncu target) ----
    k_cvt<<<(NE * NH3 / 4 + 255) / 256, 256>>>((const float4*)W_p1, (__nv_bfloat162*)p_wp1_bf, NE * NH3 / 4);
    k_sort<<<1, NB>>>(gcnt);
    k_inps<<<NB, 256>>>(enc, segs);   // -> g_inps_bf, g_enc_bf
    cudaEventRecord(e0, 0);

    // epart = enc @ W1e^T  (16384 x 512, K=1024)
    gemm_bf16<<<dim3(NE / 128, (NB * NL) / 128), 256>>>(p_enc_bf, NE2, p_wp1_bf + NH, NH3, p_epart, NE, NE2);

    // ---- side stream: GRU branch, overlapped with epart ----
    cudaStreamWaitEvent(s1, e0, 0);
    k_cvt<<<(NH3 * NE2 / 4 + 255) / 256, 256, 0, s1>>>((const float4*)W_ih, (__nv_bfloat162*)p_wih_bf, NH3 * NE2 / 4);
    k_cvt<<<(NB * NKIN / 4 + 255) / 256, 256, 0, s1>>>((const float4*)ginit, (__nv_bfloat162*)p_ginit_bf, NB * NKIN / 4);
    k_cvt<<<(NH * NKIN / 4 + 255) / 256, 256, 0, s1>>>((const float4*)W_init, (__nv_bfloat162*)p_winit_bf, NH * NKIN / 4);

    // h0 = ginit @ W_init^T  (128 x 512, K=2304)
    gemm64_bf16<<<dim3(NH / 64, NB / 64), 128, 0, s1>>>(p_ginit_bf, NKIN, p_winit_bf, NKIN, p_h, NH, NKIN);
    // x_proj = inps @ W_ih^T  (1536 x 1536, K=1024)
    gemm_bf16<<<dim3(NH3 / 128, (NB * NS) / 128), 256, 0, s1>>>(p_inps_bf, NE2, p_wih_bf, NE2, p_xproj, NH3, NE2);
    // persistent GRU scan
    k_gru_persist<<<64, 256, 147456, s1>>>(W_hh, b_ih, b_hh, b_init);
    // hpart = outputs @ W1h^T  (1536 x 512, K=512)
    gemm_bf16<<<dim3(NE / 128, (NB * NS) / 128), 256, 0, s1>>>(p_outh_bf, NH, p_wp1_bf, NH3, p_hpart, NE, NH);
    cudaEventRecord(e1, s1);

    // ---- join on main stream ----
    cudaStreamWaitEvent(0, e1, 0);
    k_plan<<<dim3(16, NB), 256>>>(segs, b_p1, W_p2, b_p2);
    k_final<<<1, 1024>>>(W_stop, b_stop, out);
}

// round 5
// speedup vs baseline: 1.1956x; 1.1956x over previous
#include <cuda_runtime.h>
#include <cuda_bf16.h>
#include <mma.h>
#include <cstdint>

using namespace nvcuda;

#define NB   128
#define NS   12
#define NL   128
#define NE   512
#define NE2  1024
#define NH   512
#define NH3  1536
#define NKIN 2304

// ---------------- scratch ----------------
__device__ int   g_idx[NB];
__device__ int   g_gc[NB];
__device__ float g_mask_sum;
__device__ float g_h[NB * NH];
__device__ float g_xproj[NB * NS * NH3];
__device__ float g_outh[NB * NS * NH];
__device__ float g_hpart[NB * NS * NE];
__device__ float g_epart[NB * NL * NE];
__device__ float g_plan_partial[2048];
__device__ unsigned g_bg_arrive[4];
__device__ unsigned g_bg_gen[4];
// bf16 copies
__device__ __nv_bfloat16 g_enc_bf[NB * NL * NE2];
__device__ __nv_bfloat16 g_inps_bf[NB * NS * NE2];
__device__ __nv_bfloat16 g_outh_bf[NB * NS * NH];
__device__ __nv_bfloat16 g_hb[NB * NH];
__device__ __nv_bfloat16 g_wp1_bf[NE * NH3];
__device__ __nv_bfloat16 g_wih_bf[NH3 * NE2];
__device__ __nv_bfloat16 g_ginit_bf[NB * NKIN];
__device__ __nv_bfloat16 g_winit_bf[NH * NKIN];

// ---------------- helpers ----------------
__device__ __forceinline__ float fast_tanh(float x) {
    float y; asm("tanh.approx.f32 %0, %1;" : "=f"(y) : "f"(x)); return y;
}
__device__ __forceinline__ float sigmoidf(float x) { return 1.f / (1.f + __expf(-x)); }
__device__ __forceinline__ float softplusf(float x) { return (x > 15.f) ? x : log1pf(__expf(x)); }

__device__ __forceinline__ void cp16(void* sdst, const void* gsrc) {
    uint32_t s = (uint32_t)__cvta_generic_to_shared(sdst);
    asm volatile("cp.async.cg.shared.global [%0], [%1], 16;\n" :: "r"(s), "l"(gsrc));
}
#define CP_COMMIT() asm volatile("cp.async.commit_group;\n")
#define CP_WAIT1()  asm volatile("cp.async.wait_group 1;\n")
#define CP_WAIT0()  asm volatile("cp.async.wait_group 0;\n")

// ---------------- fp32 -> bf16 convert ----------------
__global__ void k_cvt(const float4* __restrict__ src, __nv_bfloat162* __restrict__ dst, int n4) {
    int i = blockIdx.x * 256 + threadIdx.x;
    if (i < n4) {
        float4 v = src[i];
        dst[2 * i]     = __nv_bfloat162{__float2bfloat16(v.x), __float2bfloat16(v.y)};
        dst[2 * i + 1] = __nv_bfloat162{__float2bfloat16(v.z), __float2bfloat16(v.w)};
    }
}

// ---------------- stable descending sort of group_count ----------------
__global__ void k_sort(const int* __restrict__ gc) {
    __shared__ int s_gc[NB];
    __shared__ int red[NB];
    int t = threadIdx.x;
    s_gc[t] = gc[t];
    __syncthreads();
    int my = s_gc[t];
    int rank = 0;
    #pragma unroll 8
    for (int j = 0; j < NB; j++) {
        int v = s_gc[j];
        rank += (v > my) || (v == my && j < t);
    }
    g_idx[rank] = t;
    g_gc[rank]  = my;
    red[t] = my;
    __syncthreads();
    for (int off = 64; off > 0; off >>= 1) {
        if (t < off) red[t] += red[t + off];
        __syncthreads();
    }
    if (t == 0) g_mask_sum = (float)red[0];
}

// ---------------- alpha + inps einsum; emits bf16 inps and bf16 enc ----------------
__global__ void k_inps(const float* __restrict__ enc, const int* __restrict__ segments) {
    __shared__ float s_a[NS][NL];
    __shared__ float s_inv[NS];
    int b = blockIdx.x, t = threadIdx.x;  // 256
    int p = g_idx[b];
    for (int i = t; i < NS * NL; i += 256) {
        int s = i >> 7, l = i & 127;
        float v = 0.f;
        if (s > 0) v = (float)segments[(p * NS + (s - 1)) * NL + l];
        s_a[s][l] = v;
    }
    __syncthreads();
    if (t < NS) {
        float sum = 0.f;
        for (int l = 0; l < NL; l++) sum += s_a[t][l];
        s_inv[t] = 1.f / (sum + 1.f);
    }
    __syncthreads();
    for (int i = t; i < NS * NL; i += 256) {
        int s = i >> 7;
        s_a[s][i & 127] *= s_inv[s];
    }
    __syncthreads();
    const float* encb = enc + (size_t)b * NL * NE2;
    #pragma unroll
    for (int eo = 0; eo < NE2 / 256; eo++) {
        int e = eo * 256 + t;
        float acc[NS];
        #pragma unroll
        for (int s = 0; s < NS; s++) acc[s] = 0.f;
        for (int l = 0; l < NL; l++) {
            float v = encb[l * NE2 + e];
            g_enc_bf[((size_t)b * NL + l) * NE2 + e] = __float2bfloat16(v);
            #pragma unroll
            for (int s = 0; s < NS; s++) acc[s] += s_a[s][l] * v;
        }
        #pragma unroll
        for (int s = 0; s < NS; s++)
            g_inps_bf[((size_t)b * NS + s) * NE2 + e] = __float2bfloat16(acc[s]);
    }
}

// ---------------- bf16 GEMM: 128x128 block, 4 warps, 64x64 warp tile, 3-stage cp.async ----
// C[m,n] = sum_k A[m,k] * W[n,k]; bf16 in, fp32 out. Dynamic smem = 3*2*128*40*2 B.
#define GSTG 3
__global__ __launch_bounds__(128) void gemm128_bf16(
    const __nv_bfloat16* __restrict__ A, int lda,
    const __nv_bfloat16* __restrict__ W, int ldw,
    float* __restrict__ C, int ldc, int K) {
    extern __shared__ __align__(16) __nv_bfloat16 gsm[];
    __nv_bfloat16* sA = gsm;                  // [GSTG][128][40]
    __nv_bfloat16* sW = gsm + GSTG * 128 * 40;

    const int tid  = threadIdx.x;
    const int warp = tid >> 5;
    const int wm   = warp & 1;     // m offset wm*64
    const int wn   = warp >> 1;    // n offset wn*64
    const int m0   = blockIdx.y * 128;
    const int n0   = blockIdx.x * 128;
    const int nkt  = K >> 5;

    wmma::fragment<wmma::accumulator, 16, 16, 16, float> acc[4][4];
    #pragma unroll
    for (int i = 0; i < 4; i++)
        #pragma unroll
        for (int j = 0; j < 4; j++) wmma::fill_fragment(acc[i][j], 0.f);

    auto issue = [&](int kt, int st) {
        int k0 = kt << 5;
        __nv_bfloat16* a = sA + st * 128 * 40;
        __nv_bfloat16* w = sW + st * 128 * 40;
        #pragma unroll
        for (int q = 0; q < 4; q++) {
            int chunk = q * 128 + tid;        // 0..511
            int r  = chunk >> 2;              // 0..127
            int c8 = (chunk & 3) * 8;
            cp16(a + r * 40 + c8, A + (size_t)(m0 + r) * lda + k0 + c8);
            cp16(w + r * 40 + c8, W + (size_t)(n0 + r) * ldw + k0 + c8);
        }
        CP_COMMIT();
    };

    issue(0, 0);
    issue(1, 1);
    for (int kt = 0; kt < nkt; kt++) {
        int st = kt % GSTG;
        CP_WAIT1();          // oldest group (stage st) complete
        __syncthreads();     // also: everyone done computing stage (kt-1)%GSTG
        if (kt + 2 < nkt) issue(kt + 2, (kt + 2) % GSTG);
        const __nv_bfloat16* a = sA + st * 128 * 40;
        const __nv_bfloat16* w = sW + st * 128 * 40;
        #pragma unroll
        for (int kk = 0; kk < 32; kk += 16) {
            wmma::fragment<wmma::matrix_a, 16, 16, 16, __nv_bfloat16, wmma::row_major> af[4];
            wmma::fragment<wmma::matrix_b, 16, 16, 16, __nv_bfloat16, wmma::col_major> bf[4];
            #pragma unroll
            for (int i = 0; i < 4; i++)
                wmma::load_matrix_sync(af[i], a + (wm * 64 + i * 16) * 40 + kk, 40);
            #pragma unroll
            for (int j = 0; j < 4; j++)
                wmma::load_matrix_sync(bf[j], w + (wn * 64 + j * 16) * 40 + kk, 40);
            #pragma unroll
            for (int i = 0; i < 4; i++)
                #pragma unroll
                for (int j = 0; j < 4; j++)
                    wmma::mma_sync(acc[i][j], af[i], bf[j], acc[i][j]);
        }
    }
    #pragma unroll
    for (int i = 0; i < 4; i++)
        #pragma unroll
        for (int j = 0; j < 4; j++)
            wmma::store_matrix_sync(
                C + (size_t)(m0 + wm * 64 + i * 16) * ldc + n0 + wn * 64 + j * 16,
                acc[i][j], ldc, wmma::mem_row_major);
}
#define GSMEM (GSTG * 2 * 128 * 40 * 2)   // 61440 B

// ---------------- bf16 GEMM, 64x64 tile (h0) ----------------
__global__ __launch_bounds__(128) void gemm64_bf16(
    const __nv_bfloat16* __restrict__ A, int lda,
    const __nv_bfloat16* __restrict__ W, int ldw,
    float* __restrict__ C, int ldc, int K) {
    __shared__ __align__(16) __nv_bfloat16 As[2][64][40];
    __shared__ __align__(16) __nv_bfloat16 Ws[2][64][40];

    const int tid  = threadIdx.x;
    const int warp = tid >> 5;
    const int wm   = warp & 1;
    const int wn   = warp >> 1;
    const int m0   = blockIdx.y * 64;
    const int n0   = blockIdx.x * 64;
    const int nkt  = K >> 5;

    wmma::fragment<wmma::accumulator, 16, 16, 16, float> acc[2][2];
    #pragma unroll
    for (int i = 0; i < 2; i++)
        #pragma unroll
        for (int j = 0; j < 2; j++) wmma::fill_fragment(acc[i][j], 0.f);

    auto issue = [&](int kt, int st) {
        int k0 = kt << 5;
        #pragma unroll
        for (int q = 0; q < 2; q++) {
            int chunk = tid * 2 + q;
            int r  = chunk >> 2;
            int c8 = (chunk & 3) * 8;
            cp16(&As[st][r][c8], A + (size_t)(m0 + r) * lda + k0 + c8);
            cp16(&Ws[st][r][c8], W + (size_t)(n0 + r) * ldw + k0 + c8);
        }
        CP_COMMIT();
    };

    issue(0, 0);
    for (int kt = 0; kt < nkt; kt++) {
        int st = kt & 1;
        if (kt + 1 < nkt) { issue(kt + 1, st ^ 1); CP_WAIT1(); }
        else             { CP_WAIT0(); }
        __syncthreads();
        #pragma unroll
        for (int kk = 0; kk < 32; kk += 16) {
            wmma::fragment<wmma::matrix_a, 16, 16, 16, __nv_bfloat16, wmma::row_major> af[2];
            wmma::fragment<wmma::matrix_b, 16, 16, 16, __nv_bfloat16, wmma::col_major> bf[2];
            #pragma unroll
            for (int i = 0; i < 2; i++)
                wmma::load_matrix_sync(af[i], &As[st][wm * 32 + i * 16][kk], 40);
            #pragma unroll
            for (int j = 0; j < 2; j++)
                wmma::load_matrix_sync(bf[j], &Ws[st][wn * 32 + j * 16][kk], 40);
            #pragma unroll
            for (int i = 0; i < 2; i++)
                #pragma unroll
                for (int j = 0; j < 2; j++)
                    wmma::mma_sync(acc[i][j], af[i], bf[j], acc[i][j]);
        }
        __syncthreads();
    }
    #pragma unroll
    for (int i = 0; i < 2; i++)
        #pragma unroll
        for (int j = 0; j < 2; j++)
            wmma::store_matrix_sync(
                C + (size_t)(m0 + wm * 32 + i * 16) * ldc + n0 + wn * 32 + j * 16,
                acc[i][j], ldc, wmma::mem_row_major);
}

// ---------------- per-batch-group barrier (16 CTAs each) ----------------
__device__ __forceinline__ void bgsync(int bg) {
    __syncthreads();
    if (threadIdx.x == 0) {
        unsigned gen;
        asm volatile("ld.acquire.gpu.u32 %0, [%1];" : "=r"(gen) : "l"(&g_bg_gen[bg]) : "memory");
        __threadfence();
        unsigned old = atomicAdd(&g_bg_arrive[bg], 1u);
        if (old == 15) {
            g_bg_arrive[bg] = 0;
            __threadfence();
            atomicAdd(&g_bg_gen[bg], 1u);
        } else {
            unsigned cur;
            do {
                __nanosleep(32);
                asm volatile("ld.acquire.gpu.u32 %0, [%1];" : "=r"(cur) : "l"(&g_bg_gen[bg]) : "memory");
            } while (cur == gen);
        }
    }
    __syncthreads();
}

// ---------------- persistent GRU scan ----------------
__global__ __launch_bounds__(256) void k_gru_persist(
    const float* __restrict__ Whh, const float* __restrict__ bih,
    const float* __restrict__ bhh, const float* __restrict__ binit) {
    extern __shared__ __align__(16) char dyn[];
    __nv_bfloat16* sW  = (__nv_bfloat16*)dyn;          // [96][520]
    __nv_bfloat16* sH  = sW + 96 * 520;                // [32][520]
    float*         sGH = (float*)(sH + 32 * 520);      // [32][100]
    float*         sB  = sGH + 32 * 100;               // [192]

    const int tid  = threadIdx.x;
    const int warp = tid >> 5;
    const int cs   = blockIdx.x & 15;
    const int bg   = blockIdx.x >> 4;
    const int C0   = cs * 32;
    const int B0   = bg * 32;

    for (int i = tid; i < 96 * 128; i += 256) {
        int r = i >> 7, c4 = (i & 127) * 4;
        int p = r >> 5, j = r & 31;
        float4 v = *(const float4*)(Whh + (size_t)(p * NH + C0 + j) * NH + c4);
        __nv_bfloat16* d = sW + r * 520 + c4;
        d[0] = __float2bfloat16(v.x); d[1] = __float2bfloat16(v.y);
        d[2] = __float2bfloat16(v.z); d[3] = __float2bfloat16(v.w);
    }
    if (tid < 96) {
        int p = tid >> 5, j = tid & 31;
        sB[tid]      = bih[p * NH + C0 + j];
        sB[96 + tid] = bhh[p * NH + C0 + j];
    }
    for (int i = tid; i < 32 * 32; i += 256) {
        int bi = i >> 5, ci = i & 31;
        int b = B0 + bi, c = C0 + ci;
        float v = g_h[b * NH + c] + binit[c];
        g_h[b * NH + c]  = v;
        g_hb[b * NH + c] = __float2bfloat16(v);
    }
    const int smax = g_gc[B0];
    bgsync(bg);

    for (int s = 0; s < smax; s++) {
        for (int i = tid; i < 32 * 64; i += 256) {
            int r = i >> 6, c8 = (i & 63) * 8;
            *(uint4*)(sH + r * 520 + c8) =
                *(const uint4*)(g_hb + (size_t)(B0 + r) * NH + c8);
        }
        __syncthreads();
        if (warp < 6) {
            wmma::fragment<wmma::accumulator, 16, 16, 16, float> acc[2];
            wmma::fill_fragment(acc[0], 0.f);
            wmma::fill_fragment(acc[1], 0.f);
            for (int kk = 0; kk < 512; kk += 16) {
                wmma::fragment<wmma::matrix_a, 16, 16, 16, __nv_bfloat16, wmma::row_major> af[2];
                wmma::fragment<wmma::matrix_b, 16, 16, 16, __nv_bfloat16, wmma::col_major> bf;
                wmma::load_matrix_sync(af[0], sH + kk, 520);
                wmma::load_matrix_sync(af[1], sH + 16 * 520 + kk, 520);
                wmma::load_matrix_sync(bf, sW + warp * 16 * 520 + kk, 520);
                wmma::mma_sync(acc[0], af[0], bf, acc[0]);
                wmma::mma_sync(acc[1], af[1], bf, acc[1]);
            }
            wmma::store_matrix_sync(sGH + warp * 16, acc[0], 100, wmma::mem_row_major);
            wmma::store_matrix_sync(sGH + 16 * 100 + warp * 16, acc[1], 100, wmma::mem_row_major);
        }
        __syncthreads();
        for (int i = tid; i < 32 * 32; i += 256) {
            int bi = i >> 5, ci = i & 31;
            int b = B0 + bi, c = C0 + ci;
            const float* x = g_xproj + ((size_t)b * NS + s) * NH3;
            float r = sigmoidf(x[c]           + sB[ci]      + sGH[bi * 100 + ci]      + sB[96 + ci]);
            float z = sigmoidf(x[NH + c]      + sB[32 + ci] + sGH[bi * 100 + 32 + ci] + sB[96 + 32 + ci]);
            float n = tanhf(x[2 * NH + c] + sB[64 + ci] +
                            r * (sGH[bi * 100 + 64 + ci] + sB[96 + 64 + ci]));
            float hp = g_h[b * NH + c];
            float hn = (1.f - z) * n + z * hp;
            g_h[b * NH + c]  = hn;
            g_hb[b * NH + c] = __float2bfloat16(hn);
            size_t oi = ((size_t)b * NS + s) * NH + c;
            g_outh[oi]    = hn;
            g_outh_bf[oi] = __float2bfloat16(hn);
        }
        bgsync(bg);
    }
}

// ---------------- fused plan logits + BCE ----------------
__global__ void k_plan(const int* __restrict__ segments,
                       const float* __restrict__ b_p1,
                       const float* __restrict__ W_p2,
                       const float* __restrict__ b_p2) {
    __shared__ float s_h[NS][NE];
    __shared__ float s_w2[NE];
    __shared__ float s_b1[NE];
    __shared__ float s_warp[8];
    int t = threadIdx.x;
    int b = blockIdx.y, ltile = blockIdx.x;  // (16, B)
    for (int i = t; i < NS * NE; i += 256) s_h[i >> 9][i & 511] = g_hpart[(size_t)b * NS * NE + i];
    for (int i = t; i < NE; i += 256) { s_w2[i] = W_p2[i]; s_b1[i] = b_p1[i]; }
    __syncthreads();

    int warp = t >> 5, lane = t & 31;
    int l = ltile * 8 + warp;
    const float* ep = g_epart + (size_t)(b * NL + l) * NE;
    float epr[16];
    #pragma unroll
    for (int j = 0; j < 16; j++) {
        int e = lane + 32 * j;
        epr[j] = ep[e] + s_b1[e];
    }

    int gcb = g_gc[b];
    int p   = g_idx[b];
    float bp2 = b_p2[0];
    float local = 0.f;
    for (int s = 0; s < gcb; s++) {
        float acc = 0.f;
        #pragma unroll
        for (int j = 0; j < 16; j++) {
            int e = lane + 32 * j;
            acc += fast_tanh(s_h[s][e] + epr[j]) * s_w2[e];
        }
        #pragma unroll
        for (int off = 16; off; off >>= 1) acc += __shfl_xor_sync(0xffffffffu, acc, off);
        if (lane == 0) {
            float pl  = acc + bp2;
            float tgt = (float)segments[(p * NS + s) * NL + l];
            local += softplusf(pl) - pl * tgt;
        }
    }
    if (lane == 0) s_warp[warp] = local;
    __syncthreads();
    if (t == 0) {
        float sum = 0.f;
        #pragma unroll
        for (int w = 0; w < 8; w++) sum += s_warp[w];
        g_plan_partial[b * 16 + ltile] = sum;
    }
}

// ---------------- stop loss + final reduction ----------------
__global__ void k_final(const float* __restrict__ W_stop,
                        const float* __restrict__ b_stop,
                        float* __restrict__ out) {
    __shared__ float s_w[NH];
    __shared__ float s_stop[32];
    __shared__ float s_red[1024];
    int t = threadIdx.x;  // 1024
    for (int i = t; i < NH; i += 1024) s_w[i] = W_stop[i];
    __syncthreads();

    int warp = t >> 5, lane = t & 31;
    float stop_local = 0.f;
    for (int bs = warp; bs < NB * NS; bs += 32) {
        int b = bs / NS, s = bs % NS;
        int gcb = g_gc[b];
        if (s < gcb) {
            const float* o = g_outh + (size_t)bs * NH;
            float a = 0.f;
            #pragma unroll
            for (int j = 0; j < 16; j++) a += o[lane + 32 * j] * s_w[lane + 32 * j];
            #pragma unroll
            for (int off = 16; off; off >>= 1) a += __shfl_xor_sync(0xffffffffu, a, off);
            if (lane == 0) {
                float logit = a + b_stop[0];
                float label = (s == gcb - 1) ? 1.f : 0.f;
                stop_local += softplusf(logit) - logit * label;
            }
        }
    }
    if (lane == 0) s_stop[warp] = stop_local;

    s_red[t] = g_plan_partial[t] + g_plan_partial[t + 1024];
    __syncthreads();
    for (int off = 512; off; off >>= 1) {
        if (t < off) s_red[t] += s_red[t + off];
        __syncthreads();
    }
    if (t == 0) {
        float stop_sum = 0.f;
        #pragma unroll
        for (int w = 0; w < 32; w++) stop_sum += s_stop[w];
        float ms = g_mask_sum;
        out[0] = stop_sum / ms;
        out[1] = s_red[0] / (ms * (float)NL);
    }
}

// ---------------- launch (single stream) ----------------
extern "C" void kernel_launch(void* const* d_in, const int* in_sizes, int n_in,
                              void* d_out, int out_size) {
    const float* enc    = (const float*)d_in[0];
    const int*   segs   = (const int*)d_in[1];
    const int*   gcnt   = (const int*)d_in[2];
    const float* ginit  = (const float*)d_in[3];
    const float* W_init = (const float*)d_in[4];
    const float* b_init = (const float*)d_in[5];
    const float* W_ih   = (const float*)d_in[6];
    const float* b_ih   = (const float*)d_in[7];
    const float* W_hh   = (const float*)d_in[8];
    const float* b_hh   = (const float*)d_in[9];
    const float* W_p1   = (const float*)d_in[10];
    const float* b_p1   = (const float*)d_in[11];
    const float* W_p2   = (const float*)d_in[12];
    const float* b_p2   = (const float*)d_in[13];
    const float* W_stop = (const float*)d_in[14];
    const float* b_stop = (const float*)d_in[15];
    float* out = (float*)d_out;

    float *p_h, *p_xproj, *p_hpart, *p_epart;
    __nv_bfloat16 *p_inps_bf, *p_outh_bf, *p_enc_bf, *p_wp1_bf, *p_wih_bf, *p_ginit_bf, *p_winit_bf;
    cudaGetSymbolAddress((void**)&p_h,        g_h);
    cudaGetSymbolAddress((void**)&p_xproj,    g_xproj);
    cudaGetSymbolAddress((void**)&p_hpart,    g_hpart);
    cudaGetSymbolAddress((void**)&p_epart,    g_epart);
    cudaGetSymbolAddress((void**)&p_inps_bf,  g_inps_bf);
    cudaGetSymbolAddress((void**)&p_outh_bf,  g_outh_bf);
    cudaGetSymbolAddress((void**)&p_enc_bf,   g_enc_bf);
    cudaGetSymbolAddress((void**)&p_wp1_bf,   g_wp1_bf);
    cudaGetSymbolAddress((void**)&p_wih_bf,   g_wih_bf);
    cudaGetSymbolAddress((void**)&p_ginit_bf, g_ginit_bf);
    cudaGetSymbolAddress((void**)&p_winit_bf, g_winit_bf);

    static int inited = 0;
    if (!inited) {
        cudaFuncSetAttribute(k_gru_persist, cudaFuncAttributeMaxDynamicSharedMemorySize, 147456);
        cudaFuncSetAttribute(gemm128_bf16, cudaFuncAttributeMaxDynamicSharedMemorySize, GSMEM);
        inited = 1;
    }

    // converts
    k_cvt<<<(NE * NH3 / 4 + 255) / 256, 256>>>((const float4*)W_p1, (__nv_bfloat162*)p_wp1_bf, NE * NH3 / 4);
    k_cvt<<<(NH3 * NE2 / 4 + 255) / 256, 256>>>((const float4*)W_ih, (__nv_bfloat162*)p_wih_bf, NH3 * NE2 / 4);
    k_cvt<<<(NB * NKIN / 4 + 255) / 256, 256>>>((const float4*)ginit, (__nv_bfloat162*)p_ginit_bf, NB * NKIN / 4);
    k_cvt<<<(NH * NKIN / 4 + 255) / 256, 256>>>((const float4*)W_init, (__nv_bfloat162*)p_winit_bf, NH * NKIN / 4);

    k_sort<<<1, NB>>>(gcnt);
    k_inps<<<NB, 256>>>(enc, segs);   // -> g_inps_bf, g_enc_bf

    // epart = enc @ W1e^T  (16384 x 512, K=1024)
    gemm128_bf16<<<dim3(NE / 128, (NB * NL) / 128), 128, GSMEM>>>(
        p_enc_bf, NE2, p_wp1_bf + NH, NH3, p_epart, NE, NE2);

    // h0 = ginit @ W_init^T  (128 x 512, K=2304)
    gemm64_bf16<<<dim3(NH / 64, NB / 64), 128>>>(p_ginit_bf, NKIN, p_winit_bf, NKIN, p_h, NH, NKIN);

    // x_proj = inps @ W_ih^T  (1536 x 1536, K=1024)
    gemm128_bf16<<<dim3(NH3 / 128, (NB * NS) / 128), 128, GSMEM>>>(
        p_inps_bf, NE2, p_wih_bf, NE2, p_xproj, NH3, NE2);

    // persistent GRU scan
    k_gru_persist<<<64, 256, 147456>>>(W_hh, b_ih, b_hh, b_init);

    // hpart = outputs @ W1h^T  (1536 x 512, K=512)
    gemm128_bf16<<<dim3(NE / 128, (NB * NS) / 128), 128, GSMEM>>>(
        p_outh_bf, NH, p_wp1_bf, NH3, p_hpart, NE, NH);

    k_plan<<<dim3(16, NB), 256>>>(segs, b_p1, W_p2, b_p2);
    k_final<<<1, 1024>>>(W_stop, b_stop, out);
}

// round 8
// speedup vs baseline: 1.3715x; 1.1471x over previous
// R8: re-bench of R7 (round-7 bench died to a container/broker infra failure,
// same signature as round 0; no kernel-side diagnostics). Logic unchanged.
#include <cuda_runtime.h>
#include <cuda_bf16.h>
#include <mma.h>
#include <cstdint>

using namespace nvcuda;

#define NB   128
#define NS   12
#define NL   128
#define NE   512
#define NE2  1024
#define NH   512
#define NH3  1536
#define NKIN 2304

// ---------------- scratch ----------------
__device__ int   g_idx[NB];
__device__ int   g_gc[NB];
__device__ float g_mask_sum;
__device__ float g_h[NB * NH];
__device__ float g_xproj[NB * NS * NH3];
__device__ float g_hpart[NB * NS * NE];
__device__ float g_plan_partial[2048];
__device__ unsigned g_bg_arrive[4];
__device__ unsigned g_bg_gen[4];
// bf16 buffers
__device__ __nv_bfloat16 g_epart_bf[NB * NL * NE];
__device__ __nv_bfloat16 g_enc_bf[NB * NL * NE2];
__device__ __nv_bfloat16 g_inps_bf[NB * NS * NE2];
__device__ __nv_bfloat16 g_outh_bf[NB * NS * NH];
__device__ __nv_bfloat16 g_hb[NB * NH];
__device__ __nv_bfloat16 g_wp1_bf[NE * NH3];
__device__ __nv_bfloat16 g_wih_bf[NH3 * NE2];
__device__ __nv_bfloat16 g_ginit_bf[NB * NKIN];
__device__ __nv_bfloat16 g_winit_bf[NH * NKIN];

// ---------------- helpers ----------------
__device__ __forceinline__ float fast_tanh(float x) {
    float y; asm("tanh.approx.f32 %0, %1;" : "=f"(y) : "f"(x)); return y;
}
__device__ __forceinline__ float sigmoidf(float x) { return 1.f / (1.f + __expf(-x)); }
__device__ __forceinline__ float softplusf(float x) { return (x > 15.f) ? x : log1pf(__expf(x)); }

__device__ __forceinline__ void cp16(void* sdst, const void* gsrc) {
    uint32_t s = (uint32_t)__cvta_generic_to_shared(sdst);
    asm volatile("cp.async.cg.shared.global [%0], [%1], 16;\n" :: "r"(s), "l"(gsrc));
}
#define CP_COMMIT() asm volatile("cp.async.commit_group;\n")
#define CP_WAIT1()  asm volatile("cp.async.wait_group 1;\n")
#define CP_WAIT0()  asm volatile("cp.async.wait_group 0;\n")

__device__ __forceinline__ uint32_t bf2_bits(float a, float b) {
    __nv_bfloat162 v{__float2bfloat16(a), __float2bfloat16(b)};
    return *reinterpret_cast<uint32_t*>(&v);
}

// ---------------- fp32 -> bf16 convert ----------------
__global__ void k_cvt(const float4* __restrict__ src, __nv_bfloat162* __restrict__ dst, int n4) {
    int i = blockIdx.x * 256 + threadIdx.x;
    if (i < n4) {
        float4 v = src[i];
        dst[2 * i]     = __nv_bfloat162{__float2bfloat16(v.x), __float2bfloat16(v.y)};
        dst[2 * i + 1] = __nv_bfloat162{__float2bfloat16(v.z), __float2bfloat16(v.w)};
    }
}

// ---------------- stable descending sort of group_count ----------------
__global__ void k_sort(const int* __restrict__ gc) {
    __shared__ int s_gc[NB];
    __shared__ int red[NB];
    int t = threadIdx.x;
    s_gc[t] = gc[t];
    __syncthreads();
    int my = s_gc[t];
    int rank = 0;
    #pragma unroll 8
    for (int j = 0; j < NB; j++) {
        int v = s_gc[j];
        rank += (v > my) || (v == my && j < t);
    }
    g_idx[rank] = t;
    g_gc[rank]  = my;
    red[t] = my;
    __syncthreads();
    for (int off = 64; off > 0; off >>= 1) {
        if (t < off) red[t] += red[t + off];
        __syncthreads();
    }
    if (t == 0) g_mask_sum = (float)red[0];
}

// ---------------- alpha + inps einsum (vectorized); emits bf16 inps + bf16 enc ----------------
__global__ __launch_bounds__(256) void k_inps(const float* __restrict__ enc,
                                              const int* __restrict__ segments) {
    __shared__ float s_a[NS][NL];
    __shared__ float s_inv[NS];
    int b = blockIdx.x, t = threadIdx.x;  // 256 threads; each owns 4 consecutive e
    int p = g_idx[b];
    for (int i = t; i < NS * NL; i += 256) {
        int s = i >> 7, l = i & 127;
        float v = 0.f;
        if (s > 0) v = (float)segments[(p * NS + (s - 1)) * NL + l];
        s_a[s][l] = v;
    }
    __syncthreads();
    if (t < NS) {
        float sum = 0.f;
        for (int l = 0; l < NL; l++) sum += s_a[t][l];
        s_inv[t] = 1.f / (sum + 1.f);
    }
    __syncthreads();
    for (int i = t; i < NS * NL; i += 256) {
        int s = i >> 7;
        s_a[s][i & 127] *= s_inv[s];
    }
    __syncthreads();

    const float* encb = enc + (size_t)b * NL * NE2;
    const int e4 = t * 4;
    float acc[NS][4];
    #pragma unroll
    for (int s = 0; s < NS; s++)
        #pragma unroll
        for (int q = 0; q < 4; q++) acc[s][q] = 0.f;

    for (int l = 0; l < NL; l++) {
        float4 v = *reinterpret_cast<const float4*>(encb + (size_t)l * NE2 + e4);
        uint2 pk{bf2_bits(v.x, v.y), bf2_bits(v.z, v.w)};
        *reinterpret_cast<uint2*>(g_enc_bf + ((size_t)b * NL + l) * NE2 + e4) = pk;
        #pragma unroll
        for (int s = 0; s < NS; s++) {
            float a = s_a[s][l];
            acc[s][0] += a * v.x; acc[s][1] += a * v.y;
            acc[s][2] += a * v.z; acc[s][3] += a * v.w;
        }
    }
    #pragma unroll
    for (int s = 0; s < NS; s++) {
        uint2 pk{bf2_bits(acc[s][0], acc[s][1]), bf2_bits(acc[s][2], acc[s][3])};
        *reinterpret_cast<uint2*>(g_inps_bf + ((size_t)b * NS + s) * NE2 + e4) = pk;
    }
}

// ---------------- bf16 GEMM: 128x128 block, 4 warps, 64x64 warp tile, 3-stage cp.async ----
#define GSTG 3
template <typename OutT>
__global__ __launch_bounds__(128) void gemm128(
    const __nv_bfloat16* __restrict__ A, int lda,
    const __nv_bfloat16* __restrict__ W, int ldw,
    OutT* __restrict__ C, int ldc, int K) {
    extern __shared__ __align__(16) __nv_bfloat16 gsm[];
    __nv_bfloat16* sA = gsm;                  // [GSTG][128][40]
    __nv_bfloat16* sW = gsm + GSTG * 128 * 40;

    const int tid  = threadIdx.x;
    const int warp = tid >> 5;
    const int lane = tid & 31;
    const int wm   = warp & 1;
    const int wn   = warp >> 1;
    const int m0   = blockIdx.y * 128;
    const int n0   = blockIdx.x * 128;
    const int nkt  = K >> 5;

    wmma::fragment<wmma::accumulator, 16, 16, 16, float> acc[4][4];
    #pragma unroll
    for (int i = 0; i < 4; i++)
        #pragma unroll
        for (int j = 0; j < 4; j++) wmma::fill_fragment(acc[i][j], 0.f);

    auto issue = [&](int kt, int st) {
        int k0 = kt << 5;
        __nv_bfloat16* a = sA + st * 128 * 40;
        __nv_bfloat16* w = sW + st * 128 * 40;
        #pragma unroll
        for (int q = 0; q < 4; q++) {
            int chunk = q * 128 + tid;        // 0..511
            int r  = chunk >> 2;              // 0..127
            int c8 = (chunk & 3) * 8;
            cp16(a + r * 40 + c8, A + (size_t)(m0 + r) * lda + k0 + c8);
            cp16(w + r * 40 + c8, W + (size_t)(n0 + r) * ldw + k0 + c8);
        }
        CP_COMMIT();
    };

    issue(0, 0);
    issue(1, 1);
    for (int kt = 0; kt < nkt; kt++) {
        int st = kt % GSTG;
        if (kt == nkt - 1) CP_WAIT0(); else CP_WAIT1();
        __syncthreads();
        if (kt + 2 < nkt) issue(kt + 2, (kt + 2) % GSTG);
        const __nv_bfloat16* a = sA + st * 128 * 40;
        const __nv_bfloat16* w = sW + st * 128 * 40;
        #pragma unroll
        for (int kk = 0; kk < 32; kk += 16) {
            wmma::fragment<wmma::matrix_a, 16, 16, 16, __nv_bfloat16, wmma::row_major> af[4];
            wmma::fragment<wmma::matrix_b, 16, 16, 16, __nv_bfloat16, wmma::col_major> bf[4];
            #pragma unroll
            for (int i = 0; i < 4; i++)
                wmma::load_matrix_sync(af[i], a + (wm * 64 + i * 16) * 40 + kk, 40);
            #pragma unroll
            for (int j = 0; j < 4; j++)
                wmma::load_matrix_sync(bf[j], w + (wn * 64 + j * 16) * 40 + kk, 40);
            #pragma unroll
            for (int i = 0; i < 4; i++)
                #pragma unroll
                for (int j = 0; j < 4; j++)
                    wmma::mma_sync(acc[i][j], af[i], bf[j], acc[i][j]);
        }
        __syncthreads();
    }

    if constexpr (sizeof(OutT) == 4) {
        #pragma unroll
        for (int i = 0; i < 4; i++)
            #pragma unroll
            for (int j = 0; j < 4; j++)
                wmma::store_matrix_sync(
                    (float*)C + (size_t)(m0 + wm * 64 + i * 16) * ldc + n0 + wn * 64 + j * 16,
                    acc[i][j], ldc, wmma::mem_row_major);
    } else {
        // bf16 epilogue via per-warp smem staging (16x68 fp32 per warp)
        float* stage = reinterpret_cast<float*>(gsm) + warp * 16 * 68;
        #pragma unroll
        for (int i = 0; i < 4; i++) {
            #pragma unroll
            for (int j = 0; j < 4; j++)
                wmma::store_matrix_sync(stage + j * 16, acc[i][j], 68, wmma::mem_row_major);
            __syncwarp();
            int gr = m0 + wm * 64 + i * 16;
            int gc0 = n0 + wn * 64;
            #pragma unroll
            for (int p = 0; p < 16; p++) {
                float v0 = stage[p * 68 + lane * 2];
                float v1 = stage[p * 68 + lane * 2 + 1];
                uint32_t pk = bf2_bits(v0, v1);
                *reinterpret_cast<uint32_t*>(
                    (__nv_bfloat16*)C + (size_t)(gr + p) * ldc + gc0 + lane * 2) = pk;
            }
            __syncwarp();
        }
    }
}
#define GSMEM (GSTG * 2 * 128 * 40 * 2)   // 61440 B

// ---------------- bf16 GEMM, 64x64 tile (h0) ----------------
__global__ __launch_bounds__(128) void gemm64_bf16(
    const __nv_bfloat16* __restrict__ A, int lda,
    const __nv_bfloat16* __restrict__ W, int ldw,
    float* __restrict__ C, int ldc, int K) {
    __shared__ __align__(16) __nv_bfloat16 As[2][64][40];
    __shared__ __align__(16) __nv_bfloat16 Ws[2][64][40];

    const int tid  = threadIdx.x;
    const int warp = tid >> 5;
    const int wm   = warp & 1;
    const int wn   = warp >> 1;
    const int m0   = blockIdx.y * 64;
    const int n0   = blockIdx.x * 64;
    const int nkt  = K >> 5;

    wmma::fragment<wmma::accumulator, 16, 16, 16, float> acc[2][2];
    #pragma unroll
    for (int i = 0; i < 2; i++)
        #pragma unroll
        for (int j = 0; j < 2; j++) wmma::fill_fragment(acc[i][j], 0.f);

    auto issue = [&](int kt, int st) {
        int k0 = kt << 5;
        #pragma unroll
        for (int q = 0; q < 2; q++) {
            int chunk = tid * 2 + q;
            int r  = chunk >> 2;
            int c8 = (chunk & 3) * 8;
            cp16(&As[st][r][c8], A + (size_t)(m0 + r) * lda + k0 + c8);
            cp16(&Ws[st][r][c8], W + (size_t)(n0 + r) * ldw + k0 + c8);
        }
        CP_COMMIT();
    };

    issue(0, 0);
    for (int kt = 0; kt < nkt; kt++) {
        int st = kt & 1;
        if (kt + 1 < nkt) { issue(kt + 1, st ^ 1); CP_WAIT1(); }
        else             { CP_WAIT0(); }
        __syncthreads();
        #pragma unroll
        for (int kk = 0; kk < 32; kk += 16) {
            wmma::fragment<wmma::matrix_a, 16, 16, 16, __nv_bfloat16, wmma::row_major> af[2];
            wmma::fragment<wmma::matrix_b, 16, 16, 16, __nv_bfloat16, wmma::col_major> bf[2];
            #pragma unroll
            for (int i = 0; i < 2; i++)
                wmma::load_matrix_sync(af[i], &As[st][wm * 32 + i * 16][kk], 40);
            #pragma unroll
            for (int j = 0; j < 2; j++)
                wmma::load_matrix_sync(bf[j], &Ws[st][wn * 32 + j * 16][kk], 40);
            #pragma unroll
            for (int i = 0; i < 2; i++)
                #pragma unroll
                for (int j = 0; j < 2; j++)
                    wmma::mma_sync(acc[i][j], af[i], bf[j], acc[i][j]);
        }
        __syncthreads();
    }
    #pragma unroll
    for (int i = 0; i < 2; i++)
        #pragma unroll
        for (int j = 0; j < 2; j++)
            wmma::store_matrix_sync(
                C + (size_t)(m0 + wm * 32 + i * 16) * ldc + n0 + wn * 32 + j * 16,
                acc[i][j], ldc, wmma::mem_row_major);
}

// ---------------- per-batch-group barrier (16 CTAs each) ----------------
__device__ __forceinline__ void bgsync(int bg) {
    __syncthreads();
    if (threadIdx.x == 0) {
        unsigned gen;
        asm volatile("ld.acquire.gpu.u32 %0, [%1];" : "=r"(gen) : "l"(&g_bg_gen[bg]) : "memory");
        __threadfence();
        unsigned old = atomicAdd(&g_bg_arrive[bg], 1u);
        if (old == 15) {
            g_bg_arrive[bg] = 0;
            __threadfence();
            atomicAdd(&g_bg_gen[bg], 1u);
        } else {
            unsigned cur;
            do {
                __nanosleep(32);
                asm volatile("ld.acquire.gpu.u32 %0, [%1];" : "=r"(cur) : "l"(&g_bg_gen[bg]) : "memory");
            } while (cur == gen);
        }
    }
    __syncthreads();
}

// ---------------- persistent GRU scan ----------------
__global__ __launch_bounds__(256) void k_gru_persist(
    const float* __restrict__ Whh, const float* __restrict__ bih,
    const float* __restrict__ bhh, const float* __restrict__ binit) {
    extern __shared__ __align__(16) char dyn[];
    __nv_bfloat16* sW  = (__nv_bfloat16*)dyn;          // [96][520]
    __nv_bfloat16* sH  = sW + 96 * 520;                // [32][520]
    float*         sGH = (float*)(sH + 32 * 520);      // [32][100]
    float*         sB  = sGH + 32 * 100;               // [192]

    const int tid  = threadIdx.x;
    const int warp = tid >> 5;
    const int cs   = blockIdx.x & 15;
    const int bg   = blockIdx.x >> 4;
    const int C0   = cs * 32;
    const int B0   = bg * 32;

    for (int i = tid; i < 96 * 128; i += 256) {
        int r = i >> 7, c4 = (i & 127) * 4;
        int p = r >> 5, j = r & 31;
        float4 v = *(const float4*)(Whh + (size_t)(p * NH + C0 + j) * NH + c4);
        __nv_bfloat16* d = sW + r * 520 + c4;
        d[0] = __float2bfloat16(v.x); d[1] = __float2bfloat16(v.y);
        d[2] = __float2bfloat16(v.z); d[3] = __float2bfloat16(v.w);
    }
    if (tid < 96) {
        int p = tid >> 5, j = tid & 31;
        sB[tid]      = bih[p * NH + C0 + j];
        sB[96 + tid] = bhh[p * NH + C0 + j];
    }
    for (int i = tid; i < 32 * 32; i += 256) {
        int bi = i >> 5, ci = i & 31;
        int b = B0 + bi, c = C0 + ci;
        float v = g_h[b * NH + c] + binit[c];
        g_h[b * NH + c]  = v;
        g_hb[b * NH + c] = __float2bfloat16(v);
    }
    const int smax = g_gc[B0];
    bgsync(bg);

    for (int s = 0; s < smax; s++) {
        for (int i = tid; i < 32 * 64; i += 256) {
            int r = i >> 6, c8 = (i & 63) * 8;
            *(uint4*)(sH + r * 520 + c8) =
                *(const uint4*)(g_hb + (size_t)(B0 + r) * NH + c8);
        }
        __syncthreads();
        if (warp < 6) {
            wmma::fragment<wmma::accumulator, 16, 16, 16, float> acc[2];
            wmma::fill_fragment(acc[0], 0.f);
            wmma::fill_fragment(acc[1], 0.f);
            for (int kk = 0; kk < 512; kk += 16) {
                wmma::fragment<wmma::matrix_a, 16, 16, 16, __nv_bfloat16, wmma::row_major> af[2];
                wmma::fragment<wmma::matrix_b, 16, 16, 16, __nv_bfloat16, wmma::col_major> bf;
                wmma::load_matrix_sync(af[0], sH + kk, 520);
                wmma::load_matrix_sync(af[1], sH + 16 * 520 + kk, 520);
                wmma::load_matrix_sync(bf, sW + warp * 16 * 520 + kk, 520);
                wmma::mma_sync(acc[0], af[0], bf, acc[0]);
                wmma::mma_sync(acc[1], af[1], bf, acc[1]);
            }
            wmma::store_matrix_sync(sGH + warp * 16, acc[0], 100, wmma::mem_row_major);
            wmma::store_matrix_sync(sGH + 16 * 100 + warp * 16, acc[1], 100, wmma::mem_row_major);
        }
        __syncthreads();
        for (int i = tid; i < 32 * 32; i += 256) {
            int bi = i >> 5, ci = i & 31;
            int b = B0 + bi, c = C0 + ci;
            const float* x = g_xproj + ((size_t)b * NS + s) * NH3;
            float r = sigmoidf(x[c]           + sB[ci]      + sGH[bi * 100 + ci]      + sB[96 + ci]);
            float z = sigmoidf(x[NH + c]      + sB[32 + ci] + sGH[bi * 100 + 32 + ci] + sB[96 + 32 + ci]);
            float n = tanhf(x[2 * NH + c] + sB[64 + ci] +
                            r * (sGH[bi * 100 + 64 + ci] + sB[96 + 64 + ci]));
            float hp = g_h[b * NH + c];
            float hn = (1.f - z) * n + z * hp;
            g_h[b * NH + c]  = hn;
            __nv_bfloat16 hb = __float2bfloat16(hn);
            g_hb[b * NH + c] = hb;
            g_outh_bf[((size_t)b * NS + s) * NH + c] = hb;
        }
        bgsync(bg);
    }
}

// ---------------- fused plan logits + BCE (epart in bf16) ----------------
__global__ void k_plan(const int* __restrict__ segments,
                       const float* __restrict__ b_p1,
                       const float* __restrict__ W_p2,
                       const float* __restrict__ b_p2) {
    __shared__ float s_h[NS][NE];
    __shared__ float s_w2[NE];
    __shared__ float s_b1[NE];
    __shared__ float s_warp[8];
    int t = threadIdx.x;
    int b = blockIdx.y, ltile = blockIdx.x;  // (16, B)
    for (int i = t; i < NS * NE; i += 256) s_h[i >> 9][i & 511] = g_hpart[(size_t)b * NS * NE + i];
    for (int i = t; i < NE; i += 256) { s_w2[i] = W_p2[i]; s_b1[i] = b_p1[i]; }
    __syncthreads();

    int warp = t >> 5, lane = t & 31;
    int l = ltile * 8 + warp;
    const __nv_bfloat16* ep = g_epart_bf + (size_t)(b * NL + l) * NE;
    float epr[16];
    #pragma unroll
    for (int j = 0; j < 16; j++) {
        int e = lane + 32 * j;
        epr[j] = __bfloat162float(ep[e]) + s_b1[e];
    }

    int gcb = g_gc[b];
    int p   = g_idx[b];
    float bp2 = b_p2[0];
    float local = 0.f;
    for (int s = 0; s < gcb; s++) {
        float acc = 0.f;
        #pragma unroll
        for (int j = 0; j < 16; j++) {
            int e = lane + 32 * j;
            acc += fast_tanh(s_h[s][e] + epr[j]) * s_w2[e];
        }
        #pragma unroll
        for (int off = 16; off; off >>= 1) acc += __shfl_xor_sync(0xffffffffu, acc, off);
        if (lane == 0) {
            float pl  = acc + bp2;
            float tgt = (float)segments[(p * NS + s) * NL + l];
            local += softplusf(pl) - pl * tgt;
        }
    }
    if (lane == 0) s_warp[warp] = local;
    __syncthreads();
    if (t == 0) {
        float sum = 0.f;
        #pragma unroll
        for (int w = 0; w < 8; w++) sum += s_warp[w];
        g_plan_partial[b * 16 + ltile] = sum;
    }
}

// ---------------- stop loss + final reduction (outh in bf16) ----------------
__global__ void k_final(const float* __restrict__ W_stop,
                        const float* __restrict__ b_stop,
                        float* __restrict__ out) {
    __shared__ float s_w[NH];
    __shared__ float s_stop[32];
    __shared__ float s_red[1024];
    int t = threadIdx.x;  // 1024
    for (int i = t; i < NH; i += 1024) s_w[i] = W_stop[i];
    __syncthreads();

    int warp = t >> 5, lane = t & 31;
    float stop_local = 0.f;
    for (int bs = warp; bs < NB * NS; bs += 32) {
        int b = bs / NS, s = bs % NS;
        int gcb = g_gc[b];
        if (s < gcb) {
            const __nv_bfloat16* o = g_outh_bf + (size_t)bs * NH;
            float a = 0.f;
            #pragma unroll
            for (int j = 0; j < 16; j++)
                a += __bfloat162float(o[lane + 32 * j]) * s_w[lane + 32 * j];
            #pragma unroll
            for (int off = 16; off; off >>= 1) a += __shfl_xor_sync(0xffffffffu, a, off);
            if (lane == 0) {
                float logit = a + b_stop[0];
                float label = (s == gcb - 1) ? 1.f : 0.f;
                stop_local += softplusf(logit) - logit * label;
            }
        }
    }
    if (lane == 0) s_stop[warp] = stop_local;

    s_red[t] = g_plan_partial[t] + g_plan_partial[t + 1024];
    __syncthreads();
    for (int off = 512; off; off >>= 1) {
        if (t < off) s_red[t] += s_red[t + off];
        __syncthreads();
    }
    if (t == 0) {
        float stop_sum = 0.f;
        #pragma unroll
        for (int w = 0; w < 32; w++) stop_sum += s_stop[w];
        float ms = g_mask_sum;
        out[0] = stop_sum / ms;
        out[1] = s_red[0] / (ms * (float)NL);
    }
}

// ---------------- launch: proper fork/join for graph capture ----------------
extern "C" void kernel_launch(void* const* d_in, const int* in_sizes, int n_in,
                              void* d_out, int out_size) {
    const float* enc    = (const float*)d_in[0];
    const int*   segs   = (const int*)d_in[1];
    const int*   gcnt   = (const int*)d_in[2];
    const float* ginit  = (const float*)d_in[3];
    const float* W_init = (const float*)d_in[4];
    const float* b_init = (const float*)d_in[5];
    const float* W_ih   = (const float*)d_in[6];
    const float* b_ih   = (const float*)d_in[7];
    const float* W_hh   = (const float*)d_in[8];
    const float* b_hh   = (const float*)d_in[9];
    const float* W_p1   = (const float*)d_in[10];
    const float* b_p1   = (const float*)d_in[11];
    const float* W_p2   = (const float*)d_in[12];
    const float* b_p2   = (const float*)d_in[13];
    const float* W_stop = (const float*)d_in[14];
    const float* b_stop = (const float*)d_in[15];
    float* out = (float*)d_out;

    float *p_h, *p_xproj, *p_hpart;
    __nv_bfloat16 *p_epart_bf, *p_inps_bf, *p_outh_bf, *p_enc_bf, *p_wp1_bf, *p_wih_bf,
                  *p_ginit_bf, *p_winit_bf;
    cudaGetSymbolAddress((void**)&p_h,        g_h);
    cudaGetSymbolAddress((void**)&p_xproj,    g_xproj);
    cudaGetSymbolAddress((void**)&p_hpart,    g_hpart);
    cudaGetSymbolAddress((void**)&p_epart_bf, g_epart_bf);
    cudaGetSymbolAddress((void**)&p_inps_bf,  g_inps_bf);
    cudaGetSymbolAddress((void**)&p_outh_bf,  g_outh_bf);
    cudaGetSymbolAddress((void**)&p_enc_bf,   g_enc_bf);
    cudaGetSymbolAddress((void**)&p_wp1_bf,   g_wp1_bf);
    cudaGetSymbolAddress((void**)&p_wih_bf,   g_wih_bf);
    cudaGetSymbolAddress((void**)&p_ginit_bf, g_ginit_bf);
    cudaGetSymbolAddress((void**)&p_winit_bf, g_winit_bf);

    static cudaStream_t s1 = nullptr;
    static cudaEvent_t eF = nullptr, e0 = nullptr, e1 = nullptr;
    if (!s1) {
        cudaStreamCreateWithFlags(&s1, cudaStreamNonBlocking);
        cudaEventCreateWithFlags(&eF, cudaEventDisableTiming);
        cudaEventCreateWithFlags(&e0, cudaEventDisableTiming);
        cudaEventCreateWithFlags(&e1, cudaEventDisableTiming);
        cudaFuncSetAttribute(k_gru_persist, cudaFuncAttributeMaxDynamicSharedMemorySize, 147456);
        cudaFuncSetAttribute(gemm128<float>, cudaFuncAttributeMaxDynamicSharedMemorySize, GSMEM);
        cudaFuncSetAttribute(gemm128<__nv_bfloat16>, cudaFuncAttributeMaxDynamicSharedMemorySize, GSMEM);
    }

    // ---- fork: s1 must join the capture BEFORE any s1 work ----
    cudaEventRecord(eF, 0);
    cudaStreamWaitEvent(s1, eF, 0);

    // ---- s1: weight cvts + h0 (independent of inps) ----
    k_cvt<<<(NH3 * NE2 / 4 + 255) / 256, 256, 0, s1>>>((const float4*)W_ih, (__nv_bfloat162*)p_wih_bf, NH3 * NE2 / 4);
    k_cvt<<<(NB * NKIN / 4 + 255) / 256, 256, 0, s1>>>((const float4*)ginit, (__nv_bfloat162*)p_ginit_bf, NB * NKIN / 4);
    k_cvt<<<(NH * NKIN / 4 + 255) / 256, 256, 0, s1>>>((const float4*)W_init, (__nv_bfloat162*)p_winit_bf, NH * NKIN / 4);
    gemm64_bf16<<<dim3(NH / 64, NB / 64), 128, 0, s1>>>(p_ginit_bf, NKIN, p_winit_bf, NKIN, p_h, NH, NKIN);

    // ---- s0: cvt W_p1, sort, inps -> epart ----
    k_cvt<<<(NE * NH3 / 4 + 255) / 256, 256>>>((const float4*)W_p1, (__nv_bfloat162*)p_wp1_bf, NE * NH3 / 4);
    k_sort<<<1, NB>>>(gcnt);
    k_inps<<<NB, 256>>>(enc, segs);   // -> g_inps_bf, g_enc_bf
    cudaEventRecord(e0, 0);

    // epart (bf16 out) = enc @ W1e^T  (16384 x 512, K=1024)
    gemm128<__nv_bfloat16><<<dim3(NE / 128, (NB * NL) / 128), 128, GSMEM>>>(
        p_enc_bf, NE2, p_wp1_bf + NH, NH3, p_epart_bf, NE, NE2);

    // ---- s1: xproj (needs inps) ----
    cudaStreamWaitEvent(s1, e0, 0);
    gemm128<float><<<dim3(NH3 / 128, (NB * NS) / 128), 128, GSMEM, s1>>>(
        p_inps_bf, NE2, p_wih_bf, NE2, p_xproj, NH3, NE2);
    cudaEventRecord(e1, s1);

    // ---- join on s0: GRU runs alone after epart & xproj ----
    cudaStreamWaitEvent(0, e1, 0);
    k_gru_persist<<<64, 256, 147456>>>(W_hh, b_ih, b_hh, b_init);

    // hpart = outputs @ W1h^T  (1536 x 512, K=512)
    gemm128<float><<<dim3(NE / 128, (NB * NS) / 128), 128, GSMEM>>>(
        p_outh_bf, NH, p_wp1_bf, NH3, p_hpart, NE, NH);

    k_plan<<<dim3(16, NB), 256>>>(segs, b_p1, W_p2, b_p2);
    k_final<<<1, 1024>>>(W_stop, b_stop, out);
}

// round 10
// speedup vs baseline: 1.5011x; 1.0945x over previous
// R10: re-bench of R9 (round-9 bench died to the same container/broker infra
// failure as rounds 0 and 7; R7->R8 precedent: resubmit verbatim). Logic unchanged:
// merged converts (epart = submission idx 3 for ncu), split-K h0, GRU cp.async
// prefetch of x + h with smem-resident hidden state.
#include <cuda_runtime.h>
#include <cuda_bf16.h>
#include <mma.h>
#include <cstdint>

using namespace nvcuda;

#define NB   128
#define NS   12
#define NL   128
#define NE   512
#define NE2  1024
#define NH   512
#define NH3  1536
#define NKIN 2304

// ---------------- scratch ----------------
__device__ int   g_idx[NB];
__device__ int   g_gc[NB];
__device__ float g_mask_sum;
__device__ float g_h0p[3 * NB * NH];        // split-K h0 partials
__device__ float g_xproj[NB * NS * NH3];
__device__ float g_hpart[NB * NS * NE];
__device__ float g_plan_partial[2048];
__device__ unsigned g_bg_arrive[4];
__device__ unsigned g_bg_gen[4];
// bf16 buffers
__device__ __nv_bfloat16 g_epart_bf[NB * NL * NE];
__device__ __nv_bfloat16 g_enc_bf[NB * NL * NE2];
__device__ __nv_bfloat16 g_inps_bf[NB * NS * NE2];
__device__ __nv_bfloat16 g_outh_bf[NB * NS * NH];
__device__ __nv_bfloat16 g_hb[NB * NH];
__device__ __nv_bfloat16 g_wp1_bf[NE * NH3];
__device__ __nv_bfloat16 g_wih_bf[NH3 * NE2];
__device__ __nv_bfloat16 g_ginit_bf[NB * NKIN];
__device__ __nv_bfloat16 g_winit_bf[NH * NKIN];

// ---------------- helpers ----------------
__device__ __forceinline__ float fast_tanh(float x) {
    float y; asm("tanh.approx.f32 %0, %1;" : "=f"(y) : "f"(x)); return y;
}
__device__ __forceinline__ float sigmoidf(float x) { return 1.f / (1.f + __expf(-x)); }
__device__ __forceinline__ float softplusf(float x) { return (x > 15.f) ? x : log1pf(__expf(x)); }

__device__ __forceinline__ void cp16(void* sdst, const void* gsrc) {
    uint32_t s = (uint32_t)__cvta_generic_to_shared(sdst);
    asm volatile("cp.async.cg.shared.global [%0], [%1], 16;\n" :: "r"(s), "l"(gsrc));
}
#define CP_COMMIT() asm volatile("cp.async.commit_group;\n")
#define CP_WAIT1()  asm volatile("cp.async.wait_group 1;\n")
#define CP_WAIT0()  asm volatile("cp.async.wait_group 0;\n")

__device__ __forceinline__ uint32_t bf2_bits(float a, float b) {
    __nv_bfloat162 v{__float2bfloat16(a), __float2bfloat16(b)};
    return *reinterpret_cast<uint32_t*>(&v);
}

// ---------------- single merged fp32 -> bf16 convert ----------------
// float4 ranges: W_p1 196608 | W_ih 393216 | ginit 73728 | W_init 294912 = 958464
__global__ void k_cvt_all(const float4* __restrict__ wp1, const float4* __restrict__ wih,
                          const float4* __restrict__ gin, const float4* __restrict__ win) {
    int i = blockIdx.x * 256 + threadIdx.x;
    const float4* src; __nv_bfloat162* dst; int off;
    if (i < 196608)      { src = wp1; dst = (__nv_bfloat162*)g_wp1_bf;   off = i; }
    else if (i < 589824) { src = wih; dst = (__nv_bfloat162*)g_wih_bf;   off = i - 196608; }
    else if (i < 663552) { src = gin; dst = (__nv_bfloat162*)g_ginit_bf; off = i - 589824; }
    else if (i < 958464) { src = win; dst = (__nv_bfloat162*)g_winit_bf; off = i - 663552; }
    else return;
    float4 v = src[off];
    dst[2 * off]     = __nv_bfloat162{__float2bfloat16(v.x), __float2bfloat16(v.y)};
    dst[2 * off + 1] = __nv_bfloat162{__float2bfloat16(v.z), __float2bfloat16(v.w)};
}

// ---------------- stable descending sort of group_count ----------------
__global__ void k_sort(const int* __restrict__ gc) {
    __shared__ int s_gc[NB];
    __shared__ int red[NB];
    int t = threadIdx.x;
    s_gc[t] = gc[t];
    __syncthreads();
    int my = s_gc[t];
    int rank = 0;
    #pragma unroll 8
    for (int j = 0; j < NB; j++) {
        int v = s_gc[j];
        rank += (v > my) || (v == my && j < t);
    }
    g_idx[rank] = t;
    g_gc[rank]  = my;
    red[t] = my;
    __syncthreads();
    for (int off = 64; off > 0; off >>= 1) {
        if (t < off) red[t] += red[t + off];
        __syncthreads();
    }
    if (t == 0) g_mask_sum = (float)red[0];
}

// ---------------- alpha + inps einsum (vectorized) ----------------
__global__ __launch_bounds__(256) void k_inps(const float* __restrict__ enc,
                                              const int* __restrict__ segments) {
    __shared__ float s_a[NS][NL];
    __shared__ float s_inv[NS];
    int b = blockIdx.x, t = threadIdx.x;
    int p = g_idx[b];
    for (int i = t; i < NS * NL; i += 256) {
        int s = i >> 7, l = i & 127;
        float v = 0.f;
        if (s > 0) v = (float)segments[(p * NS + (s - 1)) * NL + l];
        s_a[s][l] = v;
    }
    __syncthreads();
    if (t < NS) {
        float sum = 0.f;
        for (int l = 0; l < NL; l++) sum += s_a[t][l];
        s_inv[t] = 1.f / (sum + 1.f);
    }
    __syncthreads();
    for (int i = t; i < NS * NL; i += 256) {
        int s = i >> 7;
        s_a[s][i & 127] *= s_inv[s];
    }
    __syncthreads();

    const float* encb = enc + (size_t)b * NL * NE2;
    const int e4 = t * 4;
    float acc[NS][4];
    #pragma unroll
    for (int s = 0; s < NS; s++)
        #pragma unroll
        for (int q = 0; q < 4; q++) acc[s][q] = 0.f;

    for (int l = 0; l < NL; l++) {
        float4 v = *reinterpret_cast<const float4*>(encb + (size_t)l * NE2 + e4);
        uint2 pk{bf2_bits(v.x, v.y), bf2_bits(v.z, v.w)};
        *reinterpret_cast<uint2*>(g_enc_bf + ((size_t)b * NL + l) * NE2 + e4) = pk;
        #pragma unroll
        for (int s = 0; s < NS; s++) {
            float a = s_a[s][l];
            acc[s][0] += a * v.x; acc[s][1] += a * v.y;
            acc[s][2] += a * v.z; acc[s][3] += a * v.w;
        }
    }
    #pragma unroll
    for (int s = 0; s < NS; s++) {
        uint2 pk{bf2_bits(acc[s][0], acc[s][1]), bf2_bits(acc[s][2], acc[s][3])};
        *reinterpret_cast<uint2*>(g_inps_bf + ((size_t)b * NS + s) * NE2 + e4) = pk;
    }
}

// ---------------- bf16 GEMM: 128x128 block, 4 warps, 64x64 warp tile, 3-stage cp.async ----
#define GSTG 3
template <typename OutT>
__global__ __launch_bounds__(128) void gemm128(
    const __nv_bfloat16* __restrict__ A, int lda,
    const __nv_bfloat16* __restrict__ W, int ldw,
    OutT* __restrict__ C, int ldc, int K) {
    extern __shared__ __align__(16) __nv_bfloat16 gsm[];
    __nv_bfloat16* sA = gsm;                  // [GSTG][128][40]
    __nv_bfloat16* sW = gsm + GSTG * 128 * 40;

    const int tid  = threadIdx.x;
    const int warp = tid >> 5;
    const int lane = tid & 31;
    const int wm   = warp & 1;
    const int wn   = warp >> 1;
    const int m0   = blockIdx.y * 128;
    const int n0   = blockIdx.x * 128;
    const int nkt  = K >> 5;

    wmma::fragment<wmma::accumulator, 16, 16, 16, float> acc[4][4];
    #pragma unroll
    for (int i = 0; i < 4; i++)
        #pragma unroll
        for (int j = 0; j < 4; j++) wmma::fill_fragment(acc[i][j], 0.f);

    auto issue = [&](int kt, int st) {
        int k0 = kt << 5;
        __nv_bfloat16* a = sA + st * 128 * 40;
        __nv_bfloat16* w = sW + st * 128 * 40;
        #pragma unroll
        for (int q = 0; q < 4; q++) {
            int chunk = q * 128 + tid;
            int r  = chunk >> 2;
            int c8 = (chunk & 3) * 8;
            cp16(a + r * 40 + c8, A + (size_t)(m0 + r) * lda + k0 + c8);
            cp16(w + r * 40 + c8, W + (size_t)(n0 + r) * ldw + k0 + c8);
        }
        CP_COMMIT();
    };

    issue(0, 0);
    issue(1, 1);
    for (int kt = 0; kt < nkt; kt++) {
        int st = kt % GSTG;
        if (kt == nkt - 1) CP_WAIT0(); else CP_WAIT1();
        __syncthreads();
        if (kt + 2 < nkt) issue(kt + 2, (kt + 2) % GSTG);
        const __nv_bfloat16* a = sA + st * 128 * 40;
        const __nv_bfloat16* w = sW + st * 128 * 40;
        #pragma unroll
        for (int kk = 0; kk < 32; kk += 16) {
            wmma::fragment<wmma::matrix_a, 16, 16, 16, __nv_bfloat16, wmma::row_major> af[4];
            wmma::fragment<wmma::matrix_b, 16, 16, 16, __nv_bfloat16, wmma::col_major> bf[4];
            #pragma unroll
            for (int i = 0; i < 4; i++)
                wmma::load_matrix_sync(af[i], a + (wm * 64 + i * 16) * 40 + kk, 40);
            #pragma unroll
            for (int j = 0; j < 4; j++)
                wmma::load_matrix_sync(bf[j], w + (wn * 64 + j * 16) * 40 + kk, 40);
            #pragma unroll
            for (int i = 0; i < 4; i++)
                #pragma unroll
                for (int j = 0; j < 4; j++)
                    wmma::mma_sync(acc[i][j], af[i], bf[j], acc[i][j]);
        }
        __syncthreads();
    }

    if constexpr (sizeof(OutT) == 4) {
        #pragma unroll
        for (int i = 0; i < 4; i++)
            #pragma unroll
            for (int j = 0; j < 4; j++)
                wmma::store_matrix_sync(
                    (float*)C + (size_t)(m0 + wm * 64 + i * 16) * ldc + n0 + wn * 64 + j * 16,
                    acc[i][j], ldc, wmma::mem_row_major);
    } else {
        float* stage = reinterpret_cast<float*>(gsm) + warp * 16 * 68;
        #pragma unroll
        for (int i = 0; i < 4; i++) {
            #pragma unroll
            for (int j = 0; j < 4; j++)
                wmma::store_matrix_sync(stage + j * 16, acc[i][j], 68, wmma::mem_row_major);
            __syncwarp();
            int gr = m0 + wm * 64 + i * 16;
            int gc0 = n0 + wn * 64;
            #pragma unroll
            for (int p = 0; p < 16; p++) {
                float v0 = stage[p * 68 + lane * 2];
                float v1 = stage[p * 68 + lane * 2 + 1];
                uint32_t pk = bf2_bits(v0, v1);
                *reinterpret_cast<uint32_t*>(
                    (__nv_bfloat16*)C + (size_t)(gr + p) * ldc + gc0 + lane * 2) = pk;
            }
            __syncwarp();
        }
    }
}
#define GSMEM (GSTG * 2 * 128 * 40 * 2)   // 61440 B

// ---------------- bf16 GEMM, 64x64 tile, split-K over blockIdx.z (h0) ----------------
__global__ __launch_bounds__(128) void gemm64_splitk(
    const __nv_bfloat16* __restrict__ A, int lda,
    const __nv_bfloat16* __restrict__ W, int ldw,
    float* __restrict__ Cpart, int ldc, int Kchunk) {
    __shared__ __align__(16) __nv_bfloat16 As[2][64][40];
    __shared__ __align__(16) __nv_bfloat16 Ws[2][64][40];

    const int z = blockIdx.z;
    A += (size_t)z * Kchunk;
    W += (size_t)z * Kchunk;
    Cpart += (size_t)z * NB * NH;

    const int tid  = threadIdx.x;
    const int warp = tid >> 5;
    const int wm   = warp & 1;
    const int wn   = warp >> 1;
    const int m0   = blockIdx.y * 64;
    const int n0   = blockIdx.x * 64;
    const int nkt  = Kchunk >> 5;

    wmma::fragment<wmma::accumulator, 16, 16, 16, float> acc[2][2];
    #pragma unroll
    for (int i = 0; i < 2; i++)
        #pragma unroll
        for (int j = 0; j < 2; j++) wmma::fill_fragment(acc[i][j], 0.f);

    auto issue = [&](int kt, int st) {
        int k0 = kt << 5;
        #pragma unroll
        for (int q = 0; q < 2; q++) {
            int chunk = tid * 2 + q;
            int r  = chunk >> 2;
            int c8 = (chunk & 3) * 8;
            cp16(&As[st][r][c8], A + (size_t)(m0 + r) * lda + k0 + c8);
            cp16(&Ws[st][r][c8], W + (size_t)(n0 + r) * ldw + k0 + c8);
        }
        CP_COMMIT();
    };

    issue(0, 0);
    for (int kt = 0; kt < nkt; kt++) {
        int st = kt & 1;
        if (kt + 1 < nkt) { issue(kt + 1, st ^ 1); CP_WAIT1(); }
        else             { CP_WAIT0(); }
        __syncthreads();
        #pragma unroll
        for (int kk = 0; kk < 32; kk += 16) {
            wmma::fragment<wmma::matrix_a, 16, 16, 16, __nv_bfloat16, wmma::row_major> af[2];
            wmma::fragment<wmma::matrix_b, 16, 16, 16, __nv_bfloat16, wmma::col_major> bf[2];
            #pragma unroll
            for (int i = 0; i < 2; i++)
                wmma::load_matrix_sync(af[i], &As[st][wm * 32 + i * 16][kk], 40);
            #pragma unroll
            for (int j = 0; j < 2; j++)
                wmma::load_matrix_sync(bf[j], &Ws[st][wn * 32 + j * 16][kk], 40);
            #pragma unroll
            for (int i = 0; i < 2; i++)
                #pragma unroll
                for (int j = 0; j < 2; j++)
                    wmma::mma_sync(acc[i][j], af[i], bf[j], acc[i][j]);
        }
        __syncthreads();
    }
    #pragma unroll
    for (int i = 0; i < 2; i++)
        #pragma unroll
        for (int j = 0; j < 2; j++)
            wmma::store_matrix_sync(
                Cpart + (size_t)(m0 + wm * 32 + i * 16) * ldc + n0 + wn * 32 + j * 16,
                acc[i][j], ldc, wmma::mem_row_major);
}

// ---------------- per-batch-group barrier (16 CTAs each; proven form) ----------------
__device__ __forceinline__ void bgsync(int bg) {
    __syncthreads();
    if (threadIdx.x == 0) {
        unsigned gen;
        asm volatile("ld.acquire.gpu.u32 %0, [%1];" : "=r"(gen) : "l"(&g_bg_gen[bg]) : "memory");
        __threadfence();
        unsigned old = atomicAdd(&g_bg_arrive[bg], 1u);
        if (old == 15) {
            g_bg_arrive[bg] = 0;
            __threadfence();
            atomicAdd(&g_bg_gen[bg], 1u);
        } else {
            unsigned cur;
            do {
                __nanosleep(32);
                asm volatile("ld.acquire.gpu.u32 %0, [%1];" : "=r"(cur) : "l"(&g_bg_gen[bg]) : "memory");
            } while (cur == gen);
        }
    }
    __syncthreads();
}

// ---------------- persistent GRU scan (cp.async prefetch, smem-resident hp) ----------------
// 64 CTAs: (colslice 0..15) x (batchgroup 0..3); dyn smem 163072 B.
__global__ __launch_bounds__(256) void k_gru_persist(
    const float* __restrict__ Whh, const float* __restrict__ bih,
    const float* __restrict__ bhh, const float* __restrict__ binit) {
    extern __shared__ __align__(16) char dyn[];
    __nv_bfloat16* sW  = (__nv_bfloat16*)dyn;          // [96][520]  99840 B
    __nv_bfloat16* sH  = sW + 96 * 520;                // [32][520]  33280 B
    float*         sGH = (float*)(sH + 32 * 520);      // [32][100]  12800 B
    float*         sB  = sGH + 32 * 100;               // [192]        768 B
    float*         sX  = sB + 192;                     // [96][32]   12288 B
    float*         sHP = sX + 96 * 32;                 // [32][32]    4096 B

    const int tid  = threadIdx.x;
    const int warp = tid >> 5;
    const int cs   = blockIdx.x & 15;
    const int bg   = blockIdx.x >> 4;
    const int C0   = cs * 32;
    const int B0   = bg * 32;

    // W_hh slice rows {C0.., NH+C0.., 2NH+C0..} -> bf16 smem (once)
    for (int i = tid; i < 96 * 128; i += 256) {
        int r = i >> 7, c4 = (i & 127) * 4;
        int p = r >> 5, j = r & 31;
        float4 v = *(const float4*)(Whh + (size_t)(p * NH + C0 + j) * NH + c4);
        __nv_bfloat16* d = sW + r * 520 + c4;
        d[0] = __float2bfloat16(v.x); d[1] = __float2bfloat16(v.y);
        d[2] = __float2bfloat16(v.z); d[3] = __float2bfloat16(v.w);
    }
    if (tid < 96) {
        int p = tid >> 5, j = tid & 31;
        sB[tid]      = bih[p * NH + C0 + j];
        sB[96 + tid] = bhh[p * NH + C0 + j];
    }
    // h0 = sum of 3 split-K partials + b_init; keep fp32 in smem, publish bf16
    for (int i = tid; i < 32 * 32; i += 256) {
        int bi = i >> 5, ci = i & 31;
        int gi = (B0 + bi) * NH + C0 + ci;
        float v = g_h0p[gi] + g_h0p[NB * NH + gi] + g_h0p[2 * NB * NH + gi] + binit[C0 + ci];
        sHP[i] = v;
        g_hb[gi] = __float2bfloat16(v);
    }
    const int smax = g_gc[B0];   // sorted desc -> max for this batch group
    bgsync(bg);

    for (int s = 0; s < smax; s++) {
        // group A: full h (bf16) for our 32 batches -> sH
        #pragma unroll
        for (int q = 0; q < 8; q++) {
            int idx = q * 256 + tid;          // 0..2047
            int r = idx >> 6, c8 = (idx & 63) * 8;
            cp16(sH + r * 520 + c8, g_hb + (size_t)(B0 + r) * NH + c8);
        }
        CP_COMMIT();
        // group B: xproj slice (32 batches x 3 gates x 32 cols) -> sX
        #pragma unroll
        for (int q = 0; q < 3; q++) {
            int idx = q * 256 + tid;          // 0..767
            int seg = idx >> 3;               // 0..95 = bi*3+p
            int f   = (idx & 7) * 4;
            int bb  = seg / 3, p = seg - bb * 3;
            cp16(sX + seg * 32 + f,
                 g_xproj + ((size_t)(B0 + bb) * NS + s) * NH3 + p * NH + C0 + f);
        }
        CP_COMMIT();
        CP_WAIT1();      // sH complete (own chunks)
        __syncthreads(); // all threads' sH chunks visible
        if (warp < 6) {
            wmma::fragment<wmma::accumulator, 16, 16, 16, float> acc[2];
            wmma::fill_fragment(acc[0], 0.f);
            wmma::fill_fragment(acc[1], 0.f);
            for (int kk = 0; kk < 512; kk += 16) {
                wmma::fragment<wmma::matrix_a, 16, 16, 16, __nv_bfloat16, wmma::row_major> af[2];
                wmma::fragment<wmma::matrix_b, 16, 16, 16, __nv_bfloat16, wmma::col_major> bf;
                wmma::load_matrix_sync(af[0], sH + kk, 520);
                wmma::load_matrix_sync(af[1], sH + 16 * 520 + kk, 520);
                wmma::load_matrix_sync(bf, sW + warp * 16 * 520 + kk, 520);
                wmma::mma_sync(acc[0], af[0], bf, acc[0]);
                wmma::mma_sync(acc[1], af[1], bf, acc[1]);
            }
            wmma::store_matrix_sync(sGH + warp * 16, acc[0], 100, wmma::mem_row_major);
            wmma::store_matrix_sync(sGH + 16 * 100 + warp * 16, acc[1], 100, wmma::mem_row_major);
        }
        CP_WAIT0();      // sX complete
        __syncthreads(); // sGH + sX visible to all
        for (int i = tid; i < 32 * 32; i += 256) {
            int bi = i >> 5, ci = i & 31;
            float r = sigmoidf(sX[(bi * 3 + 0) * 32 + ci] + sB[ci] +
                               sGH[bi * 100 + ci] + sB[96 + ci]);
            float z = sigmoidf(sX[(bi * 3 + 1) * 32 + ci] + sB[32 + ci] +
                               sGH[bi * 100 + 32 + ci] + sB[96 + 32 + ci]);
            float n = tanhf(sX[(bi * 3 + 2) * 32 + ci] + sB[64 + ci] +
                            r * (sGH[bi * 100 + 64 + ci] + sB[96 + 64 + ci]));
            float hp = sHP[i];
            float hn = (1.f - z) * n + z * hp;
            sHP[i] = hn;
            __nv_bfloat16 hb = __float2bfloat16(hn);
            int gi = (B0 + bi) * NH + C0 + ci;
            g_hb[gi] = hb;
            g_outh_bf[((size_t)(B0 + bi) * NS + s) * NH + C0 + ci] = hb;
        }
        bgsync(bg);
    }
}
#define GRUSMEM 163072

// ---------------- fused plan logits + BCE (epart in bf16) ----------------
__global__ void k_plan(const int* __restrict__ segments,
                       const float* __restrict__ b_p1,
                       const float* __restrict__ W_p2,
                       const float* __restrict__ b_p2) {
    __shared__ float s_h[NS][NE];
    __shared__ float s_w2[NE];
    __shared__ float s_b1[NE];
    __shared__ float s_warp[8];
    int t = threadIdx.x;
    int b = blockIdx.y, ltile = blockIdx.x;  // (16, B)
    for (int i = t; i < NS * NE; i += 256) s_h[i >> 9][i & 511] = g_hpart[(size_t)b * NS * NE + i];
    for (int i = t; i < NE; i += 256) { s_w2[i] = W_p2[i]; s_b1[i] = b_p1[i]; }
    __syncthreads();

    int warp = t >> 5, lane = t & 31;
    int l = ltile * 8 + warp;
    const __nv_bfloat16* ep = g_epart_bf + (size_t)(b * NL + l) * NE;
    float epr[16];
    #pragma unroll
    for (int j = 0; j < 16; j++) {
        int e = lane + 32 * j;
        epr[j] = __bfloat162float(ep[e]) + s_b1[e];
    }

    int gcb = g_gc[b];
    int p   = g_idx[b];
    float bp2 = b_p2[0];
    float local = 0.f;
    for (int s = 0; s < gcb; s++) {
        float acc = 0.f;
        #pragma unroll
        for (int j = 0; j < 16; j++) {
            int e = lane + 32 * j;
            acc += fast_tanh(s_h[s][e] + epr[j]) * s_w2[e];
        }
        #pragma unroll
        for (int off = 16; off; off >>= 1) acc += __shfl_xor_sync(0xffffffffu, acc, off);
        if (lane == 0) {
            float pl  = acc + bp2;
            float tgt = (float)segments[(p * NS + s) * NL + l];
            local += softplusf(pl) - pl * tgt;
        }
    }
    if (lane == 0) s_warp[warp] = local;
    __syncthreads();
    if (t == 0) {
        float sum = 0.f;
        #pragma unroll
        for (int w = 0; w < 8; w++) sum += s_warp[w];
        g_plan_partial[b * 16 + ltile] = sum;
    }
}

// ---------------- stop loss + final reduction (outh in bf16) ----------------
__global__ void k_final(const float* __restrict__ W_stop,
                        const float* __restrict__ b_stop,
                        float* __restrict__ out) {
    __shared__ float s_w[NH];
    __shared__ float s_stop[32];
    __shared__ float s_red[1024];
    int t = threadIdx.x;  // 1024
    for (int i = t; i < NH; i += 1024) s_w[i] = W_stop[i];
    __syncthreads();

    int warp = t >> 5, lane = t & 31;
    float stop_local = 0.f;
    for (int bs = warp; bs < NB * NS; bs += 32) {
        int b = bs / NS, s = bs % NS;
        int gcb = g_gc[b];
        if (s < gcb) {
            const __nv_bfloat16* o = g_outh_bf + (size_t)bs * NH;
            float a = 0.f;
            #pragma unroll
            for (int j = 0; j < 16; j++)
                a += __bfloat162float(o[lane + 32 * j]) * s_w[lane + 32 * j];
            #pragma unroll
            for (int off = 16; off; off >>= 1) a += __shfl_xor_sync(0xffffffffu, a, off);
            if (lane == 0) {
                float logit = a + b_stop[0];
                float label = (s == gcb - 1) ? 1.f : 0.f;
                stop_local += softplusf(logit) - logit * label;
            }
        }
    }
    if (lane == 0) s_stop[warp] = stop_local;

    s_red[t] = g_plan_partial[t] + g_plan_partial[t + 1024];
    __syncthreads();
    for (int off = 512; off; off >>= 1) {
        if (t < off) s_red[t] += s_red[t + off];
        __syncthreads();
    }
    if (t == 0) {
        float stop_sum = 0.f;
        #pragma unroll
        for (int w = 0; w < 32; w++) stop_sum += s_stop[w];
        float ms = g_mask_sum;
        out[0] = stop_sum / ms;
        out[1] = s_red[0] / (ms * (float)NL);
    }
}

// ---------------- launch ----------------
extern "C" void kernel_launch(void* const* d_in, const int* in_sizes, int n_in,
                              void* d_out, int out_size) {
    const float* enc    = (const float*)d_in[0];
    const int*   segs   = (const int*)d_in[1];
    const int*   gcnt   = (const int*)d_in[2];
    const float* ginit  = (const float*)d_in[3];
    const float* W_init = (const float*)d_in[4];
    const float* b_init = (const float*)d_in[5];
    const float* W_ih   = (const float*)d_in[6];
    const float* b_ih   = (const float*)d_in[7];
    const float* W_hh   = (const float*)d_in[8];
    const float* b_hh   = (const float*)d_in[9];
    const float* W_p1   = (const float*)d_in[10];
    const float* b_p1   = (const float*)d_in[11];
    const float* W_p2   = (const float*)d_in[12];
    const float* b_p2   = (const float*)d_in[13];
    const float* W_stop = (const float*)d_in[14];
    const float* b_stop = (const float*)d_in[15];
    float* out = (float*)d_out;

    float *p_h0p, *p_xproj, *p_hpart;
    __nv_bfloat16 *p_epart_bf, *p_inps_bf, *p_outh_bf, *p_enc_bf, *p_wp1_bf, *p_wih_bf,
                  *p_ginit_bf, *p_winit_bf;
    cudaGetSymbolAddress((void**)&p_h0p,      g_h0p);
    cudaGetSymbolAddress((void**)&p_xproj,    g_xproj);
    cudaGetSymbolAddress((void**)&p_hpart,    g_hpart);
    cudaGetSymbolAddress((void**)&p_epart_bf, g_epart_bf);
    cudaGetSymbolAddress((void**)&p_inps_bf,  g_inps_bf);
    cudaGetSymbolAddress((void**)&p_outh_bf,  g_outh_bf);
    cudaGetSymbolAddress((void**)&p_enc_bf,   g_enc_bf);
    cudaGetSymbolAddress((void**)&p_wp1_bf,   g_wp1_bf);
    cudaGetSymbolAddress((void**)&p_wih_bf,   g_wih_bf);
    cudaGetSymbolAddress((void**)&p_ginit_bf, g_ginit_bf);
    cudaGetSymbolAddress((void**)&p_winit_bf, g_winit_bf);

    static cudaStream_t s1 = nullptr;
    static cudaEvent_t eC = nullptr, eI = nullptr, e1 = nullptr;
    if (!s1) {
        cudaStreamCreateWithFlags(&s1, cudaStreamNonBlocking);
        cudaEventCreateWithFlags(&eC, cudaEventDisableTiming);
        cudaEventCreateWithFlags(&eI, cudaEventDisableTiming);
        cudaEventCreateWithFlags(&e1, cudaEventDisableTiming);
        cudaFuncSetAttribute(k_gru_persist, cudaFuncAttributeMaxDynamicSharedMemorySize, GRUSMEM);
        cudaFuncSetAttribute(gemm128<float>, cudaFuncAttributeMaxDynamicSharedMemorySize, GSMEM);
        cudaFuncSetAttribute(gemm128<__nv_bfloat16>, cudaFuncAttributeMaxDynamicSharedMemorySize, GSMEM);
    }

    // ---- s0: merged cvt(0), sort(1), inps(2), epart(3 = ncu capture target) ----
    k_cvt_all<<<3744, 256>>>((const float4*)W_p1, (const float4*)W_ih,
                             (const float4*)ginit, (const float4*)W_init);
    cudaEventRecord(eC, 0);
    k_sort<<<1, NB>>>(gcnt);
    k_inps<<<NB, 256>>>(enc, segs);
    cudaEventRecord(eI, 0);
    gemm128<__nv_bfloat16><<<dim3(NE / 128, (NB * NL) / 128), 128, GSMEM>>>(
        p_enc_bf, NE2, p_wp1_bf + NH, NH3, p_epart_bf, NE, NE2);

    // ---- s1 (joins capture via eC): h0 split-K, then xproj after inps ----
    cudaStreamWaitEvent(s1, eC, 0);
    gemm64_splitk<<<dim3(NH / 64, NB / 64, 3), 128, 0, s1>>>(
        p_ginit_bf, NKIN, p_winit_bf, NKIN, p_h0p, NH, NKIN / 3);
    cudaStreamWaitEvent(s1, eI, 0);
    gemm128<float><<<dim3(NH3 / 128, (NB * NS) / 128), 128, GSMEM, s1>>>(
        p_inps_bf, NE2, p_wih_bf, NE2, p_xproj, NH3, NE2);
    cudaEventRecord(e1, s1);

    // ---- join on s0: GRU runs alone after epart & xproj ----
    cudaStreamWaitEvent(0, e1, 0);
    k_gru_persist<<<64, 256, GRUSMEM>>>(W_hh, b_ih, b_hh, b_init);

    // hpart = outputs @ W1h^T  (1536 x 512, K=512)
    gemm128<float><<<dim3(NE / 128, (NB * NS) / 128), 128, GSMEM>>>(
        p_outh_bf, NH, p_wp1_bf, NH3, p_hpart, NE, NH);

    k_plan<<<dim3(16, NB), 256>>>(segs, b_p1, W_p2, b_p2);
    k_final<<<1, 1024>>>(W_stop, b_stop, out);
}

// round 11
// speedup vs baseline: 1.5537x; 1.0350x over previous
// R11: gemm128 BK=64 (half the syncs per K, 3-stage 110.6KB smem) + cvt_all moved
// off the critical path (s0: sort->inps->epart, s1: cvt->h0->xproj).
#include <cuda_runtime.h>
#include <cuda_bf16.h>
#include <mma.h>
#include <cstdint>

using namespace nvcuda;

#define NB   128
#define NS   12
#define NL   128
#define NE   512
#define NE2  1024
#define NH   512
#define NH3  1536
#define NKIN 2304

// ---------------- scratch ----------------
__device__ int   g_idx[NB];
__device__ int   g_gc[NB];
__device__ float g_mask_sum;
__device__ float g_h0p[3 * NB * NH];
__device__ float g_xproj[NB * NS * NH3];
__device__ float g_hpart[NB * NS * NE];
__device__ float g_plan_partial[2048];
__device__ unsigned g_bg_arrive[4];
__device__ unsigned g_bg_gen[4];
// bf16 buffers
__device__ __nv_bfloat16 g_epart_bf[NB * NL * NE];
__device__ __nv_bfloat16 g_enc_bf[NB * NL * NE2];
__device__ __nv_bfloat16 g_inps_bf[NB * NS * NE2];
__device__ __nv_bfloat16 g_outh_bf[NB * NS * NH];
__device__ __nv_bfloat16 g_hb[NB * NH];
__device__ __nv_bfloat16 g_wp1_bf[NE * NH3];
__device__ __nv_bfloat16 g_wih_bf[NH3 * NE2];
__device__ __nv_bfloat16 g_ginit_bf[NB * NKIN];
__device__ __nv_bfloat16 g_winit_bf[NH * NKIN];

// ---------------- helpers ----------------
__device__ __forceinline__ float fast_tanh(float x) {
    float y; asm("tanh.approx.f32 %0, %1;" : "=f"(y) : "f"(x)); return y;
}
__device__ __forceinline__ float sigmoidf(float x) { return 1.f / (1.f + __expf(-x)); }
__device__ __forceinline__ float softplusf(float x) { return (x > 15.f) ? x : log1pf(__expf(x)); }

__device__ __forceinline__ void cp16(void* sdst, const void* gsrc) {
    uint32_t s = (uint32_t)__cvta_generic_to_shared(sdst);
    asm volatile("cp.async.cg.shared.global [%0], [%1], 16;\n" :: "r"(s), "l"(gsrc));
}
#define CP_COMMIT() asm volatile("cp.async.commit_group;\n")
#define CP_WAIT1()  asm volatile("cp.async.wait_group 1;\n")
#define CP_WAIT0()  asm volatile("cp.async.wait_group 0;\n")

__device__ __forceinline__ uint32_t bf2_bits(float a, float b) {
    __nv_bfloat162 v{__float2bfloat16(a), __float2bfloat16(b)};
    return *reinterpret_cast<uint32_t*>(&v);
}

// ---------------- single merged fp32 -> bf16 convert ----------------
__global__ void k_cvt_all(const float4* __restrict__ wp1, const float4* __restrict__ wih,
                          const float4* __restrict__ gin, const float4* __restrict__ win) {
    int i = blockIdx.x * 256 + threadIdx.x;
    const float4* src; __nv_bfloat162* dst; int off;
    if (i < 196608)      { src = wp1; dst = (__nv_bfloat162*)g_wp1_bf;   off = i; }
    else if (i < 589824) { src = wih; dst = (__nv_bfloat162*)g_wih_bf;   off = i - 196608; }
    else if (i < 663552) { src = gin; dst = (__nv_bfloat162*)g_ginit_bf; off = i - 589824; }
    else if (i < 958464) { src = win; dst = (__nv_bfloat162*)g_winit_bf; off = i - 663552; }
    else return;
    float4 v = src[off];
    dst[2 * off]     = __nv_bfloat162{__float2bfloat16(v.x), __float2bfloat16(v.y)};
    dst[2 * off + 1] = __nv_bfloat162{__float2bfloat16(v.z), __float2bfloat16(v.w)};
}

// ---------------- stable descending sort of group_count ----------------
__global__ void k_sort(const int* __restrict__ gc) {
    __shared__ int s_gc[NB];
    __shared__ int red[NB];
    int t = threadIdx.x;
    s_gc[t] = gc[t];
    __syncthreads();
    int my = s_gc[t];
    int rank = 0;
    #pragma unroll 8
    for (int j = 0; j < NB; j++) {
        int v = s_gc[j];
        rank += (v > my) || (v == my && j < t);
    }
    g_idx[rank] = t;
    g_gc[rank]  = my;
    red[t] = my;
    __syncthreads();
    for (int off = 64; off > 0; off >>= 1) {
        if (t < off) red[t] += red[t + off];
        __syncthreads();
    }
    if (t == 0) g_mask_sum = (float)red[0];
}

// ---------------- alpha + inps einsum (vectorized) ----------------
__global__ __launch_bounds__(256) void k_inps(const float* __restrict__ enc,
                                              const int* __restrict__ segments) {
    __shared__ float s_a[NS][NL];
    __shared__ float s_inv[NS];
    int b = blockIdx.x, t = threadIdx.x;
    int p = g_idx[b];
    for (int i = t; i < NS * NL; i += 256) {
        int s = i >> 7, l = i & 127;
        float v = 0.f;
        if (s > 0) v = (float)segments[(p * NS + (s - 1)) * NL + l];
        s_a[s][l] = v;
    }
    __syncthreads();
    if (t < NS) {
        float sum = 0.f;
        for (int l = 0; l < NL; l++) sum += s_a[t][l];
        s_inv[t] = 1.f / (sum + 1.f);
    }
    __syncthreads();
    for (int i = t; i < NS * NL; i += 256) {
        int s = i >> 7;
        s_a[s][i & 127] *= s_inv[s];
    }
    __syncthreads();

    const float* encb = enc + (size_t)b * NL * NE2;
    const int e4 = t * 4;
    float acc[NS][4];
    #pragma unroll
    for (int s = 0; s < NS; s++)
        #pragma unroll
        for (int q = 0; q < 4; q++) acc[s][q] = 0.f;

    for (int l = 0; l < NL; l++) {
        float4 v = *reinterpret_cast<const float4*>(encb + (size_t)l * NE2 + e4);
        uint2 pk{bf2_bits(v.x, v.y), bf2_bits(v.z, v.w)};
        *reinterpret_cast<uint2*>(g_enc_bf + ((size_t)b * NL + l) * NE2 + e4) = pk;
        #pragma unroll
        for (int s = 0; s < NS; s++) {
            float a = s_a[s][l];
            acc[s][0] += a * v.x; acc[s][1] += a * v.y;
            acc[s][2] += a * v.z; acc[s][3] += a * v.w;
        }
    }
    #pragma unroll
    for (int s = 0; s < NS; s++) {
        uint2 pk{bf2_bits(acc[s][0], acc[s][1]), bf2_bits(acc[s][2], acc[s][3])};
        *reinterpret_cast<uint2*>(g_inps_bf + ((size_t)b * NS + s) * NE2 + e4) = pk;
    }
}

// ---------------- bf16 GEMM: 128x128 block, 4 warps, 64x64 warp tile, BK=64, 3-stage ----
#define GSTG 3
#define GLDS 72   // BK(64) + 8 pad, halves
template <typename OutT>
__global__ __launch_bounds__(128) void gemm128(
    const __nv_bfloat16* __restrict__ A, int lda,
    const __nv_bfloat16* __restrict__ W, int ldw,
    OutT* __restrict__ C, int ldc, int K) {
    extern __shared__ __align__(16) __nv_bfloat16 gsm[];
    __nv_bfloat16* sA = gsm;                        // [GSTG][128][GLDS]
    __nv_bfloat16* sW = gsm + GSTG * 128 * GLDS;

    const int tid  = threadIdx.x;
    const int warp = tid >> 5;
    const int lane = tid & 31;
    const int wm   = warp & 1;
    const int wn   = warp >> 1;
    const int m0   = blockIdx.y * 128;
    const int n0   = blockIdx.x * 128;
    const int nkt  = K >> 6;

    wmma::fragment<wmma::accumulator, 16, 16, 16, float> acc[4][4];
    #pragma unroll
    for (int i = 0; i < 4; i++)
        #pragma unroll
        for (int j = 0; j < 4; j++) wmma::fill_fragment(acc[i][j], 0.f);

    auto issue = [&](int kt, int st) {
        int k0 = kt << 6;
        __nv_bfloat16* a = sA + st * 128 * GLDS;
        __nv_bfloat16* w = sW + st * 128 * GLDS;
        #pragma unroll
        for (int q = 0; q < 8; q++) {
            int chunk = q * 128 + tid;        // 0..1023
            int r  = chunk >> 3;              // 0..127
            int c8 = (chunk & 7) * 8;         // 0..56
            cp16(a + r * GLDS + c8, A + (size_t)(m0 + r) * lda + k0 + c8);
            cp16(w + r * GLDS + c8, W + (size_t)(n0 + r) * ldw + k0 + c8);
        }
        CP_COMMIT();
    };

    issue(0, 0);
    issue(1, 1);
    for (int kt = 0; kt < nkt; kt++) {
        int st = kt % GSTG;
        if (kt == nkt - 1) CP_WAIT0(); else CP_WAIT1();
        __syncthreads();
        if (kt + 2 < nkt) issue(kt + 2, (kt + 2) % GSTG);
        const __nv_bfloat16* a = sA + st * 128 * GLDS;
        const __nv_bfloat16* w = sW + st * 128 * GLDS;
        #pragma unroll
        for (int kk = 0; kk < 64; kk += 16) {
            wmma::fragment<wmma::matrix_a, 16, 16, 16, __nv_bfloat16, wmma::row_major> af[4];
            wmma::fragment<wmma::matrix_b, 16, 16, 16, __nv_bfloat16, wmma::col_major> bf[4];
            #pragma unroll
            for (int i = 0; i < 4; i++)
                wmma::load_matrix_sync(af[i], a + (wm * 64 + i * 16) * GLDS + kk, GLDS);
            #pragma unroll
            for (int j = 0; j < 4; j++)
                wmma::load_matrix_sync(bf[j], w + (wn * 64 + j * 16) * GLDS + kk, GLDS);
            #pragma unroll
            for (int i = 0; i < 4; i++)
                #pragma unroll
                for (int j = 0; j < 4; j++)
                    wmma::mma_sync(acc[i][j], af[i], bf[j], acc[i][j]);
        }
        __syncthreads();
    }

    if constexpr (sizeof(OutT) == 4) {
        #pragma unroll
        for (int i = 0; i < 4; i++)
            #pragma unroll
            for (int j = 0; j < 4; j++)
                wmma::store_matrix_sync(
                    (float*)C + (size_t)(m0 + wm * 64 + i * 16) * ldc + n0 + wn * 64 + j * 16,
                    acc[i][j], ldc, wmma::mem_row_major);
    } else {
        float* stage = reinterpret_cast<float*>(gsm) + warp * 16 * 68;
        #pragma unroll
        for (int i = 0; i < 4; i++) {
            #pragma unroll
            for (int j = 0; j < 4; j++)
                wmma::store_matrix_sync(stage + j * 16, acc[i][j], 68, wmma::mem_row_major);
            __syncwarp();
            int gr = m0 + wm * 64 + i * 16;
            int gc0 = n0 + wn * 64;
            #pragma unroll
            for (int p = 0; p < 16; p++) {
                float v0 = stage[p * 68 + lane * 2];
                float v1 = stage[p * 68 + lane * 2 + 1];
                uint32_t pk = bf2_bits(v0, v1);
                *reinterpret_cast<uint32_t*>(
                    (__nv_bfloat16*)C + (size_t)(gr + p) * ldc + gc0 + lane * 2) = pk;
            }
            __syncwarp();
        }
    }
}
#define GSMEM (GSTG * 2 * 128 * GLDS * 2)   // 110592 B

// ---------------- bf16 GEMM, 64x64 tile, split-K over blockIdx.z (h0) ----------------
__global__ __launch_bounds__(128) void gemm64_splitk(
    const __nv_bfloat16* __restrict__ A, int lda,
    const __nv_bfloat16* __restrict__ W, int ldw,
    float* __restrict__ Cpart, int ldc, int Kchunk) {
    __shared__ __align__(16) __nv_bfloat16 As[2][64][40];
    __shared__ __align__(16) __nv_bfloat16 Ws[2][64][40];

    const int z = blockIdx.z;
    A += (size_t)z * Kchunk;
    W += (size_t)z * Kchunk;
    Cpart += (size_t)z * NB * NH;

    const int tid  = threadIdx.x;
    const int warp = tid >> 5;
    const int wm   = warp & 1;
    const int wn   = warp >> 1;
    const int m0   = blockIdx.y * 64;
    const int n0   = blockIdx.x * 64;
    const int nkt  = Kchunk >> 5;

    wmma::fragment<wmma::accumulator, 16, 16, 16, float> acc[2][2];
    #pragma unroll
    for (int i = 0; i < 2; i++)
        #pragma unroll
        for (int j = 0; j < 2; j++) wmma::fill_fragment(acc[i][j], 0.f);

    auto issue = [&](int kt, int st) {
        int k0 = kt << 5;
        #pragma unroll
        for (int q = 0; q < 2; q++) {
            int chunk = tid * 2 + q;
            int r  = chunk >> 2;
            int c8 = (chunk & 3) * 8;
            cp16(&As[st][r][c8], A + (size_t)(m0 + r) * lda + k0 + c8);
            cp16(&Ws[st][r][c8], W + (size_t)(n0 + r) * ldw + k0 + c8);
        }
        CP_COMMIT();
    };

    issue(0, 0);
    for (int kt = 0; kt < nkt; kt++) {
        int st = kt & 1;
        if (kt + 1 < nkt) { issue(kt + 1, st ^ 1); CP_WAIT1(); }
        else             { CP_WAIT0(); }
        __syncthreads();
        #pragma unroll
        for (int kk = 0; kk < 32; kk += 16) {
            wmma::fragment<wmma::matrix_a, 16, 16, 16, __nv_bfloat16, wmma::row_major> af[2];
            wmma::fragment<wmma::matrix_b, 16, 16, 16, __nv_bfloat16, wmma::col_major> bf[2];
            #pragma unroll
            for (int i = 0; i < 2; i++)
                wmma::load_matrix_sync(af[i], &As[st][wm * 32 + i * 16][kk], 40);
            #pragma unroll
            for (int j = 0; j < 2; j++)
                wmma::load_matrix_sync(bf[j], &Ws[st][wn * 32 + j * 16][kk], 40);
            #pragma unroll
            for (int i = 0; i < 2; i++)
                #pragma unroll
                for (int j = 0; j < 2; j++)
                    wmma::mma_sync(acc[i][j], af[i], bf[j], acc[i][j]);
        }
        __syncthreads();
    }
    #pragma unroll
    for (int i = 0; i < 2; i++)
        #pragma unroll
        for (int j = 0; j < 2; j++)
            wmma::store_matrix_sync(
                Cpart + (size_t)(m0 + wm * 32 + i * 16) * ldc + n0 + wn * 32 + j * 16,
                acc[i][j], ldc, wmma::mem_row_major);
}

// ---------------- per-batch-group barrier ----------------
__device__ __forceinline__ void bgsync(int bg) {
    __syncthreads();
    if (threadIdx.x == 0) {
        unsigned gen;
        asm volatile("ld.acquire.gpu.u32 %0, [%1];" : "=r"(gen) : "l"(&g_bg_gen[bg]) : "memory");
        __threadfence();
        unsigned old = atomicAdd(&g_bg_arrive[bg], 1u);
        if (old == 15) {
            g_bg_arrive[bg] = 0;
            __threadfence();
            atomicAdd(&g_bg_gen[bg], 1u);
        } else {
            unsigned cur;
            do {
                __nanosleep(32);
                asm volatile("ld.acquire.gpu.u32 %0, [%1];" : "=r"(cur) : "l"(&g_bg_gen[bg]) : "memory");
            } while (cur == gen);
        }
    }
    __syncthreads();
}

// ---------------- persistent GRU scan ----------------
__global__ __launch_bounds__(256) void k_gru_persist(
    const float* __restrict__ Whh, const float* __restrict__ bih,
    const float* __restrict__ bhh, const float* __restrict__ binit) {
    extern __shared__ __align__(16) char dyn[];
    __nv_bfloat16* sW  = (__nv_bfloat16*)dyn;          // [96][520]
    __nv_bfloat16* sH  = sW + 96 * 520;                // [32][520]
    float*         sGH = (float*)(sH + 32 * 520);      // [32][100]
    float*         sB  = sGH + 32 * 100;               // [192]
    float*         sX  = sB + 192;                     // [96][32]
    float*         sHP = sX + 96 * 32;                 // [32][32]

    const int tid  = threadIdx.x;
    const int warp = tid >> 5;
    const int cs   = blockIdx.x & 15;
    const int bg   = blockIdx.x >> 4;
    const int C0   = cs * 32;
    const int B0   = bg * 32;

    for (int i = tid; i < 96 * 128; i += 256) {
        int r = i >> 7, c4 = (i & 127) * 4;
        int p = r >> 5, j = r & 31;
        float4 v = *(const float4*)(Whh + (size_t)(p * NH + C0 + j) * NH + c4);
        __nv_bfloat16* d = sW + r * 520 + c4;
        d[0] = __float2bfloat16(v.x); d[1] = __float2bfloat16(v.y);
        d[2] = __float2bfloat16(v.z); d[3] = __float2bfloat16(v.w);
    }
    if (tid < 96) {
        int p = tid >> 5, j = tid & 31;
        sB[tid]      = bih[p * NH + C0 + j];
        sB[96 + tid] = bhh[p * NH + C0 + j];
    }
    for (int i = tid; i < 32 * 32; i += 256) {
        int bi = i >> 5, ci = i & 31;
        int gi = (B0 + bi) * NH + C0 + ci;
        float v = g_h0p[gi] + g_h0p[NB * NH + gi] + g_h0p[2 * NB * NH + gi] + binit[C0 + ci];
        sHP[i] = v;
        g_hb[gi] = __float2bfloat16(v);
    }
    const int smax = g_gc[B0];
    bgsync(bg);

    for (int s = 0; s < smax; s++) {
        #pragma unroll
        for (int q = 0; q < 8; q++) {
            int idx = q * 256 + tid;
            int r = idx >> 6, c8 = (idx & 63) * 8;
            cp16(sH + r * 520 + c8, g_hb + (size_t)(B0 + r) * NH + c8);
        }
        CP_COMMIT();
        #pragma unroll
        for (int q = 0; q < 3; q++) {
            int idx = q * 256 + tid;
            int seg = idx >> 3;
            int f   = (idx & 7) * 4;
            int bb  = seg / 3, p = seg - bb * 3;
            cp16(sX + seg * 32 + f,
                 g_xproj + ((size_t)(B0 + bb) * NS + s) * NH3 + p * NH + C0 + f);
        }
        CP_COMMIT();
        CP_WAIT1();
        __syncthreads();
        if (warp < 6) {
            wmma::fragment<wmma::accumulator, 16, 16, 16, float> acc[2];
            wmma::fill_fragment(acc[0], 0.f);
            wmma::fill_fragment(acc[1], 0.f);
            for (int kk = 0; kk < 512; kk += 16) {
                wmma::fragment<wmma::matrix_a, 16, 16, 16, __nv_bfloat16, wmma::row_major> af[2];
                wmma::fragment<wmma::matrix_b, 16, 16, 16, __nv_bfloat16, wmma::col_major> bf;
                wmma::load_matrix_sync(af[0], sH + kk, 520);
                wmma::load_matrix_sync(af[1], sH + 16 * 520 + kk, 520);
                wmma::load_matrix_sync(bf, sW + warp * 16 * 520 + kk, 520);
                wmma::mma_sync(acc[0], af[0], bf, acc[0]);
                wmma::mma_sync(acc[1], af[1], bf, acc[1]);
            }
            wmma::store_matrix_sync(sGH + warp * 16, acc[0], 100, wmma::mem_row_major);
            wmma::store_matrix_sync(sGH + 16 * 100 + warp * 16, acc[1], 100, wmma::mem_row_major);
        }
        CP_WAIT0();
        __syncthreads();
        for (int i = tid; i < 32 * 32; i += 256) {
            int bi = i >> 5, ci = i & 31;
            float r = sigmoidf(sX[(bi * 3 + 0) * 32 + ci] + sB[ci] +
                               sGH[bi * 100 + ci] + sB[96 + ci]);
            float z = sigmoidf(sX[(bi * 3 + 1) * 32 + ci] + sB[32 + ci] +
                               sGH[bi * 100 + 32 + ci] + sB[96 + 32 + ci]);
            float n = tanhf(sX[(bi * 3 + 2) * 32 + ci] + sB[64 + ci] +
                            r * (sGH[bi * 100 + 64 + ci] + sB[96 + 64 + ci]));
            float hp = sHP[i];
            float hn = (1.f - z) * n + z * hp;
            sHP[i] = hn;
            __nv_bfloat16 hb = __float2bfloat16(hn);
            int gi = (B0 + bi) * NH + C0 + ci;
            g_hb[gi] = hb;
            g_outh_bf[((size_t)(B0 + bi) * NS + s) * NH + C0 + ci] = hb;
        }
        bgsync(bg);
    }
}
#define GRUSMEM 163072

// ---------------- fused plan logits + BCE ----------------
__global__ void k_plan(const int* __restrict__ segments,
                       const float* __restrict__ b_p1,
                       const float* __restrict__ W_p2,
                       const float* __restrict__ b_p2) {
    __shared__ float s_h[NS][NE];
    __shared__ float s_w2[NE];
    __shared__ float s_b1[NE];
    __shared__ float s_warp[8];
    int t = threadIdx.x;
    int b = blockIdx.y, ltile = blockIdx.x;
    for (int i = t; i < NS * NE; i += 256) s_h[i >> 9][i & 511] = g_hpart[(size_t)b * NS * NE + i];
    for (int i = t; i < NE; i += 256) { s_w2[i] = W_p2[i]; s_b1[i] = b_p1[i]; }
    __syncthreads();

    int warp = t >> 5, lane = t & 31;
    int l = ltile * 8 + warp;
    const __nv_bfloat16* ep = g_epart_bf + (size_t)(b * NL + l) * NE;
    float epr[16];
    #pragma unroll
    for (int j = 0; j < 16; j++) {
        int e = lane + 32 * j;
        epr[j] = __bfloat162float(ep[e]) + s_b1[e];
    }

    int gcb = g_gc[b];
    int p   = g_idx[b];
    float bp2 = b_p2[0];
    float local = 0.f;
    for (int s = 0; s < gcb; s++) {
        float acc = 0.f;
        #pragma unroll
        for (int j = 0; j < 16; j++) {
            int e = lane + 32 * j;
            acc += fast_tanh(s_h[s][e] + epr[j]) * s_w2[e];
        }
        #pragma unroll
        for (int off = 16; off; off >>= 1) acc += __shfl_xor_sync(0xffffffffu, acc, off);
        if (lane == 0) {
            float pl  = acc + bp2;
            float tgt = (float)segments[(p * NS + s) * NL + l];
            local += softplusf(pl) - pl * tgt;
        }
    }
    if (lane == 0) s_warp[warp] = local;
    __syncthreads();
    if (t == 0) {
        float sum = 0.f;
        #pragma unroll
        for (int w = 0; w < 8; w++) sum += s_warp[w];
        g_plan_partial[b * 16 + ltile] = sum;
    }
}

// ---------------- stop loss + final reduction ----------------
__global__ void k_final(const float* __restrict__ W_stop,
                        const float* __restrict__ b_stop,
                        float* __restrict__ out) {
    __shared__ float s_w[NH];
    __shared__ float s_stop[32];
    __shared__ float s_red[1024];
    int t = threadIdx.x;
    for (int i = t; i < NH; i += 1024) s_w[i] = W_stop[i];
    __syncthreads();

    int warp = t >> 5, lane = t & 31;
    float stop_local = 0.f;
    for (int bs = warp; bs < NB * NS; bs += 32) {
        int b = bs / NS, s = bs % NS;
        int gcb = g_gc[b];
        if (s < gcb) {
            const __nv_bfloat16* o = g_outh_bf + (size_t)bs * NH;
            float a = 0.f;
            #pragma unroll
            for (int j = 0; j < 16; j++)
                a += __bfloat162float(o[lane + 32 * j]) * s_w[lane + 32 * j];
            #pragma unroll
            for (int off = 16; off; off >>= 1) a += __shfl_xor_sync(0xffffffffu, a, off);
            if (lane == 0) {
                float logit = a + b_stop[0];
                float label = (s == gcb - 1) ? 1.f : 0.f;
                stop_local += softplusf(logit) - logit * label;
            }
        }
    }
    if (lane == 0) s_stop[warp] = stop_local;

    s_red[t] = g_plan_partial[t] + g_plan_partial[t + 1024];
    __syncthreads();
    for (int off = 512; off; off >>= 1) {
        if (t < off) s_red[t] += s_red[t + off];
        __syncthreads();
    }
    if (t == 0) {
        float stop_sum = 0.f;
        #pragma unroll
        for (int w = 0; w < 32; w++) stop_sum += s_stop[w];
        float ms = g_mask_sum;
        out[0] = stop_sum / ms;
        out[1] = s_red[0] / (ms * (float)NL);
    }
}

// ---------------- launch ----------------
extern "C" void kernel_launch(void* const* d_in, const int* in_sizes, int n_in,
                              void* d_out, int out_size) {
    const float* enc    = (const float*)d_in[0];
    const int*   segs   = (const int*)d_in[1];
    const int*   gcnt   = (const int*)d_in[2];
    const float* ginit  = (const float*)d_in[3];
    const float* W_init = (const float*)d_in[4];
    const float* b_init = (const float*)d_in[5];
    const float* W_ih   = (const float*)d_in[6];
    const float* b_ih   = (const float*)d_in[7];
    const float* W_hh   = (const float*)d_in[8];
    const float* b_hh   = (const float*)d_in[9];
    const float* W_p1   = (const float*)d_in[10];
    const float* b_p1   = (const float*)d_in[11];
    const float* W_p2   = (const float*)d_in[12];
    const float* b_p2   = (const float*)d_in[13];
    const float* W_stop = (const float*)d_in[14];
    const float* b_stop = (const float*)d_in[15];
    float* out = (float*)d_out;

    float *p_h0p, *p_xproj, *p_hpart;
    __nv_bfloat16 *p_epart_bf, *p_inps_bf, *p_outh_bf, *p_enc_bf, *p_wp1_bf, *p_wih_bf,
                  *p_ginit_bf, *p_winit_bf;
    cudaGetSymbolAddress((void**)&p_h0p,      g_h0p);
    cudaGetSymbolAddress((void**)&p_xproj,    g_xproj);
    cudaGetSymbolAddress((void**)&p_hpart,    g_hpart);
    cudaGetSymbolAddress((void**)&p_epart_bf, g_epart_bf);
    cudaGetSymbolAddress((void**)&p_inps_bf,  g_inps_bf);
    cudaGetSymbolAddress((void**)&p_outh_bf,  g_outh_bf);
    cudaGetSymbolAddress((void**)&p_enc_bf,   g_enc_bf);
    cudaGetSymbolAddress((void**)&p_wp1_bf,   g_wp1_bf);
    cudaGetSymbolAddress((void**)&p_wih_bf,   g_wih_bf);
    cudaGetSymbolAddress((void**)&p_ginit_bf, g_ginit_bf);
    cudaGetSymbolAddress((void**)&p_winit_bf, g_winit_bf);

    static cudaStream_t s1 = nullptr;
    static cudaEvent_t eF = nullptr, eC = nullptr, eI = nullptr, e1 = nullptr;
    if (!s1) {
        cudaStreamCreateWithFlags(&s1, cudaStreamNonBlocking);
        cudaEventCreateWithFlags(&eF, cudaEventDisableTiming);
        cudaEventCreateWithFlags(&eC, cudaEventDisableTiming);
        cudaEventCreateWithFlags(&eI, cudaEventDisableTiming);
        cudaEventCreateWithFlags(&e1, cudaEventDisableTiming);
        cudaFuncSetAttribute(k_gru_persist, cudaFuncAttributeMaxDynamicSharedMemorySize, GRUSMEM);
        cudaFuncSetAttribute(gemm128<float>, cudaFuncAttributeMaxDynamicSharedMemorySize, GSMEM);
        cudaFuncSetAttribute(gemm128<__nv_bfloat16>, cudaFuncAttributeMaxDynamicSharedMemorySize, GSMEM);
    }

    // ---- fork: s1 joins the capture before any s1 work ----
    cudaEventRecord(eF, 0);
    cudaStreamWaitEvent(s1, eF, 0);

    // ---- s1: cvt (off critical path), then h0 split-K ----
    k_cvt_all<<<3744, 256, 0, s1>>>((const float4*)W_p1, (const float4*)W_ih,
                                    (const float4*)ginit, (const float4*)W_init);
    cudaEventRecord(eC, s1);
    gemm64_splitk<<<dim3(NH / 64, NB / 64, 3), 128, 0, s1>>>(
        p_ginit_bf, NKIN, p_winit_bf, NKIN, p_h0p, NH, NKIN / 3);

    // ---- s0: sort, inps (concurrent with cvt), then epart after cvt done ----
    k_sort<<<1, NB>>>(gcnt);
    k_inps<<<NB, 256>>>(enc, segs);
    cudaEventRecord(eI, 0);
    cudaStreamWaitEvent(0, eC, 0);
    gemm128<__nv_bfloat16><<<dim3(NE / 128, (NB * NL) / 128), 128, GSMEM>>>(
        p_enc_bf, NE2, p_wp1_bf + NH, NH3, p_epart_bf, NE, NE2);

    // ---- s1: xproj after inps ----
    cudaStreamWaitEvent(s1, eI, 0);
    gemm128<float><<<dim3(NH3 / 128, (NB * NS) / 128), 128, GSMEM, s1>>>(
        p_inps_bf, NE2, p_wih_bf, NE2, p_xproj, NH3, NE2);
    cudaEventRecord(e1, s1);

    // ---- join: GRU runs alone after epart & xproj ----
    cudaStreamWaitEvent(0, e1, 0);
    k_gru_persist<<<64, 256, GRUSMEM>>>(W_hh, b_ih, b_hh, b_init);

    // hpart = outputs @ W1h^T  (1536 x 512, K=512)
    gemm128<float><<<dim3(NE / 128, (NB * NS) / 128), 128, GSMEM>>>(
        p_outh_bf, NH, p_wp1_bf, NH3, p_hpart, NE, NH);

    k_plan<<<dim3(16, NB), 256>>>(segs, b_p1, W_p2, b_p2);
    k_final<<<1, 1024>>>(W_stop, b_stop, out);
}

// round 14
// speedup vs baseline: 1.8165x; 1.1691x over previous
// R14: R12 structure with k_inps hot loop reshaped (manual 2-way l-blocking in
// place of pragma-unroll-4) after two consecutive container failures on the R12
// form — functionally identical, different codegen. All else == R11/R12:
// BK=64 gemm128, split-K h0, persistent GRU with cp.async prefetch.
#include <cuda_runtime.h>
#include <cuda_bf16.h>
#include <mma.h>
#include <cstdint>

using namespace nvcuda;

#define NB   128
#define NS   12
#define NL   128
#define NE   512
#define NE2  1024
#define NH   512
#define NH3  1536
#define NKIN 2304

// ---------------- scratch ----------------
__device__ int   g_idx[NB];
__device__ int   g_gc[NB];
__device__ float g_mask_sum;
__device__ float g_h0p[3 * NB * NH];
__device__ float g_xproj[NB * NS * NH3];
__device__ float g_hpart[NB * NS * NE];
__device__ float g_plan_partial[2048];
__device__ unsigned g_bg_arrive[4];
__device__ unsigned g_bg_gen[4];
// bf16 buffers
__device__ __nv_bfloat16 g_epart_bf[NB * NL * NE];
__device__ __nv_bfloat16 g_enc_bf[NB * NL * NE2];
__device__ __nv_bfloat16 g_inps_bf[NB * NS * NE2];
__device__ __nv_bfloat16 g_outh_bf[NB * NS * NH];
__device__ __nv_bfloat16 g_hb[NB * NH];
__device__ __nv_bfloat16 g_wp1_bf[NE * NH3];
__device__ __nv_bfloat16 g_wih_bf[NH3 * NE2];
__device__ __nv_bfloat16 g_ginit_bf[NB * NKIN];
__device__ __nv_bfloat16 g_winit_bf[NH * NKIN];

// ---------------- helpers ----------------
__device__ __forceinline__ float fast_tanh(float x) {
    float y; asm("tanh.approx.f32 %0, %1;" : "=f"(y) : "f"(x)); return y;
}
__device__ __forceinline__ float sigmoidf(float x) { return 1.f / (1.f + __expf(-x)); }
__device__ __forceinline__ float softplusf(float x) { return (x > 15.f) ? x : log1pf(__expf(x)); }

__device__ __forceinline__ void cp16(void* sdst, const void* gsrc) {
    uint32_t s = (uint32_t)__cvta_generic_to_shared(sdst);
    asm volatile("cp.async.cg.shared.global [%0], [%1], 16;\n" :: "r"(s), "l"(gsrc));
}
#define CP_COMMIT() asm volatile("cp.async.commit_group;\n")
#define CP_WAIT1()  asm volatile("cp.async.wait_group 1;\n")
#define CP_WAIT0()  asm volatile("cp.async.wait_group 0;\n")

__device__ __forceinline__ uint32_t bf2_bits(float a, float b) {
    __nv_bfloat162 v{__float2bfloat16(a), __float2bfloat16(b)};
    return *reinterpret_cast<uint32_t*>(&v);
}

// ---------------- single merged fp32 -> bf16 convert ----------------
__global__ void k_cvt_all(const float4* __restrict__ wp1, const float4* __restrict__ wih,
                          const float4* __restrict__ gin, const float4* __restrict__ win) {
    int i = blockIdx.x * 256 + threadIdx.x;
    const float4* src; __nv_bfloat162* dst; int off;
    if (i < 196608)      { src = wp1; dst = (__nv_bfloat162*)g_wp1_bf;   off = i; }
    else if (i < 589824) { src = wih; dst = (__nv_bfloat162*)g_wih_bf;   off = i - 196608; }
    else if (i < 663552) { src = gin; dst = (__nv_bfloat162*)g_ginit_bf; off = i - 589824; }
    else if (i < 958464) { src = win; dst = (__nv_bfloat162*)g_winit_bf; off = i - 663552; }
    else return;
    float4 v = src[off];
    dst[2 * off]     = __nv_bfloat162{__float2bfloat16(v.x), __float2bfloat16(v.y)};
    dst[2 * off + 1] = __nv_bfloat162{__float2bfloat16(v.z), __float2bfloat16(v.w)};
}

// ---------------- stable descending sort of group_count ----------------
__global__ void k_sort(const int* __restrict__ gc) {
    __shared__ int s_gc[NB];
    __shared__ int red[NB];
    int t = threadIdx.x;
    s_gc[t] = gc[t];
    __syncthreads();
    int my = s_gc[t];
    int rank = 0;
    #pragma unroll 8
    for (int j = 0; j < NB; j++) {
        int v = s_gc[j];
        rank += (v > my) || (v == my && j < t);
    }
    g_idx[rank] = t;
    g_gc[rank]  = my;
    red[t] = my;
    __syncthreads();
    for (int off = 64; off > 0; off >>= 1) {
        if (t < off) red[t] += red[t + off];
        __syncthreads();
    }
    if (t == 0) g_mask_sum = (float)red[0];
}

// ---------------- alpha + inps einsum: grid (2, NB), 2 e's/thread, 2-way l-blocking ----
__global__ __launch_bounds__(256) void k_inps(const float* __restrict__ enc,
                                              const int* __restrict__ segments) {
    __shared__ float s_a[NS][NL];
    __shared__ float s_inv[NS];
    const int eo = blockIdx.x;            // 0..1 (e-half)
    const int b  = blockIdx.y;
    const int t  = threadIdx.x;           // 256 threads
    const int p  = g_idx[b];
    for (int i = t; i < NS * NL; i += 256) {
        int s = i >> 7, l = i & 127;
        float v = 0.f;
        if (s > 0) v = (float)segments[(p * NS + (s - 1)) * NL + l];
        s_a[s][l] = v;
    }
    __syncthreads();
    if (t < NS) {
        float sum = 0.f;
        for (int l = 0; l < NL; l++) sum += s_a[t][l];
        s_inv[t] = 1.f / (sum + 1.f);
    }
    __syncthreads();
    for (int i = t; i < NS * NL; i += 256) {
        int s = i >> 7;
        s_a[s][i & 127] *= s_inv[s];
    }
    __syncthreads();

    const int e2 = eo * 512 + t * 2;      // this thread's 2 e-columns
    const float* encb = enc + (size_t)b * NL * NE2 + e2;
    __nv_bfloat16* encbf = g_enc_bf + (size_t)b * NL * NE2 + e2;

    float acc0[NS], acc1[NS];
    #pragma unroll
    for (int s = 0; s < NS; s++) { acc0[s] = 0.f; acc1[s] = 0.f; }

    // two independent load streams per iteration -> MLP >= 2 (x unroll 2 -> ~4)
    #pragma unroll 2
    for (int l = 0; l < NL; l += 2) {
        float2 va = *reinterpret_cast<const float2*>(encb + (size_t)l * NE2);
        float2 vb = *reinterpret_cast<const float2*>(encb + (size_t)(l + 1) * NE2);
        uint32_t pa = bf2_bits(va.x, va.y);
        uint32_t pb = bf2_bits(vb.x, vb.y);
        *reinterpret_cast<uint32_t*>(encbf + (size_t)l * NE2) = pa;
        *reinterpret_cast<uint32_t*>(encbf + (size_t)(l + 1) * NE2) = pb;
        #pragma unroll
        for (int s = 0; s < NS; s++) {
            float aa = s_a[s][l];
            float ab = s_a[s][l + 1];
            acc0[s] += aa * va.x + ab * vb.x;
            acc1[s] += aa * va.y + ab * vb.y;
        }
    }
    #pragma unroll
    for (int s = 0; s < NS; s++)
        *reinterpret_cast<uint32_t*>(g_inps_bf + ((size_t)b * NS + s) * NE2 + e2) =
            bf2_bits(acc0[s], acc1[s]);
}

// ---------------- bf16 GEMM: 128x128 block, 4 warps, 64x64 warp tile, BK=64, 3-stage ----
#define GSTG 3
#define GLDS 72
template <typename OutT>
__global__ __launch_bounds__(128) void gemm128(
    const __nv_bfloat16* __restrict__ A, int lda,
    const __nv_bfloat16* __restrict__ W, int ldw,
    OutT* __restrict__ C, int ldc, int K) {
    extern __shared__ __align__(16) __nv_bfloat16 gsm[];
    __nv_bfloat16* sA = gsm;                        // [GSTG][128][GLDS]
    __nv_bfloat16* sW = gsm + GSTG * 128 * GLDS;

    const int tid  = threadIdx.x;
    const int warp = tid >> 5;
    const int lane = tid & 31;
    const int wm   = warp & 1;
    const int wn   = warp >> 1;
    const int m0   = blockIdx.y * 128;
    const int n0   = blockIdx.x * 128;
    const int nkt  = K >> 6;

    wmma::fragment<wmma::accumulator, 16, 16, 16, float> acc[4][4];
    #pragma unroll
    for (int i = 0; i < 4; i++)
        #pragma unroll
        for (int j = 0; j < 4; j++) wmma::fill_fragment(acc[i][j], 0.f);

    auto issue = [&](int kt, int st) {
        int k0 = kt << 6;
        __nv_bfloat16* a = sA + st * 128 * GLDS;
        __nv_bfloat16* w = sW + st * 128 * GLDS;
        #pragma unroll
        for (int q = 0; q < 8; q++) {
            int chunk = q * 128 + tid;
            int r  = chunk >> 3;
            int c8 = (chunk & 7) * 8;
            cp16(a + r * GLDS + c8, A + (size_t)(m0 + r) * lda + k0 + c8);
            cp16(w + r * GLDS + c8, W + (size_t)(n0 + r) * ldw + k0 + c8);
        }
        CP_COMMIT();
    };

    issue(0, 0);
    issue(1, 1);
    for (int kt = 0; kt < nkt; kt++) {
        int st = kt % GSTG;
        if (kt == nkt - 1) CP_WAIT0(); else CP_WAIT1();
        __syncthreads();
        if (kt + 2 < nkt) issue(kt + 2, (kt + 2) % GSTG);
        const __nv_bfloat16* a = sA + st * 128 * GLDS;
        const __nv_bfloat16* w = sW + st * 128 * GLDS;
        #pragma unroll
        for (int kk = 0; kk < 64; kk += 16) {
            wmma::fragment<wmma::matrix_a, 16, 16, 16, __nv_bfloat16, wmma::row_major> af[4];
            wmma::fragment<wmma::matrix_b, 16, 16, 16, __nv_bfloat16, wmma::col_major> bf[4];
            #pragma unroll
            for (int i = 0; i < 4; i++)
                wmma::load_matrix_sync(af[i], a + (wm * 64 + i * 16) * GLDS + kk, GLDS);
            #pragma unroll
            for (int j = 0; j < 4; j++)
                wmma::load_matrix_sync(bf[j], w + (wn * 64 + j * 16) * GLDS + kk, GLDS);
            #pragma unroll
            for (int i = 0; i < 4; i++)
                #pragma unroll
                for (int j = 0; j < 4; j++)
                    wmma::mma_sync(acc[i][j], af[i], bf[j], acc[i][j]);
        }
        __syncthreads();
    }

    if constexpr (sizeof(OutT) == 4) {
        #pragma unroll
        for (int i = 0; i < 4; i++)
            #pragma unroll
            for (int j = 0; j < 4; j++)
                wmma::store_matrix_sync(
                    (float*)C + (size_t)(m0 + wm * 64 + i * 16) * ldc + n0 + wn * 64 + j * 16,
                    acc[i][j], ldc, wmma::mem_row_major);
    } else {
        float* stage = reinterpret_cast<float*>(gsm) + warp * 16 * 68;
        #pragma unroll
        for (int i = 0; i < 4; i++) {
            #pragma unroll
            for (int j = 0; j < 4; j++)
                wmma::store_matrix_sync(stage + j * 16, acc[i][j], 68, wmma::mem_row_major);
            __syncwarp();
            int gr = m0 + wm * 64 + i * 16;
            int gc0 = n0 + wn * 64;
            #pragma unroll
            for (int p = 0; p < 16; p++) {
                float v0 = stage[p * 68 + lane * 2];
                float v1 = stage[p * 68 + lane * 2 + 1];
                uint32_t pk = bf2_bits(v0, v1);
                *reinterpret_cast<uint32_t*>(
                    (__nv_bfloat16*)C + (size_t)(gr + p) * ldc + gc0 + lane * 2) = pk;
            }
            __syncwarp();
        }
    }
}
#define GSMEM (GSTG * 2 * 128 * GLDS * 2)   // 110592 B

// ---------------- bf16 GEMM, 64x64 tile, split-K over blockIdx.z (h0) ----------------
__global__ __launch_bounds__(128) void gemm64_splitk(
    const __nv_bfloat16* __restrict__ A, int lda,
    const __nv_bfloat16* __restrict__ W, int ldw,
    float* __restrict__ Cpart, int ldc, int Kchunk) {
    __shared__ __align__(16) __nv_bfloat16 As[2][64][40];
    __shared__ __align__(16) __nv_bfloat16 Ws[2][64][40];

    const int z = blockIdx.z;
    A += (size_t)z * Kchunk;
    W += (size_t)z * Kchunk;
    Cpart += (size_t)z * NB * NH;

    const int tid  = threadIdx.x;
    const int warp = tid >> 5;
    const int wm   = warp & 1;
    const int wn   = warp >> 1;
    const int m0   = blockIdx.y * 64;
    const int n0   = blockIdx.x * 64;
    const int nkt  = Kchunk >> 5;

    wmma::fragment<wmma::accumulator, 16, 16, 16, float> acc[2][2];
    #pragma unroll
    for (int i = 0; i < 2; i++)
        #pragma unroll
        for (int j = 0; j < 2; j++) wmma::fill_fragment(acc[i][j], 0.f);

    auto issue = [&](int kt, int st) {
        int k0 = kt << 5;
        #pragma unroll
        for (int q = 0; q < 2; q++) {
            int chunk = tid * 2 + q;
            int r  = chunk >> 2;
            int c8 = (chunk & 3) * 8;
            cp16(&As[st][r][c8], A + (size_t)(m0 + r) * lda + k0 + c8);
            cp16(&Ws[st][r][c8], W + (size_t)(n0 + r) * ldw + k0 + c8);
        }
        CP_COMMIT();
    };

    issue(0, 0);
    for (int kt = 0; kt < nkt; kt++) {
        int st = kt & 1;
        if (kt + 1 < nkt) { issue(kt + 1, st ^ 1); CP_WAIT1(); }
        else             { CP_WAIT0(); }
        __syncthreads();
        #pragma unroll
        for (int kk = 0; kk < 32; kk += 16) {
            wmma::fragment<wmma::matrix_a, 16, 16, 16, __nv_bfloat16, wmma::row_major> af[2];
            wmma::fragment<wmma::matrix_b, 16, 16, 16, __nv_bfloat16, wmma::col_major> bf[2];
            #pragma unroll
            for (int i = 0; i < 2; i++)
                wmma::load_matrix_sync(af[i], &As[st][wm * 32 + i * 16][kk], 40);
            #pragma unroll
            for (int j = 0; j < 2; j++)
                wmma::load_matrix_sync(bf[j], &Ws[st][wn * 32 + j * 16][kk], 40);
            #pragma unroll
            for (int i = 0; i < 2; i++)
                #pragma unroll
                for (int j = 0; j < 2; j++)
                    wmma::mma_sync(acc[i][j], af[i], bf[j], acc[i][j]);
        }
        __syncthreads();
    }
    #pragma unroll
    for (int i = 0; i < 2; i++)
        #pragma unroll
        for (int j = 0; j < 2; j++)
            wmma::store_matrix_sync(
                Cpart + (size_t)(m0 + wm * 32 + i * 16) * ldc + n0 + wn * 32 + j * 16,
                acc[i][j], ldc, wmma::mem_row_major);
}

// ---------------- per-batch-group barrier ----------------
__device__ __forceinline__ void bgsync(int bg) {
    __syncthreads();
    if (threadIdx.x == 0) {
        unsigned gen;
        asm volatile("ld.acquire.gpu.u32 %0, [%1];" : "=r"(gen) : "l"(&g_bg_gen[bg]) : "memory");
        __threadfence();
        unsigned old = atomicAdd(&g_bg_arrive[bg], 1u);
        if (old == 15) {
            g_bg_arrive[bg] = 0;
            __threadfence();
            atomicAdd(&g_bg_gen[bg], 1u);
        } else {
            unsigned cur;
            do {
                __nanosleep(32);
                asm volatile("ld.acquire.gpu.u32 %0, [%1];" : "=r"(cur) : "l"(&g_bg_gen[bg]) : "memory");
            } while (cur == gen);
        }
    }
    __syncthreads();
}

// ---------------- persistent GRU scan ----------------
__global__ __launch_bounds__(256) void k_gru_persist(
    const float* __restrict__ Whh, const float* __restrict__ bih,
    const float* __restrict__ bhh, const float* __restrict__ binit) {
    extern __shared__ __align__(16) char dyn[];
    __nv_bfloat16* sW  = (__nv_bfloat16*)dyn;          // [96][520]
    __nv_bfloat16* sH  = sW + 96 * 520;                // [32][520]
    float*         sGH = (float*)(sH + 32 * 520);      // [32][100]
    float*         sB  = sGH + 32 * 100;               // [192]
    float*         sX  = sB + 192;                     // [96][32]
    float*         sHP = sX + 96 * 32;                 // [32][32]

    const int tid  = threadIdx.x;
    const int warp = tid >> 5;
    const int cs   = blockIdx.x & 15;
    const int bg   = blockIdx.x >> 4;
    const int C0   = cs * 32;
    const int B0   = bg * 32;

    for (int i = tid; i < 96 * 128; i += 256) {
        int r = i >> 7, c4 = (i & 127) * 4;
        int p = r >> 5, j = r & 31;
        float4 v = *(const float4*)(Whh + (size_t)(p * NH + C0 + j) * NH + c4);
        __nv_bfloat16* d = sW + r * 520 + c4;
        d[0] = __float2bfloat16(v.x); d[1] = __float2bfloat16(v.y);
        d[2] = __float2bfloat16(v.z); d[3] = __float2bfloat16(v.w);
    }
    if (tid < 96) {
        int p = tid >> 5, j = tid & 31;
        sB[tid]      = bih[p * NH + C0 + j];
        sB[96 + tid] = bhh[p * NH + C0 + j];
    }
    for (int i = tid; i < 32 * 32; i += 256) {
        int bi = i >> 5, ci = i & 31;
        int gi = (B0 + bi) * NH + C0 + ci;
        float v = g_h0p[gi] + g_h0p[NB * NH + gi] + g_h0p[2 * NB * NH + gi] + binit[C0 + ci];
        sHP[i] = v;
        g_hb[gi] = __float2bfloat16(v);
    }
    const int smax = g_gc[B0];
    bgsync(bg);

    for (int s = 0; s < smax; s++) {
        #pragma unroll
        for (int q = 0; q < 8; q++) {
            int idx = q * 256 + tid;
            int r = idx >> 6, c8 = (idx & 63) * 8;
            cp16(sH + r * 520 + c8, g_hb + (size_t)(B0 + r) * NH + c8);
        }
        CP_COMMIT();
        #pragma unroll
        for (int q = 0; q < 3; q++) {
            int idx = q * 256 + tid;
            int seg = idx >> 3;
            int f   = (idx & 7) * 4;
            int bb  = seg / 3, p = seg - bb * 3;
            cp16(sX + seg * 32 + f,
                 g_xproj + ((size_t)(B0 + bb) * NS + s) * NH3 + p * NH + C0 + f);
        }
        CP_COMMIT();
        CP_WAIT1();
        __syncthreads();
        if (warp < 6) {
            wmma::fragment<wmma::accumulator, 16, 16, 16, float> acc[2];
            wmma::fill_fragment(acc[0], 0.f);
            wmma::fill_fragment(acc[1], 0.f);
            for (int kk = 0; kk < 512; kk += 16) {
                wmma::fragment<wmma::matrix_a, 16, 16, 16, __nv_bfloat16, wmma::row_major> af[2];
                wmma::fragment<wmma::matrix_b, 16, 16, 16, __nv_bfloat16, wmma::col_major> bf;
                wmma::load_matrix_sync(af[0], sH + kk, 520);
                wmma::load_matrix_sync(af[1], sH + 16 * 520 + kk, 520);
                wmma::load_matrix_sync(bf, sW + warp * 16 * 520 + kk, 520);
                wmma::mma_sync(acc[0], af[0], bf, acc[0]);
                wmma::mma_sync(acc[1], af[1], bf, acc[1]);
            }
            wmma::store_matrix_sync(sGH + warp * 16, acc[0], 100, wmma::mem_row_major);
            wmma::store_matrix_sync(sGH + 16 * 100 + warp * 16, acc[1], 100, wmma::mem_row_major);
        }
        CP_WAIT0();
        __syncthreads();
        for (int i = tid; i < 32 * 32; i += 256) {
            int bi = i >> 5, ci = i & 31;
            float r = sigmoidf(sX[(bi * 3 + 0) * 32 + ci] + sB[ci] +
                               sGH[bi * 100 + ci] + sB[96 + ci]);
            float z = sigmoidf(sX[(bi * 3 + 1) * 32 + ci] + sB[32 + ci] +
                               sGH[bi * 100 + 32 + ci] + sB[96 + 32 + ci]);
            float n = tanhf(sX[(bi * 3 + 2) * 32 + ci] + sB[64 + ci] +
                            r * (sGH[bi * 100 + 64 + ci] + sB[96 + 64 + ci]));
            float hp = sHP[i];
            float hn = (1.f - z) * n + z * hp;
            sHP[i] = hn;
            __nv_bfloat16 hb = __float2bfloat16(hn);
            int gi = (B0 + bi) * NH + C0 + ci;
            g_hb[gi] = hb;
            g_outh_bf[((size_t)(B0 + bi) * NS + s) * NH + C0 + ci] = hb;
        }
        bgsync(bg);
    }
}
#define GRUSMEM 163072

// ---------------- fused plan logits + BCE ----------------
__global__ void k_plan(const int* __restrict__ segments,
                       const float* __restrict__ b_p1,
                       const float* __restrict__ W_p2,
                       const float* __restrict__ b_p2) {
    __shared__ float s_h[NS][NE];
    __shared__ float s_w2[NE];
    __shared__ float s_b1[NE];
    __shared__ float s_warp[8];
    int t = threadIdx.x;
    int b = blockIdx.y, ltile = blockIdx.x;
    for (int i = t; i < NS * NE; i += 256) s_h[i >> 9][i & 511] = g_hpart[(size_t)b * NS * NE + i];
    for (int i = t; i < NE; i += 256) { s_w2[i] = W_p2[i]; s_b1[i] = b_p1[i]; }
    __syncthreads();

    int warp = t >> 5, lane = t & 31;
    int l = ltile * 8 + warp;
    const __nv_bfloat16* ep = g_epart_bf + (size_t)(b * NL + l) * NE;
    float epr[16];
    #pragma unroll
    for (int j = 0; j < 16; j++) {
        int e = lane + 32 * j;
        epr[j] = __bfloat162float(ep[e]) + s_b1[e];
    }

    int gcb = g_gc[b];
    int p   = g_idx[b];
    float bp2 = b_p2[0];
    float local = 0.f;
    for (int s = 0; s < gcb; s++) {
        float acc = 0.f;
        #pragma unroll
        for (int j = 0; j < 16; j++) {
            int e = lane + 32 * j;
            acc += fast_tanh(s_h[s][e] + epr[j]) * s_w2[e];
        }
        #pragma unroll
        for (int off = 16; off; off >>= 1) acc += __shfl_xor_sync(0xffffffffu, acc, off);
        if (lane == 0) {
            float pl  = acc + bp2;
            float tgt = (float)segments[(p * NS + s) * NL + l];
            local += softplusf(pl) - pl * tgt;
        }
    }
    if (lane == 0) s_warp[warp] = local;
    __syncthreads();
    if (t == 0) {
        float sum = 0.f;
        #pragma unroll
        for (int w = 0; w < 8; w++) sum += s_warp[w];
        g_plan_partial[b * 16 + ltile] = sum;
    }
}

// ---------------- stop loss + final reduction ----------------
__global__ void k_final(const float* __restrict__ W_stop,
                        const float* __restrict__ b_stop,
                        float* __restrict__ out) {
    __shared__ float s_w[NH];
    __shared__ float s_stop[32];
    __shared__ float s_red[1024];
    int t = threadIdx.x;
    for (int i = t; i < NH; i += 1024) s_w[i] = W_stop[i];
    __syncthreads();

    int warp = t >> 5, lane = t & 31;
    float stop_local = 0.f;
    for (int bs = warp; bs < NB * NS; bs += 32) {
        int b = bs / NS, s = bs % NS;
        int gcb = g_gc[b];
        if (s < gcb) {
            const __nv_bfloat16* o = g_outh_bf + (size_t)bs * NH;
            float a = 0.f;
            #pragma unroll
            for (int j = 0; j < 16; j++)
                a += __bfloat162float(o[lane + 32 * j]) * s_w[lane + 32 * j];
            #pragma unroll
            for (int off = 16; off; off >>= 1) a += __shfl_xor_sync(0xffffffffu, a, off);
            if (lane == 0) {
                float logit = a + b_stop[0];
                float label = (s == gcb - 1) ? 1.f : 0.f;
                stop_local += softplusf(logit) - logit * label;
            }
        }
    }
    if (lane == 0) s_stop[warp] = stop_local;

    s_red[t] = g_plan_partial[t] + g_plan_partial[t + 1024];
    __syncthreads();
    for (int off = 512; off; off >>= 1) {
        if (t < off) s_red[t] += s_red[t + off];
        __syncthreads();
    }
    if (t == 0) {
        float stop_sum = 0.f;
        #pragma unroll
        for (int w = 0; w < 32; w++) stop_sum += s_stop[w];
        float ms = g_mask_sum;
        out[0] = stop_sum / ms;
        out[1] = s_red[0] / (ms * (float)NL);
    }
}

// ---------------- launch ----------------
extern "C" void kernel_launch(void* const* d_in, const int* in_sizes, int n_in,
                              void* d_out, int out_size) {
    const float* enc    = (const float*)d_in[0];
    const int*   segs   = (const int*)d_in[1];
    const int*   gcnt   = (const int*)d_in[2];
    const float* ginit  = (const float*)d_in[3];
    const float* W_init = (const float*)d_in[4];
    const float* b_init = (const float*)d_in[5];
    const float* W_ih   = (const float*)d_in[6];
    const float* b_ih   = (const float*)d_in[7];
    const float* W_hh   = (const float*)d_in[8];
    const float* b_hh   = (const float*)d_in[9];
    const float* W_p1   = (const float*)d_in[10];
    const float* b_p1   = (const float*)d_in[11];
    const float* W_p2   = (const float*)d_in[12];
    const float* b_p2   = (const float*)d_in[13];
    const float* W_stop = (const float*)d_in[14];
    const float* b_stop = (const float*)d_in[15];
    float* out = (float*)d_out;

    float *p_h0p, *p_xproj, *p_hpart;
    __nv_bfloat16 *p_epart_bf, *p_inps_bf, *p_outh_bf, *p_enc_bf, *p_wp1_bf, *p_wih_bf,
                  *p_ginit_bf, *p_winit_bf;
    cudaGetSymbolAddress((void**)&p_h0p,      g_h0p);
    cudaGetSymbolAddress((void**)&p_xproj,    g_xproj);
    cudaGetSymbolAddress((void**)&p_hpart,    g_hpart);
    cudaGetSymbolAddress((void**)&p_epart_bf, g_epart_bf);
    cudaGetSymbolAddress((void**)&p_inps_bf,  g_inps_bf);
    cudaGetSymbolAddress((void**)&p_outh_bf,  g_outh_bf);
    cudaGetSymbolAddress((void**)&p_enc_bf,   g_enc_bf);
    cudaGetSymbolAddress((void**)&p_wp1_bf,   g_wp1_bf);
    cudaGetSymbolAddress((void**)&p_wih_bf,   g_wih_bf);
    cudaGetSymbolAddress((void**)&p_ginit_bf, g_ginit_bf);
    cudaGetSymbolAddress((void**)&p_winit_bf, g_winit_bf);

    static cudaStream_t s1 = nullptr;
    static cudaEvent_t eF = nullptr, eC = nullptr, eI = nullptr, e1 = nullptr;
    if (!s1) {
        cudaStreamCreateWithFlags(&s1, cudaStreamNonBlocking);
        cudaEventCreateWithFlags(&eF, cudaEventDisableTiming);
        cudaEventCreateWithFlags(&eC, cudaEventDisableTiming);
        cudaEventCreateWithFlags(&eI, cudaEventDisableTiming);
        cudaEventCreateWithFlags(&e1, cudaEventDisableTiming);
        cudaFuncSetAttribute(k_gru_persist, cudaFuncAttributeMaxDynamicSharedMemorySize, GRUSMEM);
        cudaFuncSetAttribute(gemm128<float>, cudaFuncAttributeMaxDynamicSharedMemorySize, GSMEM);
        cudaFuncSetAttribute(gemm128<__nv_bfloat16>, cudaFuncAttributeMaxDynamicSharedMemorySize, GSMEM);
    }

    // ---- fork: s1 joins the capture before any s1 work ----
    cudaEventRecord(eF, 0);
    cudaStreamWaitEvent(s1, eF, 0);

    // ---- s1: cvt (off critical path), then h0 split-K ----
    k_cvt_all<<<3744, 256, 0, s1>>>((const float4*)W_p1, (const float4*)W_ih,
                                    (const float4*)ginit, (const float4*)W_init);
    cudaEventRecord(eC, s1);
    gemm64_splitk<<<dim3(NH / 64, NB / 64, 3), 128, 0, s1>>>(
        p_ginit_bf, NKIN, p_winit_bf, NKIN, p_h0p, NH, NKIN / 3);

    // ---- s0: sort, inps (concurrent with cvt), then epart after cvt done ----
    k_sort<<<1, NB>>>(gcnt);
    k_inps<<<dim3(2, NB), 256>>>(enc, segs);
    cudaEventRecord(eI, 0);
    cudaStreamWaitEvent(0, eC, 0);
    gemm128<__nv_bfloat16><<<dim3(NE / 128, (NB * NL) / 128), 128, GSMEM>>>(
        p_enc_bf, NE2, p_wp1_bf + NH, NH3, p_epart_bf, NE, NE2);

    // ---- s1: xproj after inps ----
    cudaStreamWaitEvent(s1, eI, 0);
    gemm128<float><<<dim3(NH3 / 128, (NB * NS) / 128), 128, GSMEM, s1>>>(
        p_inps_bf, NE2, p_wih_bf, NE2, p_xproj, NH3, NE2);
    cudaEventRecord(e1, s1);

    // ---- join: GRU runs alone after epart & xproj ----
    cudaStreamWaitEvent(0, e1, 0);
    k_gru_persist<<<64, 256, GRUSMEM>>>(W_hh, b_ih, b_hh, b_init);

    // hpart = outputs @ W1h^T  (1536 x 512, K=512)
    gemm128<float><<<dim3(NE / 128, (NB * NS) / 128), 128, GSMEM>>>(
        p_outh_bf, NH, p_wp1_bf, NH3, p_hpart, NE, NH);

    k_plan<<<dim3(16, NB), 256>>>(segs, b_p1, W_p2, b_p2);
    k_final<<<1, 1024>>>(W_stop, b_stop, out);
}

// round 15
// speedup vs baseline: 1.9259x; 1.0603x over previous
// R15: GRU overlapped with epart (s0: sort->inps->xproj->GRU->hpart->plan; s1:
// cvt->h0->epart). Safe now: GRU 163KB smem vs epart 110KB cannot co-reside on
// an SM; per-16-CTA barriers; epart never waits on GRU (no deadlock).
// Plus k_inps unroll 2->4 (MLP ~8).
#include <cuda_runtime.h>
#include <cuda_bf16.h>
#include <mma.h>
#include <cstdint>

using namespace nvcuda;

#define NB   128
#define NS   12
#define NL   128
#define NE   512
#define NE2  1024
#define NH   512
#define NH3  1536
#define NKIN 2304

// ---------------- scratch ----------------
__device__ int   g_idx[NB];
__device__ int   g_gc[NB];
__device__ float g_mask_sum;
__device__ float g_h0p[3 * NB * NH];
__device__ float g_xproj[NB * NS * NH3];
__device__ float g_hpart[NB * NS * NE];
__device__ float g_plan_partial[2048];
__device__ unsigned g_bg_arrive[4];
__device__ unsigned g_bg_gen[4];
// bf16 buffers
__device__ __nv_bfloat16 g_epart_bf[NB * NL * NE];
__device__ __nv_bfloat16 g_enc_bf[NB * NL * NE2];
__device__ __nv_bfloat16 g_inps_bf[NB * NS * NE2];
__device__ __nv_bfloat16 g_outh_bf[NB * NS * NH];
__device__ __nv_bfloat16 g_hb[NB * NH];
__device__ __nv_bfloat16 g_wp1_bf[NE * NH3];
__device__ __nv_bfloat16 g_wih_bf[NH3 * NE2];
__device__ __nv_bfloat16 g_ginit_bf[NB * NKIN];
__device__ __nv_bfloat16 g_winit_bf[NH * NKIN];

// ---------------- helpers ----------------
__device__ __forceinline__ float fast_tanh(float x) {
    float y; asm("tanh.approx.f32 %0, %1;" : "=f"(y) : "f"(x)); return y;
}
__device__ __forceinline__ float sigmoidf(float x) { return 1.f / (1.f + __expf(-x)); }
__device__ __forceinline__ float softplusf(float x) { return (x > 15.f) ? x : log1pf(__expf(x)); }

__device__ __forceinline__ void cp16(void* sdst, const void* gsrc) {
    uint32_t s = (uint32_t)__cvta_generic_to_shared(sdst);
    asm volatile("cp.async.cg.shared.global [%0], [%1], 16;\n" :: "r"(s), "l"(gsrc));
}
#define CP_COMMIT() asm volatile("cp.async.commit_group;\n")
#define CP_WAIT1()  asm volatile("cp.async.wait_group 1;\n")
#define CP_WAIT0()  asm volatile("cp.async.wait_group 0;\n")

__device__ __forceinline__ uint32_t bf2_bits(float a, float b) {
    __nv_bfloat162 v{__float2bfloat16(a), __float2bfloat16(b)};
    return *reinterpret_cast<uint32_t*>(&v);
}

// ---------------- single merged fp32 -> bf16 convert ----------------
__global__ void k_cvt_all(const float4* __restrict__ wp1, const float4* __restrict__ wih,
                          const float4* __restrict__ gin, const float4* __restrict__ win) {
    int i = blockIdx.x * 256 + threadIdx.x;
    const float4* src; __nv_bfloat162* dst; int off;
    if (i < 196608)      { src = wp1; dst = (__nv_bfloat162*)g_wp1_bf;   off = i; }
    else if (i < 589824) { src = wih; dst = (__nv_bfloat162*)g_wih_bf;   off = i - 196608; }
    else if (i < 663552) { src = gin; dst = (__nv_bfloat162*)g_ginit_bf; off = i - 589824; }
    else if (i < 958464) { src = win; dst = (__nv_bfloat162*)g_winit_bf; off = i - 663552; }
    else return;
    float4 v = src[off];
    dst[2 * off]     = __nv_bfloat162{__float2bfloat16(v.x), __float2bfloat16(v.y)};
    dst[2 * off + 1] = __nv_bfloat162{__float2bfloat16(v.z), __float2bfloat16(v.w)};
}

// ---------------- stable descending sort of group_count ----------------
__global__ void k_sort(const int* __restrict__ gc) {
    __shared__ int s_gc[NB];
    __shared__ int red[NB];
    int t = threadIdx.x;
    s_gc[t] = gc[t];
    __syncthreads();
    int my = s_gc[t];
    int rank = 0;
    #pragma unroll 8
    for (int j = 0; j < NB; j++) {
        int v = s_gc[j];
        rank += (v > my) || (v == my && j < t);
    }
    g_idx[rank] = t;
    g_gc[rank]  = my;
    red[t] = my;
    __syncthreads();
    for (int off = 64; off > 0; off >>= 1) {
        if (t < off) red[t] += red[t + off];
        __syncthreads();
    }
    if (t == 0) g_mask_sum = (float)red[0];
}

// ---------------- alpha + inps einsum: grid (2, NB), 2 e's/thread, 2-way blocking x4 ----
__global__ __launch_bounds__(256) void k_inps(const float* __restrict__ enc,
                                              const int* __restrict__ segments) {
    __shared__ float s_a[NS][NL];
    __shared__ float s_inv[NS];
    const int eo = blockIdx.x;
    const int b  = blockIdx.y;
    const int t  = threadIdx.x;
    const int p  = g_idx[b];
    for (int i = t; i < NS * NL; i += 256) {
        int s = i >> 7, l = i & 127;
        float v = 0.f;
        if (s > 0) v = (float)segments[(p * NS + (s - 1)) * NL + l];
        s_a[s][l] = v;
    }
    __syncthreads();
    if (t < NS) {
        float sum = 0.f;
        for (int l = 0; l < NL; l++) sum += s_a[t][l];
        s_inv[t] = 1.f / (sum + 1.f);
    }
    __syncthreads();
    for (int i = t; i < NS * NL; i += 256) {
        int s = i >> 7;
        s_a[s][i & 127] *= s_inv[s];
    }
    __syncthreads();

    const int e2 = eo * 512 + t * 2;
    const float* encb = enc + (size_t)b * NL * NE2 + e2;
    __nv_bfloat16* encbf = g_enc_bf + (size_t)b * NL * NE2 + e2;

    float acc0[NS], acc1[NS];
    #pragma unroll
    for (int s = 0; s < NS; s++) { acc0[s] = 0.f; acc1[s] = 0.f; }

    #pragma unroll 4
    for (int l = 0; l < NL; l += 2) {
        float2 va = *reinterpret_cast<const float2*>(encb + (size_t)l * NE2);
        float2 vb = *reinterpret_cast<const float2*>(encb + (size_t)(l + 1) * NE2);
        uint32_t pa = bf2_bits(va.x, va.y);
        uint32_t pb = bf2_bits(vb.x, vb.y);
        *reinterpret_cast<uint32_t*>(encbf + (size_t)l * NE2) = pa;
        *reinterpret_cast<uint32_t*>(encbf + (size_t)(l + 1) * NE2) = pb;
        #pragma unroll
        for (int s = 0; s < NS; s++) {
            float aa = s_a[s][l];
            float ab = s_a[s][l + 1];
            acc0[s] += aa * va.x + ab * vb.x;
            acc1[s] += aa * va.y + ab * vb.y;
        }
    }
    #pragma unroll
    for (int s = 0; s < NS; s++)
        *reinterpret_cast<uint32_t*>(g_inps_bf + ((size_t)b * NS + s) * NE2 + e2) =
            bf2_bits(acc0[s], acc1[s]);
}

// ---------------- bf16 GEMM: 128x128 block, 4 warps, 64x64 warp tile, BK=64, 3-stage ----
#define GSTG 3
#define GLDS 72
template <typename OutT>
__global__ __launch_bounds__(128) void gemm128(
    const __nv_bfloat16* __restrict__ A, int lda,
    const __nv_bfloat16* __restrict__ W, int ldw,
    OutT* __restrict__ C, int ldc, int K) {
    extern __shared__ __align__(16) __nv_bfloat16 gsm[];
    __nv_bfloat16* sA = gsm;
    __nv_bfloat16* sW = gsm + GSTG * 128 * GLDS;

    const int tid  = threadIdx.x;
    const int warp = tid >> 5;
    const int lane = tid & 31;
    const int wm   = warp & 1;
    const int wn   = warp >> 1;
    const int m0   = blockIdx.y * 128;
    const int n0   = blockIdx.x * 128;
    const int nkt  = K >> 6;

    wmma::fragment<wmma::accumulator, 16, 16, 16, float> acc[4][4];
    #pragma unroll
    for (int i = 0; i < 4; i++)
        #pragma unroll
        for (int j = 0; j < 4; j++) wmma::fill_fragment(acc[i][j], 0.f);

    auto issue = [&](int kt, int st) {
        int k0 = kt << 6;
        __nv_bfloat16* a = sA + st * 128 * GLDS;
        __nv_bfloat16* w = sW + st * 128 * GLDS;
        #pragma unroll
        for (int q = 0; q < 8; q++) {
            int chunk = q * 128 + tid;
            int r  = chunk >> 3;
            int c8 = (chunk & 7) * 8;
            cp16(a + r * GLDS + c8, A + (size_t)(m0 + r) * lda + k0 + c8);
            cp16(w + r * GLDS + c8, W + (size_t)(n0 + r) * ldw + k0 + c8);
        }
        CP_COMMIT();
    };

    issue(0, 0);
    issue(1, 1);
    for (int kt = 0; kt < nkt; kt++) {
        int st = kt % GSTG;
        if (kt == nkt - 1) CP_WAIT0(); else CP_WAIT1();
        __syncthreads();
        if (kt + 2 < nkt) issue(kt + 2, (kt + 2) % GSTG);
        const __nv_bfloat16* a = sA + st * 128 * GLDS;
        const __nv_bfloat16* w = sW + st * 128 * GLDS;
        #pragma unroll
        for (int kk = 0; kk < 64; kk += 16) {
            wmma::fragment<wmma::matrix_a, 16, 16, 16, __nv_bfloat16, wmma::row_major> af[4];
            wmma::fragment<wmma::matrix_b, 16, 16, 16, __nv_bfloat16, wmma::col_major> bf[4];
            #pragma unroll
            for (int i = 0; i < 4; i++)
                wmma::load_matrix_sync(af[i], a + (wm * 64 + i * 16) * GLDS + kk, GLDS);
            #pragma unroll
            for (int j = 0; j < 4; j++)
                wmma::load_matrix_sync(bf[j], w + (wn * 64 + j * 16) * GLDS + kk, GLDS);
            #pragma unroll
            for (int i = 0; i < 4; i++)
                #pragma unroll
                for (int j = 0; j < 4; j++)
                    wmma::mma_sync(acc[i][j], af[i], bf[j], acc[i][j]);
        }
        __syncthreads();
    }

    if constexpr (sizeof(OutT) == 4) {
        #pragma unroll
        for (int i = 0; i < 4; i++)
            #pragma unroll
            for (int j = 0; j < 4; j++)
                wmma::store_matrix_sync(
                    (float*)C + (size_t)(m0 + wm * 64 + i * 16) * ldc + n0 + wn * 64 + j * 16,
                    acc[i][j], ldc, wmma::mem_row_major);
    } else {
        float* stage = reinterpret_cast<float*>(gsm) + warp * 16 * 68;
        #pragma unroll
        for (int i = 0; i < 4; i++) {
            #pragma unroll
            for (int j = 0; j < 4; j++)
                wmma::store_matrix_sync(stage + j * 16, acc[i][j], 68, wmma::mem_row_major);
            __syncwarp();
            int gr = m0 + wm * 64 + i * 16;
            int gc0 = n0 + wn * 64;
            #pragma unroll
            for (int p = 0; p < 16; p++) {
                float v0 = stage[p * 68 + lane * 2];
                float v1 = stage[p * 68 + lane * 2 + 1];
                uint32_t pk = bf2_bits(v0, v1);
                *reinterpret_cast<uint32_t*>(
                    (__nv_bfloat16*)C + (size_t)(gr + p) * ldc + gc0 + lane * 2) = pk;
            }
            __syncwarp();
        }
    }
}
#define GSMEM (GSTG * 2 * 128 * GLDS * 2)   // 110592 B

// ---------------- bf16 GEMM, 64x64 tile, split-K over blockIdx.z (h0) ----------------
__global__ __launch_bounds__(128) void gemm64_splitk(
    const __nv_bfloat16* __restrict__ A, int lda,
    const __nv_bfloat16* __restrict__ W, int ldw,
    float* __restrict__ Cpart, int ldc, int Kchunk) {
    __shared__ __align__(16) __nv_bfloat16 As[2][64][40];
    __shared__ __align__(16) __nv_bfloat16 Ws[2][64][40];

    const int z = blockIdx.z;
    A += (size_t)z * Kchunk;
    W += (size_t)z * Kchunk;
    Cpart += (size_t)z * NB * NH;

    const int tid  = threadIdx.x;
    const int warp = tid >> 5;
    const int wm   = warp & 1;
    const int wn   = warp >> 1;
    const int m0   = blockIdx.y * 64;
    const int n0   = blockIdx.x * 64;
    const int nkt  = Kchunk >> 5;

    wmma::fragment<wmma::accumulator, 16, 16, 16, float> acc[2][2];
    #pragma unroll
    for (int i = 0; i < 2; i++)
        #pragma unroll
        for (int j = 0; j < 2; j++) wmma::fill_fragment(acc[i][j], 0.f);

    auto issue = [&](int kt, int st) {
        int k0 = kt << 5;
        #pragma unroll
        for (int q = 0; q < 2; q++) {
            int chunk = tid * 2 + q;
            int r  = chunk >> 2;
            int c8 = (chunk & 3) * 8;
            cp16(&As[st][r][c8], A + (size_t)(m0 + r) * lda + k0 + c8);
            cp16(&Ws[st][r][c8], W + (size_t)(n0 + r) * ldw + k0 + c8);
        }
        CP_COMMIT();
    };

    issue(0, 0);
    for (int kt = 0; kt < nkt; kt++) {
        int st = kt & 1;
        if (kt + 1 < nkt) { issue(kt + 1, st ^ 1); CP_WAIT1(); }
        else             { CP_WAIT0(); }
        __syncthreads();
        #pragma unroll
        for (int kk = 0; kk < 32; kk += 16) {
            wmma::fragment<wmma::matrix_a, 16, 16, 16, __nv_bfloat16, wmma::row_major> af[2];
            wmma::fragment<wmma::matrix_b, 16, 16, 16, __nv_bfloat16, wmma::col_major> bf[2];
            #pragma unroll
            for (int i = 0; i < 2; i++)
                wmma::load_matrix_sync(af[i], &As[st][wm * 32 + i * 16][kk], 40);
            #pragma unroll
            for (int j = 0; j < 2; j++)
                wmma::load_matrix_sync(bf[j], &Ws[st][wn * 32 + j * 16][kk], 40);
            #pragma unroll
            for (int i = 0; i < 2; i++)
                #pragma unroll
                for (int j = 0; j < 2; j++)
                    wmma::mma_sync(acc[i][j], af[i], bf[j], acc[i][j]);
        }
        __syncthreads();
    }
    #pragma unroll
    for (int i = 0; i < 2; i++)
        #pragma unroll
        for (int j = 0; j < 2; j++)
            wmma::store_matrix_sync(
                Cpart + (size_t)(m0 + wm * 32 + i * 16) * ldc + n0 + wn * 32 + j * 16,
                acc[i][j], ldc, wmma::mem_row_major);
}

// ---------------- per-batch-group barrier ----------------
__device__ __forceinline__ void bgsync(int bg) {
    __syncthreads();
    if (threadIdx.x == 0) {
        unsigned gen;
        asm volatile("ld.acquire.gpu.u32 %0, [%1];" : "=r"(gen) : "l"(&g_bg_gen[bg]) : "memory");
        __threadfence();
        unsigned old = atomicAdd(&g_bg_arrive[bg], 1u);
        if (old == 15) {
            g_bg_arrive[bg] = 0;
            __threadfence();
            atomicAdd(&g_bg_gen[bg], 1u);
        } else {
            unsigned cur;
            do {
                __nanosleep(32);
                asm volatile("ld.acquire.gpu.u32 %0, [%1];" : "=r"(cur) : "l"(&g_bg_gen[bg]) : "memory");
            } while (cur == gen);
        }
    }
    __syncthreads();
}

// ---------------- persistent GRU scan ----------------
__global__ __launch_bounds__(256) void k_gru_persist(
    const float* __restrict__ Whh, const float* __restrict__ bih,
    const float* __restrict__ bhh, const float* __restrict__ binit) {
    extern __shared__ __align__(16) char dyn[];
    __nv_bfloat16* sW  = (__nv_bfloat16*)dyn;          // [96][520]
    __nv_bfloat16* sH  = sW + 96 * 520;                // [32][520]
    float*         sGH = (float*)(sH + 32 * 520);      // [32][100]
    float*         sB  = sGH + 32 * 100;               // [192]
    float*         sX  = sB + 192;                     // [96][32]
    float*         sHP = sX + 96 * 32;                 // [32][32]

    const int tid  = threadIdx.x;
    const int warp = tid >> 5;
    const int cs   = blockIdx.x & 15;
    const int bg   = blockIdx.x >> 4;
    const int C0   = cs * 32;
    const int B0   = bg * 32;

    for (int i = tid; i < 96 * 128; i += 256) {
        int r = i >> 7, c4 = (i & 127) * 4;
        int p = r >> 5, j = r & 31;
        float4 v = *(const float4*)(Whh + (size_t)(p * NH + C0 + j) * NH + c4);
        __nv_bfloat16* d = sW + r * 520 + c4;
        d[0] = __float2bfloat16(v.x); d[1] = __float2bfloat16(v.y);
        d[2] = __float2bfloat16(v.z); d[3] = __float2bfloat16(v.w);
    }
    if (tid < 96) {
        int p = tid >> 5, j = tid & 31;
        sB[tid]      = bih[p * NH + C0 + j];
        sB[96 + tid] = bhh[p * NH + C0 + j];
    }
    for (int i = tid; i < 32 * 32; i += 256) {
        int bi = i >> 5, ci = i & 31;
        int gi = (B0 + bi) * NH + C0 + ci;
        float v = g_h0p[gi] + g_h0p[NB * NH + gi] + g_h0p[2 * NB * NH + gi] + binit[C0 + ci];
        sHP[i] = v;
        g_hb[gi] = __float2bfloat16(v);
    }
    const int smax = g_gc[B0];
    bgsync(bg);

    for (int s = 0; s < smax; s++) {
        #pragma unroll
        for (int q = 0; q < 8; q++) {
            int idx = q * 256 + tid;
            int r = idx >> 6, c8 = (idx & 63) * 8;
            cp16(sH + r * 520 + c8, g_hb + (size_t)(B0 + r) * NH + c8);
        }
        CP_COMMIT();
        #pragma unroll
        for (int q = 0; q < 3; q++) {
            int idx = q * 256 + tid;
            int seg = idx >> 3;
            int f   = (idx & 7) * 4;
            int bb  = seg / 3, p = seg - bb * 3;
            cp16(sX + seg * 32 + f,
                 g_xproj + ((size_t)(B0 + bb) * NS + s) * NH3 + p * NH + C0 + f);
        }
        CP_COMMIT();
        CP_WAIT1();
        __syncthreads();
        if (warp < 6) {
            wmma::fragment<wmma::accumulator, 16, 16, 16, float> acc[2];
            wmma::fill_fragment(acc[0], 0.f);
            wmma::fill_fragment(acc[1], 0.f);
            for (int kk = 0; kk < 512; kk += 16) {
                wmma::fragment<wmma::matrix_a, 16, 16, 16, __nv_bfloat16, wmma::row_major> af[2];
                wmma::fragment<wmma::matrix_b, 16, 16, 16, __nv_bfloat16, wmma::col_major> bf;
                wmma::load_matrix_sync(af[0], sH + kk, 520);
                wmma::load_matrix_sync(af[1], sH + 16 * 520 + kk, 520);
                wmma::load_matrix_sync(bf, sW + warp * 16 * 520 + kk, 520);
                wmma::mma_sync(acc[0], af[0], bf, acc[0]);
                wmma::mma_sync(acc[1], af[1], bf, acc[1]);
            }
            wmma::store_matrix_sync(sGH + warp * 16, acc[0], 100, wmma::mem_row_major);
            wmma::store_matrix_sync(sGH + 16 * 100 + warp * 16, acc[1], 100, wmma::mem_row_major);
        }
        CP_WAIT0();
        __syncthreads();
        for (int i = tid; i < 32 * 32; i += 256) {
            int bi = i >> 5, ci = i & 31;
            float r = sigmoidf(sX[(bi * 3 + 0) * 32 + ci] + sB[ci] +
                               sGH[bi * 100 + ci] + sB[96 + ci]);
            float z = sigmoidf(sX[(bi * 3 + 1) * 32 + ci] + sB[32 + ci] +
                               sGH[bi * 100 + 32 + ci] + sB[96 + 32 + ci]);
            float n = tanhf(sX[(bi * 3 + 2) * 32 + ci] + sB[64 + ci] +
                            r * (sGH[bi * 100 + 64 + ci] + sB[96 + 64 + ci]));
            float hp = sHP[i];
            float hn = (1.f - z) * n + z * hp;
            sHP[i] = hn;
            __nv_bfloat16 hb = __float2bfloat16(hn);
            int gi = (B0 + bi) * NH + C0 + ci;
            g_hb[gi] = hb;
            g_outh_bf[((size_t)(B0 + bi) * NS + s) * NH + C0 + ci] = hb;
        }
        bgsync(bg);
    }
}
#define GRUSMEM 163072

// ---------------- fused plan logits + BCE ----------------
__global__ void k_plan(const int* __restrict__ segments,
                       const float* __restrict__ b_p1,
                       const float* __restrict__ W_p2,
                       const float* __restrict__ b_p2) {
    __shared__ float s_h[NS][NE];
    __shared__ float s_w2[NE];
    __shared__ float s_b1[NE];
    __shared__ float s_warp[8];
    int t = threadIdx.x;
    int b = blockIdx.y, ltile = blockIdx.x;
    for (int i = t; i < NS * NE; i += 256) s_h[i >> 9][i & 511] = g_hpart[(size_t)b * NS * NE + i];
    for (int i = t; i < NE; i += 256) { s_w2[i] = W_p2[i]; s_b1[i] = b_p1[i]; }
    __syncthreads();

    int warp = t >> 5, lane = t & 31;
    int l = ltile * 8 + warp;
    const __nv_bfloat16* ep = g_epart_bf + (size_t)(b * NL + l) * NE;
    float epr[16];
    #pragma unroll
    for (int j = 0; j < 16; j++) {
        int e = lane + 32 * j;
        epr[j] = __bfloat162float(ep[e]) + s_b1[e];
    }

    int gcb = g_gc[b];
    int p   = g_idx[b];
    float bp2 = b_p2[0];
    float local = 0.f;
    for (int s = 0; s < gcb; s++) {
        float acc = 0.f;
        #pragma unroll
        for (int j = 0; j < 16; j++) {
            int e = lane + 32 * j;
            acc += fast_tanh(s_h[s][e] + epr[j]) * s_w2[e];
        }
        #pragma unroll
        for (int off = 16; off; off >>= 1) acc += __shfl_xor_sync(0xffffffffu, acc, off);
        if (lane == 0) {
            float pl  = acc + bp2;
            float tgt = (float)segments[(p * NS + s) * NL + l];
            local += softplusf(pl) - pl * tgt;
        }
    }
    if (lane == 0) s_warp[warp] = local;
    __syncthreads();
    if (t == 0) {
        float sum = 0.f;
        #pragma unroll
        for (int w = 0; w < 8; w++) sum += s_warp[w];
        g_plan_partial[b * 16 + ltile] = sum;
    }
}

// ---------------- stop loss + final reduction ----------------
__global__ void k_final(const float* __restrict__ W_stop,
                        const float* __restrict__ b_stop,
                        float* __restrict__ out) {
    __shared__ float s_w[NH];
    __shared__ float s_stop[32];
    __shared__ float s_red[1024];
    int t = threadIdx.x;
    for (int i = t; i < NH; i += 1024) s_w[i] = W_stop[i];
    __syncthreads();

    int warp = t >> 5, lane = t & 31;
    float stop_local = 0.f;
    for (int bs = warp; bs < NB * NS; bs += 32) {
        int b = bs / NS, s = bs % NS;
        int gcb = g_gc[b];
        if (s < gcb) {
            const __nv_bfloat16* o = g_outh_bf + (size_t)bs * NH;
            float a = 0.f;
            #pragma unroll
            for (int j = 0; j < 16; j++)
                a += __bfloat162float(o[lane + 32 * j]) * s_w[lane + 32 * j];
            #pragma unroll
            for (int off = 16; off; off >>= 1) a += __shfl_xor_sync(0xffffffffu, a, off);
            if (lane == 0) {
                float logit = a + b_stop[0];
                float label = (s == gcb - 1) ? 1.f : 0.f;
                stop_local += softplusf(logit) - logit * label;
            }
        }
    }
    if (lane == 0) s_stop[warp] = stop_local;

    s_red[t] = g_plan_partial[t] + g_plan_partial[t + 1024];
    __syncthreads();
    for (int off = 512; off; off >>= 1) {
        if (t < off) s_red[t] += s_red[t + off];
        __syncthreads();
    }
    if (t == 0) {
        float stop_sum = 0.f;
        #pragma unroll
        for (int w = 0; w < 32; w++) stop_sum += s_stop[w];
        float ms = g_mask_sum;
        out[0] = stop_sum / ms;
        out[1] = s_red[0] / (ms * (float)NL);
    }
}

// ---------------- launch: GRU overlapped with epart ----------------
extern "C" void kernel_launch(void* const* d_in, const int* in_sizes, int n_in,
                              void* d_out, int out_size) {
    const float* enc    = (const float*)d_in[0];
    const int*   segs   = (const int*)d_in[1];
    const int*   gcnt   = (const int*)d_in[2];
    const float* ginit  = (const float*)d_in[3];
    const float* W_init = (const float*)d_in[4];
    const float* b_init = (const float*)d_in[5];
    const float* W_ih   = (const float*)d_in[6];
    const float* b_ih   = (const float*)d_in[7];
    const float* W_hh   = (const float*)d_in[8];
    const float* b_hh   = (const float*)d_in[9];
    const float* W_p1   = (const float*)d_in[10];
    const float* b_p1   = (const float*)d_in[11];
    const float* W_p2   = (const float*)d_in[12];
    const float* b_p2   = (const float*)d_in[13];
    const float* W_stop = (const float*)d_in[14];
    const float* b_stop = (const float*)d_in[15];
    float* out = (float*)d_out;

    float *p_h0p, *p_xproj, *p_hpart;
    __nv_bfloat16 *p_epart_bf, *p_inps_bf, *p_outh_bf, *p_enc_bf, *p_wp1_bf, *p_wih_bf,
                  *p_ginit_bf, *p_winit_bf;
    cudaGetSymbolAddress((void**)&p_h0p,      g_h0p);
    cudaGetSymbolAddress((void**)&p_xproj,    g_xproj);
    cudaGetSymbolAddress((void**)&p_hpart,    g_hpart);
    cudaGetSymbolAddress((void**)&p_epart_bf, g_epart_bf);
    cudaGetSymbolAddress((void**)&p_inps_bf,  g_inps_bf);
    cudaGetSymbolAddress((void**)&p_outh_bf,  g_outh_bf);
    cudaGetSymbolAddress((void**)&p_enc_bf,   g_enc_bf);
    cudaGetSymbolAddress((void**)&p_wp1_bf,   g_wp1_bf);
    cudaGetSymbolAddress((void**)&p_wih_bf,   g_wih_bf);
    cudaGetSymbolAddress((void**)&p_ginit_bf, g_ginit_bf);
    cudaGetSymbolAddress((void**)&p_winit_bf, g_winit_bf);

    static cudaStream_t s1 = nullptr;
    static cudaEvent_t eF = nullptr, eC = nullptr, eH = nullptr, eI = nullptr, eE = nullptr;
    if (!s1) {
        cudaStreamCreateWithFlags(&s1, cudaStreamNonBlocking);
        cudaEventCreateWithFlags(&eF, cudaEventDisableTiming);
        cudaEventCreateWithFlags(&eC, cudaEventDisableTiming);
        cudaEventCreateWithFlags(&eH, cudaEventDisableTiming);
        cudaEventCreateWithFlags(&eI, cudaEventDisableTiming);
        cudaEventCreateWithFlags(&eE, cudaEventDisableTiming);
        cudaFuncSetAttribute(k_gru_persist, cudaFuncAttributeMaxDynamicSharedMemorySize, GRUSMEM);
        cudaFuncSetAttribute(gemm128<float>, cudaFuncAttributeMaxDynamicSharedMemorySize, GSMEM);
        cudaFuncSetAttribute(gemm128<__nv_bfloat16>, cudaFuncAttributeMaxDynamicSharedMemorySize, GSMEM);
    }

    // ---- fork: s1 joins the capture before any s1 work ----
    cudaEventRecord(eF, 0);
    cudaStreamWaitEvent(s1, eF, 0);

    // ---- s1: cvt, then h0 split-K ----
    k_cvt_all<<<3744, 256, 0, s1>>>((const float4*)W_p1, (const float4*)W_ih,
                                    (const float4*)ginit, (const float4*)W_init);
    cudaEventRecord(eC, s1);
    gemm64_splitk<<<dim3(NH / 64, NB / 64, 3), 128, 0, s1>>>(
        p_ginit_bf, NKIN, p_winit_bf, NKIN, p_h0p, NH, NKIN / 3);
    cudaEventRecord(eH, s1);

    // ---- s0: sort, inps ----
    k_sort<<<1, NB>>>(gcnt);
    k_inps<<<dim3(2, NB), 256>>>(enc, segs);
    cudaEventRecord(eI, 0);

    // ---- s1: epart after inps (needs enc_bf) + cvt (in-order on s1) ----
    cudaStreamWaitEvent(s1, eI, 0);
    gemm128<__nv_bfloat16><<<dim3(NE / 128, (NB * NL) / 128), 128, GSMEM, s1>>>(
        p_enc_bf, NE2, p_wp1_bf + NH, NH3, p_epart_bf, NE, NE2);
    cudaEventRecord(eE, s1);

    // ---- s0: xproj (after cvt), then GRU overlapped with epart ----
    cudaStreamWaitEvent(0, eC, 0);
    gemm128<float><<<dim3(NH3 / 128, (NB * NS) / 128), 128, GSMEM>>>(
        p_inps_bf, NE2, p_wih_bf, NE2, p_xproj, NH3, NE2);
    cudaStreamWaitEvent(0, eH, 0);
    k_gru_persist<<<64, 256, GRUSMEM>>>(W_hh, b_ih, b_hh, b_init);

    // hpart = outputs @ W1h^T  (1536 x 512, K=512)
    gemm128<float><<<dim3(NE / 128, (NB * NS) / 128), 128, GSMEM>>>(
        p_outh_bf, NH, p_wp1_bf, NH3, p_hpart, NE, NH);

    // plan needs epart
    cudaStreamWaitEvent(0, eE, 0);
    k_plan<<<dim3(16, NB), 256>>>(segs, b_p1, W_p2, b_p2);
    k_final<<<1, 1024>>>(W_stop, b_stop, out);
}

// round 17
// speedup vs baseline: 1.9465x; 1.0107x over previous
// R17: re-bench of R16 (round-16 bench died to the recurring container/broker
// infra failure — 6th occurrence, same signature; R7->R8, R9->R10 precedent).
// Logic unchanged: k_inps unroll-2 + inline rank (sort on s1), GRU skips final
// barrier, GRU overlapped with epart, BK=64 gemm128, split-K h0.
#include <cuda_runtime.h>
#include <cuda_bf16.h>
#include <mma.h>
#include <cstdint>

using namespace nvcuda;

#define NB   128
#define NS   12
#define NL   128
#define NE   512
#define NE2  1024
#define NH   512
#define NH3  1536
#define NKIN 2304

// ---------------- scratch ----------------
__device__ int   g_idx[NB];
__device__ int   g_gc[NB];
__device__ float g_mask_sum;
__device__ float g_h0p[3 * NB * NH];
__device__ float g_xproj[NB * NS * NH3];
__device__ float g_hpart[NB * NS * NE];
__device__ float g_plan_partial[2048];
__device__ unsigned g_bg_arrive[4];
__device__ unsigned g_bg_gen[4];
// bf16 buffers
__device__ __nv_bfloat16 g_epart_bf[NB * NL * NE];
__device__ __nv_bfloat16 g_enc_bf[NB * NL * NE2];
__device__ __nv_bfloat16 g_inps_bf[NB * NS * NE2];
__device__ __nv_bfloat16 g_outh_bf[NB * NS * NH];
__device__ __nv_bfloat16 g_hb[NB * NH];
__device__ __nv_bfloat16 g_wp1_bf[NE * NH3];
__device__ __nv_bfloat16 g_wih_bf[NH3 * NE2];
__device__ __nv_bfloat16 g_ginit_bf[NB * NKIN];
__device__ __nv_bfloat16 g_winit_bf[NH * NKIN];

// ---------------- helpers ----------------
__device__ __forceinline__ float fast_tanh(float x) {
    float y; asm("tanh.approx.f32 %0, %1;" : "=f"(y) : "f"(x)); return y;
}
__device__ __forceinline__ float sigmoidf(float x) { return 1.f / (1.f + __expf(-x)); }
__device__ __forceinline__ float softplusf(float x) { return (x > 15.f) ? x : log1pf(__expf(x)); }

__device__ __forceinline__ void cp16(void* sdst, const void* gsrc) {
    uint32_t s = (uint32_t)__cvta_generic_to_shared(sdst);
    asm volatile("cp.async.cg.shared.global [%0], [%1], 16;\n" :: "r"(s), "l"(gsrc));
}
#define CP_COMMIT() asm volatile("cp.async.commit_group;\n")
#define CP_WAIT1()  asm volatile("cp.async.wait_group 1;\n")
#define CP_WAIT0()  asm volatile("cp.async.wait_group 0;\n")

__device__ __forceinline__ uint32_t bf2_bits(float a, float b) {
    __nv_bfloat162 v{__float2bfloat16(a), __float2bfloat16(b)};
    return *reinterpret_cast<uint32_t*>(&v);
}

// ---------------- single merged fp32 -> bf16 convert ----------------
__global__ void k_cvt_all(const float4* __restrict__ wp1, const float4* __restrict__ wih,
                          const float4* __restrict__ gin, const float4* __restrict__ win) {
    int i = blockIdx.x * 256 + threadIdx.x;
    const float4* src; __nv_bfloat162* dst; int off;
    if (i < 196608)      { src = wp1; dst = (__nv_bfloat162*)g_wp1_bf;   off = i; }
    else if (i < 589824) { src = wih; dst = (__nv_bfloat162*)g_wih_bf;   off = i - 196608; }
    else if (i < 663552) { src = gin; dst = (__nv_bfloat162*)g_ginit_bf; off = i - 589824; }
    else if (i < 958464) { src = win; dst = (__nv_bfloat162*)g_winit_bf; off = i - 663552; }
    else return;
    float4 v = src[off];
    dst[2 * off]     = __nv_bfloat162{__float2bfloat16(v.x), __float2bfloat16(v.y)};
    dst[2 * off + 1] = __nv_bfloat162{__float2bfloat16(v.z), __float2bfloat16(v.w)};
}

// ---------------- stable descending sort of group_count (feeds GRU/plan/final) ----------------
__global__ void k_sort(const int* __restrict__ gc) {
    __shared__ int s_gc[NB];
    __shared__ int red[NB];
    int t = threadIdx.x;
    s_gc[t] = gc[t];
    __syncthreads();
    int my = s_gc[t];
    int rank = 0;
    #pragma unroll 8
    for (int j = 0; j < NB; j++) {
        int v = s_gc[j];
        rank += (v > my) || (v == my && j < t);
    }
    g_idx[rank] = t;
    g_gc[rank]  = my;
    red[t] = my;
    __syncthreads();
    for (int off = 64; off > 0; off >>= 1) {
        if (t < off) red[t] += red[t + off];
        __syncthreads();
    }
    if (t == 0) g_mask_sum = (float)red[0];
}

// ---------------- alpha + inps einsum: inline rank (no k_sort dependency) ----------------
// grid (2, NB); 2 e's/thread; 2-way l-blocking (unroll 2 == R14-proven shape).
__global__ __launch_bounds__(256) void k_inps(const float* __restrict__ enc,
                                              const int* __restrict__ segments,
                                              const int* __restrict__ gc) {
    __shared__ float s_a[NS][NL];
    __shared__ float s_inv[NS];
    __shared__ int   s_gcv[NB];
    __shared__ int   s_p;
    const int eo = blockIdx.x;
    const int b  = blockIdx.y;
    const int t  = threadIdx.x;

    // inline stable argsort(-gc): find original index p whose rank == b
    if (t < NB) s_gcv[t] = gc[t];
    __syncthreads();
    if (t < NB) {
        int my = s_gcv[t];
        int rank = 0;
        #pragma unroll 8
        for (int j = 0; j < NB; j++) {
            int v = s_gcv[j];
            rank += (v > my) || (v == my && j < t);
        }
        if (rank == b) s_p = t;
    }
    __syncthreads();
    const int p = s_p;

    for (int i = t; i < NS * NL; i += 256) {
        int s = i >> 7, l = i & 127;
        float v = 0.f;
        if (s > 0) v = (float)segments[(p * NS + (s - 1)) * NL + l];
        s_a[s][l] = v;
    }
    __syncthreads();
    if (t < NS) {
        float sum = 0.f;
        for (int l = 0; l < NL; l++) sum += s_a[t][l];
        s_inv[t] = 1.f / (sum + 1.f);
    }
    __syncthreads();
    for (int i = t; i < NS * NL; i += 256) {
        int s = i >> 7;
        s_a[s][i & 127] *= s_inv[s];
    }
    __syncthreads();

    const int e2 = eo * 512 + t * 2;
    const float* encb = enc + (size_t)b * NL * NE2 + e2;
    __nv_bfloat16* encbf = g_enc_bf + (size_t)b * NL * NE2 + e2;

    float acc0[NS], acc1[NS];
    #pragma unroll
    for (int s = 0; s < NS; s++) { acc0[s] = 0.f; acc1[s] = 0.f; }

    #pragma unroll 2
    for (int l = 0; l < NL; l += 2) {
        float2 va = *reinterpret_cast<const float2*>(encb + (size_t)l * NE2);
        float2 vb = *reinterpret_cast<const float2*>(encb + (size_t)(l + 1) * NE2);
        uint32_t pa = bf2_bits(va.x, va.y);
        uint32_t pb = bf2_bits(vb.x, vb.y);
        *reinterpret_cast<uint32_t*>(encbf + (size_t)l * NE2) = pa;
        *reinterpret_cast<uint32_t*>(encbf + (size_t)(l + 1) * NE2) = pb;
        #pragma unroll
        for (int s = 0; s < NS; s++) {
            float aa = s_a[s][l];
            float ab = s_a[s][l + 1];
            acc0[s] += aa * va.x + ab * vb.x;
            acc1[s] += aa * va.y + ab * vb.y;
        }
    }
    #pragma unroll
    for (int s = 0; s < NS; s++)
        *reinterpret_cast<uint32_t*>(g_inps_bf + ((size_t)b * NS + s) * NE2 + e2) =
            bf2_bits(acc0[s], acc1[s]);
}

// ---------------- bf16 GEMM: 128x128 block, 4 warps, 64x64 warp tile, BK=64, 3-stage ----
#define GSTG 3
#define GLDS 72
template <typename OutT>
__global__ __launch_bounds__(128) void gemm128(
    const __nv_bfloat16* __restrict__ A, int lda,
    const __nv_bfloat16* __restrict__ W, int ldw,
    OutT* __restrict__ C, int ldc, int K) {
    extern __shared__ __align__(16) __nv_bfloat16 gsm[];
    __nv_bfloat16* sA = gsm;
    __nv_bfloat16* sW = gsm + GSTG * 128 * GLDS;

    const int tid  = threadIdx.x;
    const int warp = tid >> 5;
    const int lane = tid & 31;
    const int wm   = warp & 1;
    const int wn   = warp >> 1;
    const int m0   = blockIdx.y * 128;
    const int n0   = blockIdx.x * 128;
    const int nkt  = K >> 6;

    wmma::fragment<wmma::accumulator, 16, 16, 16, float> acc[4][4];
    #pragma unroll
    for (int i = 0; i < 4; i++)
        #pragma unroll
        for (int j = 0; j < 4; j++) wmma::fill_fragment(acc[i][j], 0.f);

    auto issue = [&](int kt, int st) {
        int k0 = kt << 6;
        __nv_bfloat16* a = sA + st * 128 * GLDS;
        __nv_bfloat16* w = sW + st * 128 * GLDS;
        #pragma unroll
        for (int q = 0; q < 8; q++) {
            int chunk = q * 128 + tid;
            int r  = chunk >> 3;
            int c8 = (chunk & 7) * 8;
            cp16(a + r * GLDS + c8, A + (size_t)(m0 + r) * lda + k0 + c8);
            cp16(w + r * GLDS + c8, W + (size_t)(n0 + r) * ldw + k0 + c8);
        }
        CP_COMMIT();
    };

    issue(0, 0);
    issue(1, 1);
    for (int kt = 0; kt < nkt; kt++) {
        int st = kt % GSTG;
        if (kt == nkt - 1) CP_WAIT0(); else CP_WAIT1();
        __syncthreads();
        if (kt + 2 < nkt) issue(kt + 2, (kt + 2) % GSTG);
        const __nv_bfloat16* a = sA + st * 128 * GLDS;
        const __nv_bfloat16* w = sW + st * 128 * GLDS;
        #pragma unroll
        for (int kk = 0; kk < 64; kk += 16) {
            wmma::fragment<wmma::matrix_a, 16, 16, 16, __nv_bfloat16, wmma::row_major> af[4];
            wmma::fragment<wmma::matrix_b, 16, 16, 16, __nv_bfloat16, wmma::col_major> bf[4];
            #pragma unroll
            for (int i = 0; i < 4; i++)
                wmma::load_matrix_sync(af[i], a + (wm * 64 + i * 16) * GLDS + kk, GLDS);
            #pragma unroll
            for (int j = 0; j < 4; j++)
                wmma::load_matrix_sync(bf[j], w + (wn * 64 + j * 16) * GLDS + kk, GLDS);
            #pragma unroll
            for (int i = 0; i < 4; i++)
                #pragma unroll
                for (int j = 0; j < 4; j++)
                    wmma::mma_sync(acc[i][j], af[i], bf[j], acc[i][j]);
        }
        __syncthreads();
    }

    if constexpr (sizeof(OutT) == 4) {
        #pragma unroll
        for (int i = 0; i < 4; i++)
            #pragma unroll
            for (int j = 0; j < 4; j++)
                wmma::store_matrix_sync(
                    (float*)C + (size_t)(m0 + wm * 64 + i * 16) * ldc + n0 + wn * 64 + j * 16,
                    acc[i][j], ldc, wmma::mem_row_major);
    } else {
        float* stage = reinterpret_cast<float*>(gsm) + warp * 16 * 68;
        #pragma unroll
        for (int i = 0; i < 4; i++) {
            #pragma unroll
            for (int j = 0; j < 4; j++)
                wmma::store_matrix_sync(stage + j * 16, acc[i][j], 68, wmma::mem_row_major);
            __syncwarp();
            int gr = m0 + wm * 64 + i * 16;
            int gc0 = n0 + wn * 64;
            #pragma unroll
            for (int p = 0; p < 16; p++) {
                float v0 = stage[p * 68 + lane * 2];
                float v1 = stage[p * 68 + lane * 2 + 1];
                uint32_t pk = bf2_bits(v0, v1);
                *reinterpret_cast<uint32_t*>(
                    (__nv_bfloat16*)C + (size_t)(gr + p) * ldc + gc0 + lane * 2) = pk;
            }
            __syncwarp();
        }
    }
}
#define GSMEM (GSTG * 2 * 128 * GLDS * 2)   // 110592 B

// ---------------- bf16 GEMM, 64x64 tile, split-K over blockIdx.z (h0) ----------------
__global__ __launch_bounds__(128) void gemm64_splitk(
    const __nv_bfloat16* __restrict__ A, int lda,
    const __nv_bfloat16* __restrict__ W, int ldw,
    float* __restrict__ Cpart, int ldc, int Kchunk) {
    __shared__ __align__(16) __nv_bfloat16 As[2][64][40];
    __shared__ __align__(16) __nv_bfloat16 Ws[2][64][40];

    const int z = blockIdx.z;
    A += (size_t)z * Kchunk;
    W += (size_t)z * Kchunk;
    Cpart += (size_t)z * NB * NH;

    const int tid  = threadIdx.x;
    const int warp = tid >> 5;
    const int wm   = warp & 1;
    const int wn   = warp >> 1;
    const int m0   = blockIdx.y * 64;
    const int n0   = blockIdx.x * 64;
    const int nkt  = Kchunk >> 5;

    wmma::fragment<wmma::accumulator, 16, 16, 16, float> acc[2][2];
    #pragma unroll
    for (int i = 0; i < 2; i++)
        #pragma unroll
        for (int j = 0; j < 2; j++) wmma::fill_fragment(acc[i][j], 0.f);

    auto issue = [&](int kt, int st) {
        int k0 = kt << 5;
        #pragma unroll
        for (int q = 0; q < 2; q++) {
            int chunk = tid * 2 + q;
            int r  = chunk >> 2;
            int c8 = (chunk & 3) * 8;
            cp16(&As[st][r][c8], A + (size_t)(m0 + r) * lda + k0 + c8);
            cp16(&Ws[st][r][c8], W + (size_t)(n0 + r) * ldw + k0 + c8);
        }
        CP_COMMIT();
    };

    issue(0, 0);
    for (int kt = 0; kt < nkt; kt++) {
        int st = kt & 1;
        if (kt + 1 < nkt) { issue(kt + 1, st ^ 1); CP_WAIT1(); }
        else             { CP_WAIT0(); }
        __syncthreads();
        #pragma unroll
        for (int kk = 0; kk < 32; kk += 16) {
            wmma::fragment<wmma::matrix_a, 16, 16, 16, __nv_bfloat16, wmma::row_major> af[2];
            wmma::fragment<wmma::matrix_b, 16, 16, 16, __nv_bfloat16, wmma::col_major> bf[2];
            #pragma unroll
            for (int i = 0; i < 2; i++)
                wmma::load_matrix_sync(af[i], &As[st][wm * 32 + i * 16][kk], 40);
            #pragma unroll
            for (int j = 0; j < 2; j++)
                wmma::load_matrix_sync(bf[j], &Ws[st][wn * 32 + j * 16][kk], 40);
            #pragma unroll
            for (int i = 0; i < 2; i++)
                #pragma unroll
                for (int j = 0; j < 2; j++)
                    wmma::mma_sync(acc[i][j], af[i], bf[j], acc[i][j]);
        }
        __syncthreads();
    }
    #pragma unroll
    for (int i = 0; i < 2; i++)
        #pragma unroll
        for (int j = 0; j < 2; j++)
            wmma::store_matrix_sync(
                Cpart + (size_t)(m0 + wm * 32 + i * 16) * ldc + n0 + wn * 32 + j * 16,
                acc[i][j], ldc, wmma::mem_row_major);
}

// ---------------- per-batch-group barrier ----------------
__device__ __forceinline__ void bgsync(int bg) {
    __syncthreads();
    if (threadIdx.x == 0) {
        unsigned gen;
        asm volatile("ld.acquire.gpu.u32 %0, [%1];" : "=r"(gen) : "l"(&g_bg_gen[bg]) : "memory");
        __threadfence();
        unsigned old = atomicAdd(&g_bg_arrive[bg], 1u);
        if (old == 15) {
            g_bg_arrive[bg] = 0;
            __threadfence();
            atomicAdd(&g_bg_gen[bg], 1u);
        } else {
            unsigned cur;
            do {
                __nanosleep(32);
                asm volatile("ld.acquire.gpu.u32 %0, [%1];" : "=r"(cur) : "l"(&g_bg_gen[bg]) : "memory");
            } while (cur == gen);
        }
    }
    __syncthreads();
}

// ---------------- persistent GRU scan ----------------
__global__ __launch_bounds__(256) void k_gru_persist(
    const float* __restrict__ Whh, const float* __restrict__ bih,
    const float* __restrict__ bhh, const float* __restrict__ binit) {
    extern __shared__ __align__(16) char dyn[];
    __nv_bfloat16* sW  = (__nv_bfloat16*)dyn;          // [96][520]
    __nv_bfloat16* sH  = sW + 96 * 520;                // [32][520]
    float*         sGH = (float*)(sH + 32 * 520);      // [32][100]
    float*         sB  = sGH + 32 * 100;               // [192]
    float*         sX  = sB + 192;                     // [96][32]
    float*         sHP = sX + 96 * 32;                 // [32][32]

    const int tid  = threadIdx.x;
    const int warp = tid >> 5;
    const int cs   = blockIdx.x & 15;
    const int bg   = blockIdx.x >> 4;
    const int C0   = cs * 32;
    const int B0   = bg * 32;

    for (int i = tid; i < 96 * 128; i += 256) {
        int r = i >> 7, c4 = (i & 127) * 4;
        int p = r >> 5, j = r & 31;
        float4 v = *(const float4*)(Whh + (size_t)(p * NH + C0 + j) * NH + c4);
        __nv_bfloat16* d = sW + r * 520 + c4;
        d[0] = __float2bfloat16(v.x); d[1] = __float2bfloat16(v.y);
        d[2] = __float2bfloat16(v.z); d[3] = __float2bfloat16(v.w);
    }
    if (tid < 96) {
        int p = tid >> 5, j = tid & 31;
        sB[tid]      = bih[p * NH + C0 + j];
        sB[96 + tid] = bhh[p * NH + C0 + j];
    }
    for (int i = tid; i < 32 * 32; i += 256) {
        int bi = i >> 5, ci = i & 31;
        int gi = (B0 + bi) * NH + C0 + ci;
        float v = g_h0p[gi] + g_h0p[NB * NH + gi] + g_h0p[2 * NB * NH + gi] + binit[C0 + ci];
        sHP[i] = v;
        g_hb[gi] = __float2bfloat16(v);
    }
    const int smax = g_gc[B0];
    bgsync(bg);

    for (int s = 0; s < smax; s++) {
        #pragma unroll
        for (int q = 0; q < 8; q++) {
            int idx = q * 256 + tid;
            int r = idx >> 6, c8 = (idx & 63) * 8;
            cp16(sH + r * 520 + c8, g_hb + (size_t)(B0 + r) * NH + c8);
        }
        CP_COMMIT();
        #pragma unroll
        for (int q = 0; q < 3; q++) {
            int idx = q * 256 + tid;
            int seg = idx >> 3;
            int f   = (idx & 7) * 4;
            int bb  = seg / 3, p = seg - bb * 3;
            cp16(sX + seg * 32 + f,
                 g_xproj + ((size_t)(B0 + bb) * NS + s) * NH3 + p * NH + C0 + f);
        }
        CP_COMMIT();
        CP_WAIT1();
        __syncthreads();
        if (warp < 6) {
            wmma::fragment<wmma::accumulator, 16, 16, 16, float> acc[2];
            wmma::fill_fragment(acc[0], 0.f);
            wmma::fill_fragment(acc[1], 0.f);
            for (int kk = 0; kk < 512; kk += 16) {
                wmma::fragment<wmma::matrix_a, 16, 16, 16, __nv_bfloat16, wmma::row_major> af[2];
                wmma::fragment<wmma::matrix_b, 16, 16, 16, __nv_bfloat16, wmma::col_major> bf;
                wmma::load_matrix_sync(af[0], sH + kk, 520);
                wmma::load_matrix_sync(af[1], sH + 16 * 520 + kk, 520);
                wmma::load_matrix_sync(bf, sW + warp * 16 * 520 + kk, 520);
                wmma::mma_sync(acc[0], af[0], bf, acc[0]);
                wmma::mma_sync(acc[1], af[1], bf, acc[1]);
            }
            wmma::store_matrix_sync(sGH + warp * 16, acc[0], 100, wmma::mem_row_major);
            wmma::store_matrix_sync(sGH + 16 * 100 + warp * 16, acc[1], 100, wmma::mem_row_major);
        }
        CP_WAIT0();
        __syncthreads();
        for (int i = tid; i < 32 * 32; i += 256) {
            int bi = i >> 5, ci = i & 31;
            float r = sigmoidf(sX[(bi * 3 + 0) * 32 + ci] + sB[ci] +
                               sGH[bi * 100 + ci] + sB[96 + ci]);
            float z = sigmoidf(sX[(bi * 3 + 1) * 32 + ci] + sB[32 + ci] +
                               sGH[bi * 100 + 32 + ci] + sB[96 + 32 + ci]);
            float n = tanhf(sX[(bi * 3 + 2) * 32 + ci] + sB[64 + ci] +
                            r * (sGH[bi * 100 + 64 + ci] + sB[96 + 64 + ci]));
            float hp = sHP[i];
            float hn = (1.f - z) * n + z * hp;
            sHP[i] = hn;
            __nv_bfloat16 hb = __float2bfloat16(hn);
            int gi = (B0 + bi) * NH + C0 + ci;
            g_hb[gi] = hb;
            g_outh_bf[((size_t)(B0 + bi) * NS + s) * NH + C0 + ci] = hb;
        }
        if (s + 1 < smax) bgsync(bg);   // last step: no successor reads g_hb
    }
}
#define GRUSMEM 163072

// ---------------- fused plan logits + BCE ----------------
__global__ void k_plan(const int* __restrict__ segments,
                       const float* __restrict__ b_p1,
                       const float* __restrict__ W_p2,
                       const float* __restrict__ b_p2) {
    __shared__ float s_h[NS][NE];
    __shared__ float s_w2[NE];
    __shared__ float s_b1[NE];
    __shared__ float s_warp[8];
    int t = threadIdx.x;
    int b = blockIdx.y, ltile = blockIdx.x;
    for (int i = t; i < NS * NE; i += 256) s_h[i >> 9][i & 511] = g_hpart[(size_t)b * NS * NE + i];
    for (int i = t; i < NE; i += 256) { s_w2[i] = W_p2[i]; s_b1[i] = b_p1[i]; }
    __syncthreads();

    int warp = t >> 5, lane = t & 31;
    int l = ltile * 8 + warp;
    const __nv_bfloat16* ep = g_epart_bf + (size_t)(b * NL + l) * NE;
    float epr[16];
    #pragma unroll
    for (int j = 0; j < 16; j++) {
        int e = lane + 32 * j;
        epr[j] = __bfloat162float(ep[e]) + s_b1[e];
    }

    int gcb = g_gc[b];
    int p   = g_idx[b];
    float bp2 = b_p2[0];
    float local = 0.f;
    for (int s = 0; s < gcb; s++) {
        float acc = 0.f;
        #pragma unroll
        for (int j = 0; j < 16; j++) {
            int e = lane + 32 * j;
            acc += fast_tanh(s_h[s][e] + epr[j]) * s_w2[e];
        }
        #pragma unroll
        for (int off = 16; off; off >>= 1) acc += __shfl_xor_sync(0xffffffffu, acc, off);
        if (lane == 0) {
            float pl  = acc + bp2;
            float tgt = (float)segments[(p * NS + s) * NL + l];
            local += softplusf(pl) - pl * tgt;
        }
    }
    if (lane == 0) s_warp[warp] = local;
    __syncthreads();
    if (t == 0) {
        float sum = 0.f;
        #pragma unroll
        for (int w = 0; w < 8; w++) sum += s_warp[w];
        g_plan_partial[b * 16 + ltile] = sum;
    }
}

// ---------------- stop loss + final reduction ----------------
__global__ void k_final(const float* __restrict__ W_stop,
                        const float* __restrict__ b_stop,
                        float* __restrict__ out) {
    __shared__ float s_w[NH];
    __shared__ float s_stop[32];
    __shared__ float s_red[1024];
    int t = threadIdx.x;
    for (int i = t; i < NH; i += 1024) s_w[i] = W_stop[i];
    __syncthreads();

    int warp = t >> 5, lane = t & 31;
    float stop_local = 0.f;
    for (int bs = warp; bs < NB * NS; bs += 32) {
        int b = bs / NS, s = bs % NS;
        int gcb = g_gc[b];
        if (s < gcb) {
            const __nv_bfloat16* o = g_outh_bf + (size_t)bs * NH;
            float a = 0.f;
            #pragma unroll
            for (int j = 0; j < 16; j++)
                a += __bfloat162float(o[lane + 32 * j]) * s_w[lane + 32 * j];
            #pragma unroll
            for (int off = 16; off; off >>= 1) a += __shfl_xor_sync(0xffffffffu, a, off);
            if (lane == 0) {
                float logit = a + b_stop[0];
                float label = (s == gcb - 1) ? 1.f : 0.f;
                stop_local += softplusf(logit) - logit * label;
            }
        }
    }
    if (lane == 0) s_stop[warp] = stop_local;

    s_red[t] = g_plan_partial[t] + g_plan_partial[t + 1024];
    __syncthreads();
    for (int off = 512; off; off >>= 1) {
        if (t < off) s_red[t] += s_red[t + off];
        __syncthreads();
    }
    if (t == 0) {
        float stop_sum = 0.f;
        #pragma unroll
        for (int w = 0; w < 32; w++) stop_sum += s_stop[w];
        float ms = g_mask_sum;
        out[0] = stop_sum / ms;
        out[1] = s_red[0] / (ms * (float)NL);
    }
}

// ---------------- launch ----------------
extern "C" void kernel_launch(void* const* d_in, const int* in_sizes, int n_in,
                              void* d_out, int out_size) {
    const float* enc    = (const float*)d_in[0];
    const int*   segs   = (const int*)d_in[1];
    const int*   gcnt   = (const int*)d_in[2];
    const float* ginit  = (const float*)d_in[3];
    const float* W_init = (const float*)d_in[4];
    const float* b_init = (const float*)d_in[5];
    const float* W_ih   = (const float*)d_in[6];
    const float* b_ih   = (const float*)d_in[7];
    const float* W_hh   = (const float*)d_in[8];
    const float* b_hh   = (const float*)d_in[9];
    const float* W_p1   = (const float*)d_in[10];
    const float* b_p1   = (const float*)d_in[11];
    const float* W_p2   = (const float*)d_in[12];
    const float* b_p2   = (const float*)d_in[13];
    const float* W_stop = (const float*)d_in[14];
    const float* b_stop = (const float*)d_in[15];
    float* out = (float*)d_out;

    float *p_h0p, *p_xproj, *p_hpart;
    __nv_bfloat16 *p_epart_bf, *p_inps_bf, *p_outh_bf, *p_enc_bf, *p_wp1_bf, *p_wih_bf,
                  *p_ginit_bf, *p_winit_bf;
    cudaGetSymbolAddress((void**)&p_h0p,      g_h0p);
    cudaGetSymbolAddress((void**)&p_xproj,    g_xproj);
    cudaGetSymbolAddress((void**)&p_hpart,    g_hpart);
    cudaGetSymbolAddress((void**)&p_epart_bf, g_epart_bf);
    cudaGetSymbolAddress((void**)&p_inps_bf,  g_inps_bf);
    cudaGetSymbolAddress((void**)&p_outh_bf,  g_outh_bf);
    cudaGetSymbolAddress((void**)&p_enc_bf,   g_enc_bf);
    cudaGetSymbolAddress((void**)&p_wp1_bf,   g_wp1_bf);
    cudaGetSymbolAddress((void**)&p_wih_bf,   g_wih_bf);
    cudaGetSymbolAddress((void**)&p_ginit_bf, g_ginit_bf);
    cudaGetSymbolAddress((void**)&p_winit_bf, g_winit_bf);

    static cudaStream_t s1 = nullptr;
    static cudaEvent_t eF = nullptr, eC = nullptr, eH = nullptr, eI = nullptr, eE = nullptr;
    if (!s1) {
        cudaStreamCreateWithFlags(&s1, cudaStreamNonBlocking);
        cudaEventCreateWithFlags(&eF, cudaEventDisableTiming);
        cudaEventCreateWithFlags(&eC, cudaEventDisableTiming);
        cudaEventCreateWithFlags(&eH, cudaEventDisableTiming);
        cudaEventCreateWithFlags(&eI, cudaEventDisableTiming);
        cudaEventCreateWithFlags(&eE, cudaEventDisableTiming);
        cudaFuncSetAttribute(k_gru_persist, cudaFuncAttributeMaxDynamicSharedMemorySize, GRUSMEM);
        cudaFuncSetAttribute(gemm128<float>, cudaFuncAttributeMaxDynamicSharedMemorySize, GSMEM);
        cudaFuncSetAttribute(gemm128<__nv_bfloat16>, cudaFuncAttributeMaxDynamicSharedMemorySize, GSMEM);
    }

    // ---- fork: s1 joins the capture before any s1 work ----
    cudaEventRecord(eF, 0);
    cudaStreamWaitEvent(s1, eF, 0);

    // ---- s1: cvt, sort (off critical path), h0 split-K ----
    k_cvt_all<<<3744, 256, 0, s1>>>((const float4*)W_p1, (const float4*)W_ih,
                                    (const float4*)ginit, (const float4*)W_init);
    cudaEventRecord(eC, s1);
    k_sort<<<1, NB, 0, s1>>>(gcnt);
    gemm64_splitk<<<dim3(NH / 64, NB / 64, 3), 128, 0, s1>>>(
        p_ginit_bf, NKIN, p_winit_bf, NKIN, p_h0p, NH, NKIN / 3);
    cudaEventRecord(eH, s1);   // h0 + sort complete

    // ---- s0: inps starts immediately (inline rank; no sort dependency) ----
    k_inps<<<dim3(2, NB), 256>>>(enc, segs, gcnt);
    cudaEventRecord(eI, 0);

    // ---- s1: epart after inps (needs enc_bf; wp1 cvt is s1-ordered) ----
    cudaStreamWaitEvent(s1, eI, 0);
    gemm128<__nv_bfloat16><<<dim3(NE / 128, (NB * NL) / 128), 128, GSMEM, s1>>>(
        p_enc_bf, NE2, p_wp1_bf + NH, NH3, p_epart_bf, NE, NE2);
    cudaEventRecord(eE, s1);

    // ---- s0: xproj (after cvt), then GRU overlapped with epart ----
    cudaStreamWaitEvent(0, eC, 0);
    gemm128<float><<<dim3(NH3 / 128, (NB * NS) / 128), 128, GSMEM>>>(
        p_inps_bf, NE2, p_wih_bf, NE2, p_xproj, NH3, NE2);
    cudaStreamWaitEvent(0, eH, 0);
    k_gru_persist<<<64, 256, GRUSMEM>>>(W_hh, b_ih, b_hh, b_init);

    // hpart = outputs @ W1h^T  (1536 x 512, K=512)
    gemm128<float><<<dim3(NE / 128, (NB * NS) / 128), 128, GSMEM>>>(
        p_outh_bf, NH, p_wp1_bf, NH3, p_hpart, NE, NH);

    // plan needs epart
    cudaStreamWaitEvent(0, eE, 0);
    k_plan<<<dim3(16, NB), 256>>>(segs, b_p1, W_p2, b_p2);
    k_final<<<1, 1024>>>(W_stop, b_stop, out);
}